// round 9
// baseline (speedup 1.0000x reference)
#include <cuda_runtime.h>
#include <math.h>

#define BATCH 4
#define CDIM  256
#define HW    4096

// ---------------- scratch (no allocations allowed) ----------------
static __device__ float g_P[(size_t)BATCH * HW * HW];          // logits -> P hi (tf32 bits)
static __device__ unsigned g_Pl[(size_t)BATCH * HW * HW];      // P lo (tf32 bits)
static __device__ float g_ax[(size_t)BATCH * HW * CDIM];
static __device__ float g_ux[(size_t)BATCH * HW * CDIM];
static __device__ float g_gen[(size_t)BATCH * HW * CDIM];
static __device__ float g_gencn[(size_t)BATCH * HW * CDIM];
static __device__ float g_sktnc[(size_t)BATCH * HW * CDIM];
static __device__ float g_refnc[(size_t)BATCH * HW * CDIM];
static __device__ float g_colpart[(size_t)BATCH * 16 * HW];
static __device__ float g_colinv[(size_t)BATCH * HW];
static __device__ unsigned g_hi0[(size_t)BATCH * HW * CDIM];
static __device__ unsigned g_lo0[(size_t)BATCH * HW * CDIM];
static __device__ unsigned g_hi1[(size_t)BATCH * HW * CDIM];
static __device__ unsigned g_lo1[(size_t)BATCH * HW * CDIM];

// ---------------- tf32 helpers ----------------
__device__ __forceinline__ unsigned f2tf(float x) {
    unsigned r;
    asm("cvt.rna.tf32.f32 %0, %1;" : "=r"(r) : "f"(x));
    return r;
}

__device__ __forceinline__ void mma_tf32(float* d, const unsigned* a, const unsigned* b) {
    asm("mma.sync.aligned.m16n8k8.row.col.f32.tf32.tf32.f32 "
        "{%0,%1,%2,%3},{%4,%5,%6,%7},{%8,%9},{%0,%1,%2,%3};"
        : "+f"(d[0]), "+f"(d[1]), "+f"(d[2]), "+f"(d[3])
        : "r"(a[0]), "r"(a[1]), "r"(a[2]), "r"(a[3]), "r"(b[0]), "r"(b[1]));
}

__device__ __forceinline__ void cpa16(unsigned saddr, const void* g) {
    asm volatile("cp.async.cg.shared.global [%0], [%1], 16;\n" :: "r"(saddr), "l"(g));
}

// ---------------- split: float -> (tf32 hi, tf32 lo) ----------------
__global__ void split_kernel(const float* __restrict__ in, unsigned* __restrict__ hi,
                             unsigned* __restrict__ lo) {
    size_t i = (size_t)blockIdx.x * 256 + threadIdx.x;
    float4 v = ((const float4*)in)[i];
    uint4 h, l;
    h.x = f2tf(v.x); l.x = f2tf(v.x - __uint_as_float(h.x));
    h.y = f2tf(v.y); l.y = f2tf(v.y - __uint_as_float(h.y));
    h.z = f2tf(v.z); l.z = f2tf(v.z - __uint_as_float(h.z));
    h.w = f2tf(v.w); l.w = f2tf(v.w - __uint_as_float(h.w));
    ((uint4*)hi)[i] = h;
    ((uint4*)lo)[i] = l;
}

// ---------------- transpose ----------------
__global__ void transpose_kernel(const float* __restrict__ in, float* __restrict__ out,
                                 int R, int S) {
    __shared__ float tile[32][33];
    int b = blockIdx.z;
    int s0 = blockIdx.x * 32, r0 = blockIdx.y * 32;
    const float* inb = in + (size_t)b * R * S;
    float* outb = out + (size_t)b * R * S;
    int tx = threadIdx.x, ty = threadIdx.y;
#pragma unroll
    for (int i = 0; i < 32; i += 8)
        tile[ty + i][tx] = inb[(size_t)(r0 + ty + i) * S + s0 + tx];
    __syncthreads();
#pragma unroll
    for (int i = 0; i < 32; i += 8)
        outb[(size_t)(s0 + ty + i) * R + r0 + tx] = tile[tx][ty + i];
}

// =====================================================================
// logits_cp: L[n][m] = sum_k A[k][n]*B[k][m], 3xTF32 pre-split, NST-stage
// =====================================================================
template<bool SYM, int NST>
__global__ __launch_bounds__(256)
void logits_cp(const unsigned* __restrict__ Ah, const unsigned* __restrict__ Al,
               const unsigned* __restrict__ Bh, const unsigned* __restrict__ Bl,
               float* __restrict__ L) {
    extern __shared__ unsigned sm[];
    constexpr int ARR = 32 * 136;
    constexpr int STG = 4 * ARR;
    constexpr int NIT = CDIM / 32;     // 8

    int bx = blockIdx.x, by = blockIdx.y, b = blockIdx.z;
    if (SYM && bx < by) return;
    int m0 = bx * 128, n0 = by * 128;

    const unsigned* Ahb = Ah + (size_t)b * CDIM * HW;
    const unsigned* Alb = Al + (size_t)b * CDIM * HW;
    const unsigned* Bhb = Bh + (size_t)b * CDIM * HW;
    const unsigned* Blb = Bl + (size_t)b * CDIM * HW;
    float* Lb = L + (size_t)b * HW * HW;

    unsigned sbase;
    asm("{ .reg .u64 t0; cvta.to.shared.u64 t0, %1; cvt.u32.u64 %0, t0; }"
        : "=r"(sbase) : "l"(sm));

    int tid = threadIdx.x;
    int warp = tid >> 5, lane = tid & 31;
    int g = lane >> 2, t = lane & 3;
    int wm = warp >> 2, wn = warp & 3;

    auto prefetch = [&](int it, int s) {
        int k0 = it * 32;
        unsigned sb = sbase + (unsigned)(s * STG) * 4u;
#pragma unroll
        for (int q = 0; q < 4; q++) {
            int f = tid + q * 256;
            int k = f >> 5, c4 = (f & 31) * 4;
            size_t go = (size_t)(k0 + k) * HW;
            unsigned so = sb + (unsigned)(k * 136 + c4) * 4u;
            cpa16(so + 0u * ARR * 4u, Ahb + go + n0 + c4);
            cpa16(so + 1u * ARR * 4u, Alb + go + n0 + c4);
            cpa16(so + 2u * ARR * 4u, Bhb + go + m0 + c4);
            cpa16(so + 3u * ARR * 4u, Blb + go + m0 + c4);
        }
        asm volatile("cp.async.commit_group;\n" ::: "memory");
    };

    float acc[4][4][4] = {};

#pragma unroll
    for (int p = 0; p < NST - 1; p++) prefetch(p, p);

    for (int it = 0; it < NIT; it++) {
        if (it + NST - 1 < NIT)
            asm volatile("cp.async.wait_group %0;\n" :: "n"(NST - 2) : "memory");
        else
            asm volatile("cp.async.wait_group 0;\n" ::: "memory");
        __syncthreads();

        const unsigned* As  = sm + (it % NST) * STG;
        const unsigned* Asr = As + ARR;
        const unsigned* Bs  = As + 2 * ARR;
        const unsigned* Bsr = As + 3 * ARR;

#pragma unroll
        for (int c = 0; c < 4; c++) {
            int kc = c * 8;
            unsigned bb[4][2], br[4][2];
#pragma unroll
            for (int j = 0; j < 4; j++) {
                int col = wn * 32 + j * 8 + g;
                bb[j][0] = Bs[(kc + t) * 136 + col];
                bb[j][1] = Bs[(kc + t + 4) * 136 + col];
                br[j][0] = Bsr[(kc + t) * 136 + col];
                br[j][1] = Bsr[(kc + t + 4) * 136 + col];
            }
#pragma unroll
            for (int i = 0; i < 4; i++) {
                int row = wm * 64 + i * 16 + g;
                unsigned aa[4], ar[4];
                aa[0] = As[(kc + t) * 136 + row];
                aa[1] = As[(kc + t) * 136 + row + 8];
                aa[2] = As[(kc + t + 4) * 136 + row];
                aa[3] = As[(kc + t + 4) * 136 + row + 8];
                ar[0] = Asr[(kc + t) * 136 + row];
                ar[1] = Asr[(kc + t) * 136 + row + 8];
                ar[2] = Asr[(kc + t + 4) * 136 + row];
                ar[3] = Asr[(kc + t + 4) * 136 + row + 8];
#pragma unroll
                for (int j = 0; j < 4; j++) {
                    mma_tf32(acc[i][j], aa, bb[j]);
                    mma_tf32(acc[i][j], aa, br[j]);
                    mma_tf32(acc[i][j], ar, bb[j]);
                }
            }
        }
        int nx = it + NST - 1;
        if (nx < NIT) prefetch(nx, nx % NST);
        __syncthreads();
    }

#pragma unroll
    for (int i = 0; i < 4; i++) {
        int r = n0 + wm * 64 + i * 16 + g;
#pragma unroll
        for (int j = 0; j < 4; j++) {
            int cc = m0 + wn * 32 + j * 8 + 2 * t;
            *(float2*)&Lb[(size_t)r * HW + cc] =
                make_float2(acc[i][j][0], acc[i][j][1]);
            *(float2*)&Lb[(size_t)(r + 8) * HW + cc] =
                make_float2(acc[i][j][2], acc[i][j][3]);
        }
    }
    if (SYM && bx != by) {
#pragma unroll
        for (int i = 0; i < 4; i++) {
            int rr = n0 + wm * 64 + i * 16 + g;
#pragma unroll
            for (int j = 0; j < 4; j++) {
                int cc = m0 + wn * 32 + j * 8 + 2 * t;
                Lb[(size_t)cc * HW + rr]           = acc[i][j][0];
                Lb[(size_t)(cc + 1) * HW + rr]     = acc[i][j][1];
                Lb[(size_t)cc * HW + rr + 8]       = acc[i][j][2];
                Lb[(size_t)(cc + 1) * HW + rr + 8] = acc[i][j][3];
            }
        }
    }
}

// =====================================================================
// pax_cp: C[n][d] = sum_k P[n][k]*ax[k][d] (+U+R), pre-split operands,
// cp.async NST-stage pipeline. THREE: 3xTF32. CTA 128x128, BK=32.
// =====================================================================
template<bool THREE, int NST>
__global__ __launch_bounds__(256)
void pax_cp(const unsigned* __restrict__ Ph, const unsigned* __restrict__ Pl,
            const unsigned* __restrict__ Bh, const unsigned* __restrict__ Bl,
            const float* __restrict__ U, const float* __restrict__ Rr,
            float* __restrict__ C) {
    extern __shared__ unsigned sm[];
    constexpr int AW = 128 * 36;
    constexpr int BW = 32 * 136;
    constexpr int BOFF = THREE ? 2 * AW : AW;
    constexpr int STG = THREE ? 2 * (AW + BW) : (AW + BW);
    constexpr int NIT = HW / 32;       // 128

    int b = blockIdx.z;
    int d0 = blockIdx.x * 128;
    int n0 = blockIdx.y * 128;

    const unsigned* Phb = Ph + (size_t)b * HW * HW;
    const unsigned* Plb = THREE ? Pl + (size_t)b * HW * HW : nullptr;
    const unsigned* Bhb = Bh + (size_t)b * HW * CDIM;
    const unsigned* Blb = THREE ? Bl + (size_t)b * HW * CDIM : nullptr;

    unsigned sbase;
    asm("{ .reg .u64 t0; cvta.to.shared.u64 t0, %1; cvt.u32.u64 %0, t0; }"
        : "=r"(sbase) : "l"(sm));

    int tid = threadIdx.x;
    int warp = tid >> 5, lane = tid & 31;
    int g = lane >> 2, t = lane & 3;
    int wm = warp >> 2, wn = warp & 3;

    auto prefetch = [&](int it, int s) {
        int k0 = it * 32;
        unsigned sb = sbase + (unsigned)(s * STG) * 4u;
#pragma unroll
        for (int q = 0; q < 4; q++) {
            int f = tid + q * 256;
            int n = f >> 3, c4 = (f & 7) * 4;
            size_t go = (size_t)(n0 + n) * HW + k0 + c4;
            unsigned so = sb + (unsigned)(n * 36 + c4) * 4u;
            cpa16(so, Phb + go);
            if (THREE) cpa16(so + AW * 4u, Plb + go);
        }
#pragma unroll
        for (int q = 0; q < 4; q++) {
            int f = tid + q * 256;
            int k = f >> 5, d4 = (f & 31) * 4;
            size_t go = (size_t)(k0 + k) * CDIM + d0 + d4;
            unsigned so = sb + (unsigned)(BOFF + k * 136 + d4) * 4u;
            cpa16(so, Bhb + go);
            if (THREE) cpa16(so + BW * 4u, Blb + go);
        }
        asm volatile("cp.async.commit_group;\n" ::: "memory");
    };

    float acc[4][4][4] = {};

#pragma unroll
    for (int p = 0; p < NST - 1; p++) prefetch(p, p);

    for (int it = 0; it < NIT; it++) {
        if (it + NST - 1 < NIT)
            asm volatile("cp.async.wait_group %0;\n" :: "n"(NST - 2) : "memory");
        else
            asm volatile("cp.async.wait_group 0;\n" ::: "memory");
        __syncthreads();

        const unsigned* As  = sm + (it % NST) * STG;
        const unsigned* Asr = As + AW;                 // valid only if THREE
        const unsigned* Bs  = As + BOFF;
        const unsigned* Bsr = Bs + BW;

#pragma unroll
        for (int c = 0; c < 4; c++) {
            int kc = c * 8;
            unsigned bb[4][2], br[4][2];
#pragma unroll
            for (int j = 0; j < 4; j++) {
                int col = wn * 32 + j * 8 + g;
                bb[j][0] = Bs[(kc + t) * 136 + col];
                bb[j][1] = Bs[(kc + t + 4) * 136 + col];
                if (THREE) {
                    br[j][0] = Bsr[(kc + t) * 136 + col];
                    br[j][1] = Bsr[(kc + t + 4) * 136 + col];
                }
            }
#pragma unroll
            for (int i = 0; i < 4; i++) {
                int row = wm * 64 + i * 16 + g;
                unsigned aa[4], ar[4];
                aa[0] = As[row * 36 + kc + t];
                aa[1] = As[(row + 8) * 36 + kc + t];
                aa[2] = As[row * 36 + kc + t + 4];
                aa[3] = As[(row + 8) * 36 + kc + t + 4];
                if (THREE) {
                    ar[0] = Asr[row * 36 + kc + t];
                    ar[1] = Asr[(row + 8) * 36 + kc + t];
                    ar[2] = Asr[row * 36 + kc + t + 4];
                    ar[3] = Asr[(row + 8) * 36 + kc + t + 4];
                }
#pragma unroll
                for (int j = 0; j < 4; j++) {
                    mma_tf32(acc[i][j], aa, bb[j]);
                    if (THREE) {
                        mma_tf32(acc[i][j], aa, br[j]);
                        mma_tf32(acc[i][j], ar, bb[j]);
                    }
                }
            }
        }
        int nx = it + NST - 1;
        if (nx < NIT) prefetch(nx, nx % NST);
        __syncthreads();
    }

    const float* Ub = U + (size_t)b * HW * CDIM;
    const float* Rb = Rr + (size_t)b * HW * CDIM;
    float* Cb = C + (size_t)b * HW * CDIM;
#pragma unroll
    for (int i = 0; i < 4; i++) {
        int r = n0 + wm * 64 + i * 16 + g;
#pragma unroll
        for (int j = 0; j < 4; j++) {
            int cc = d0 + wn * 32 + j * 8 + 2 * t;
            size_t o0 = (size_t)r * CDIM + cc;
            size_t o1 = (size_t)(r + 8) * CDIM + cc;
            float2 u0 = *(const float2*)&Ub[o0], u1 = *(const float2*)&Ub[o1];
            float2 q0 = *(const float2*)&Rb[o0], q1 = *(const float2*)&Rb[o1];
            *(float2*)&Cb[o0] = make_float2(acc[i][j][0] + u0.x + q0.x,
                                            acc[i][j][1] + u0.y + q0.y);
            *(float2*)&Cb[o1] = make_float2(acc[i][j][2] + u1.x + q1.x,
                                            acc[i][j][3] + u1.y + q1.y);
        }
    }
}

// =====================================================================
// gemm_rr (linears): C[m][n] = relu(A@W + bias)
// =====================================================================
template<bool THREE>
__global__ __launch_bounds__(256, 2)
void gemm_rr(const float* __restrict__ A, const float* __restrict__ B,
             const float* __restrict__ bias, float* __restrict__ C, int lda) {
    extern __shared__ unsigned sm[];
    unsigned* As  = sm;
    unsigned* Asr = As + 128 * 36;
    unsigned* Bs  = As + (THREE ? 2 : 1) * 128 * 36;
    unsigned* Bsr = Bs + 32 * 136;

    const float* Ab = A;
    const float* Bb = B;
    int n0 = blockIdx.x * 128;
    int m0 = blockIdx.y * 128;
    int tid = threadIdx.x;
    int warp = tid >> 5, lane = tid & 31;
    int g = lane >> 2, t = lane & 3;
    int wm = warp >> 2, wn = warp & 3;
    int la_n = tid >> 3, la_k = (tid & 7) * 4;
    int lb_k = tid >> 5, lb_n = (tid & 31) * 4;

    float acc[4][4][4] = {};

    for (int k0 = 0; k0 < CDIM; k0 += 32) {
#pragma unroll
        for (int u = 0; u < 4; u++) {
            int n = la_n + u * 32;
            float4 v = *(const float4*)&Ab[(size_t)(m0 + n) * lda + k0 + la_k];
            unsigned h0 = f2tf(v.x), h1 = f2tf(v.y), h2 = f2tf(v.z), h3 = f2tf(v.w);
            unsigned* p = &As[n * 36 + la_k];
            p[0] = h0; p[1] = h1; p[2] = h2; p[3] = h3;
            if (THREE) {
                unsigned* q = &Asr[n * 36 + la_k];
                q[0] = f2tf(v.x - __uint_as_float(h0));
                q[1] = f2tf(v.y - __uint_as_float(h1));
                q[2] = f2tf(v.z - __uint_as_float(h2));
                q[3] = f2tf(v.w - __uint_as_float(h3));
            }
        }
#pragma unroll
        for (int u = 0; u < 4; u++) {
            int k = lb_k + u * 8;
            float4 v = *(const float4*)&Bb[(size_t)(k0 + k) * CDIM + n0 + lb_n];
            unsigned h0 = f2tf(v.x), h1 = f2tf(v.y), h2 = f2tf(v.z), h3 = f2tf(v.w);
            unsigned* p = &Bs[k * 136 + lb_n];
            p[0] = h0; p[1] = h1; p[2] = h2; p[3] = h3;
            if (THREE) {
                unsigned* q = &Bsr[k * 136 + lb_n];
                q[0] = f2tf(v.x - __uint_as_float(h0));
                q[1] = f2tf(v.y - __uint_as_float(h1));
                q[2] = f2tf(v.z - __uint_as_float(h2));
                q[3] = f2tf(v.w - __uint_as_float(h3));
            }
        }
        __syncthreads();

#pragma unroll
        for (int c = 0; c < 4; c++) {
            int kc = c * 8;
            unsigned bb[4][2], br[4][2];
#pragma unroll
            for (int j = 0; j < 4; j++) {
                int col = wn * 32 + j * 8 + g;
                bb[j][0] = Bs[(kc + t) * 136 + col];
                bb[j][1] = Bs[(kc + t + 4) * 136 + col];
                if (THREE) {
                    br[j][0] = Bsr[(kc + t) * 136 + col];
                    br[j][1] = Bsr[(kc + t + 4) * 136 + col];
                }
            }
#pragma unroll
            for (int i = 0; i < 4; i++) {
                int row = wm * 64 + i * 16 + g;
                unsigned aa[4], ar[4];
                aa[0] = As[row * 36 + kc + t];
                aa[1] = As[(row + 8) * 36 + kc + t];
                aa[2] = As[row * 36 + kc + t + 4];
                aa[3] = As[(row + 8) * 36 + kc + t + 4];
                if (THREE) {
                    ar[0] = Asr[row * 36 + kc + t];
                    ar[1] = Asr[(row + 8) * 36 + kc + t];
                    ar[2] = Asr[row * 36 + kc + t + 4];
                    ar[3] = Asr[(row + 8) * 36 + kc + t + 4];
                }
#pragma unroll
                for (int j = 0; j < 4; j++) {
                    mma_tf32(acc[i][j], aa, bb[j]);
                    if (THREE) {
                        mma_tf32(acc[i][j], aa, br[j]);
                        mma_tf32(acc[i][j], ar, bb[j]);
                    }
                }
            }
        }
        __syncthreads();
    }

#pragma unroll
    for (int i = 0; i < 4; i++) {
        int r = m0 + wm * 64 + i * 16 + g;
#pragma unroll
        for (int j = 0; j < 4; j++) {
            int cc = n0 + wn * 32 + j * 8 + 2 * t;
            size_t o0 = (size_t)r * CDIM + cc;
            size_t o1 = (size_t)(r + 8) * CDIM + cc;
            float2 bv = *(const float2*)&bias[cc];
            *(float2*)&C[o0] = make_float2(fmaxf(acc[i][j][0] + bv.x, 0.f),
                                           fmaxf(acc[i][j][1] + bv.y, 0.f));
            *(float2*)&C[o1] = make_float2(fmaxf(acc[i][j][2] + bv.x, 0.f),
                                           fmaxf(acc[i][j][3] + bv.y, 0.f));
        }
    }
}

// ---------------- row softmax: read L, write tf32 hi (in place) + lo ----------------
template<bool WLO>
__global__ void softmax_kernel(const float* __restrict__ Lin, unsigned* __restrict__ Ph,
                               unsigned* __restrict__ Pl) {
    size_t ro = ((size_t)blockIdx.y * HW + blockIdx.x) * HW;
    const float* row = Lin + ro;
    int t = threadIdx.x;
    __shared__ float red[16];
    float v[8];
    float mx = -1e30f;
#pragma unroll
    for (int i = 0; i < 8; i++) { v[i] = row[t + i * 512]; mx = fmaxf(mx, v[i]); }
    for (int o = 16; o; o >>= 1) mx = fmaxf(mx, __shfl_xor_sync(0xffffffffu, mx, o));
    int warp = t >> 5, lane = t & 31;
    if (lane == 0) red[warp] = mx;
    __syncthreads();
    if (warp == 0) {
        float m2 = red[lane & 15];
        for (int o = 8; o; o >>= 1) m2 = fmaxf(m2, __shfl_xor_sync(0xffffffffu, m2, o));
        if (lane == 0) red[0] = m2;
    }
    __syncthreads();
    mx = red[0];
    __syncthreads();
    float s = 0.f;
#pragma unroll
    for (int i = 0; i < 8; i++) { v[i] = __expf(v[i] - mx); s += v[i]; }
    for (int o = 16; o; o >>= 1) s += __shfl_xor_sync(0xffffffffu, s, o);
    if (lane == 0) red[warp] = s;
    __syncthreads();
    if (warp == 0) {
        float s2 = red[lane & 15];
        for (int o = 8; o; o >>= 1) s2 += __shfl_xor_sync(0xffffffffu, s2, o);
        if (lane == 0) red[0] = s2;
    }
    __syncthreads();
    float inv = 1.f / red[0];
#pragma unroll
    for (int i = 0; i < 8; i++) {
        float p = v[i] * inv;
        unsigned h = f2tf(p);
        Ph[ro + t + i * 512] = h;
        if (WLO) Pl[ro + t + i * 512] = f2tf(p - __uint_as_float(h));
    }
}

// ---------------- column partial sums over pre-split P ----------------
template<bool WLO>
__global__ void colsum_kernel(const unsigned* __restrict__ Ph,
                              const unsigned* __restrict__ Pl,
                              float* __restrict__ part) {
    int b = blockIdx.z;
    int m = blockIdx.x * 256 + threadIdx.x;
    int r0 = blockIdx.y * 256;
    const float* Phb = (const float*)Ph + (size_t)b * HW * HW;
    const float* Plb = (const float*)Pl + (size_t)b * HW * HW;
    float s = 0.f;
#pragma unroll 8
    for (int r = 0; r < 256; r++) {
        size_t o = (size_t)(r0 + r) * HW + m;
        s += Phb[o];
        if (WLO) s += Plb[o];
    }
    part[((size_t)b * 16 + blockIdx.y) * HW + m] = s;
}

__global__ void colinv_kernel(const float* __restrict__ part, float* __restrict__ colinv) {
    int i = blockIdx.x * 256 + threadIdx.x;
    int b = i >> 12, m = i & (HW - 1);
    float s = 0.f;
#pragma unroll
    for (int c2 = 0; c2 < 16; c2++) s += part[((size_t)b * 16 + c2) * HW + m];
    colinv[i] = 1.f / fmaxf(s, 1e-12f);
}

__global__ void scale_ax_kernel(float* __restrict__ ax, const float* __restrict__ colinv) {
    size_t f4 = (size_t)blockIdx.x * 256 + threadIdx.x;
    int row = (int)(f4 >> 6);
    float sc = colinv[row];
    float4 v = ((float4*)ax)[f4];
    v.x *= sc; v.y *= sc; v.z *= sc; v.w *= sc;
    ((float4*)ax)[f4] = v;
}

// ---------------- launch ----------------
extern "C" void kernel_launch(void* const* d_in, const int* in_sizes, int n_in,
                              void* d_out, int out_size) {
    (void)in_sizes; (void)n_in; (void)out_size;
    const float* skt = (const float*)d_in[0];
    const float* ref = (const float*)d_in[1];
    const float* Wa3 = (const float*)d_in[2];
    const float* ba3 = (const float*)d_in[3];
    const float* Wu3 = (const float*)d_in[4];
    const float* bu3 = (const float*)d_in[5];
    const float* Wa4 = (const float*)d_in[6];
    const float* ba4 = (const float*)d_in[7];
    const float* Wu4 = (const float*)d_in[8];
    const float* bu4 = (const float*)d_in[9];
    float* out = (float*)d_out;

    float *P, *ax, *ux, *gen, *gencn, *sktnc, *refnc, *colpart, *colinv;
    unsigned *Pl, *hi0, *lo0, *hi1, *lo1;
    cudaGetSymbolAddress((void**)&P, g_P);
    cudaGetSymbolAddress((void**)&Pl, g_Pl);
    cudaGetSymbolAddress((void**)&ax, g_ax);
    cudaGetSymbolAddress((void**)&ux, g_ux);
    cudaGetSymbolAddress((void**)&gen, g_gen);
    cudaGetSymbolAddress((void**)&gencn, g_gencn);
    cudaGetSymbolAddress((void**)&sktnc, g_sktnc);
    cudaGetSymbolAddress((void**)&refnc, g_refnc);
    cudaGetSymbolAddress((void**)&colpart, g_colpart);
    cudaGetSymbolAddress((void**)&colinv, g_colinv);
    cudaGetSymbolAddress((void**)&hi0, g_hi0);
    cudaGetSymbolAddress((void**)&lo0, g_lo0);
    cudaGetSymbolAddress((void**)&hi1, g_hi1);
    cudaGetSymbolAddress((void**)&lo1, g_lo1);

    const int SM3   = (2 * 128 * 36 + 2 * 32 * 136) * 4;          // 71680
    const int SM1   = (128 * 36 + 32 * 136) * 4;                  // 35840
    const int SMLC  = 3 * 4 * 32 * 136 * 4;                       // 208896
    const int SMP3  = 3 * 2 * (128 * 36 + 32 * 136) * 4;          // 215040
    const int SMP1  = 4 * (128 * 36 + 32 * 136) * 4;              // 143360
    cudaFuncSetAttribute(gemm_rr<true>,      cudaFuncAttributeMaxDynamicSharedMemorySize, SM3);
    cudaFuncSetAttribute(gemm_rr<false>,     cudaFuncAttributeMaxDynamicSharedMemorySize, SM1);
    cudaFuncSetAttribute(logits_cp<false, 3>, cudaFuncAttributeMaxDynamicSharedMemorySize, SMLC);
    cudaFuncSetAttribute(logits_cp<true, 3>,  cudaFuncAttributeMaxDynamicSharedMemorySize, SMLC);
    cudaFuncSetAttribute(pax_cp<true, 3>,    cudaFuncAttributeMaxDynamicSharedMemorySize, SMP3);
    cudaFuncSetAttribute(pax_cp<false, 4>,   cudaFuncAttributeMaxDynamicSharedMemorySize, SMP1);

    dim3 tb(32, 8);
    dim3 gLin(CDIM / 128, (BATCH * HW) / 128, 1);
    dim3 gLog(HW / 128, HW / 128, BATCH);
    dim3 gPax(CDIM / 128, HW / 128, BATCH);
    const int nSplit = (BATCH * HW * CDIM) / (4 * 256);

    // ===== layer 1 =====
    transpose_kernel<<<dim3(HW / 32, CDIM / 32, BATCH), tb>>>(skt, sktnc, CDIM, HW);
    transpose_kernel<<<dim3(HW / 32, CDIM / 32, BATCH), tb>>>(ref, refnc, CDIM, HW);
    split_kernel<<<nSplit, 256>>>(skt, hi0, lo0);
    split_kernel<<<nSplit, 256>>>(ref, hi1, lo1);
    gemm_rr<true><<<gLin, 256, SM3>>>(refnc, Wa3, ba3, ax, CDIM);
    gemm_rr<true><<<gLin, 256, SM3>>>(sktnc, Wu3, bu3, ux, CDIM);
    logits_cp<false, 3><<<gLog, 256, SMLC>>>(hi0, lo0, hi1, lo1, P);
    softmax_kernel<true><<<dim3(HW, BATCH), 512>>>(P, (unsigned*)P, Pl);
    colsum_kernel<true><<<dim3(HW / 256, 16, BATCH), 256>>>((unsigned*)P, Pl, colpart);
    colinv_kernel<<<(BATCH * HW) / 256, 256>>>(colpart, colinv);
    scale_ax_kernel<<<(BATCH * HW * CDIM) / (4 * 256), 256>>>(ax, colinv);
    split_kernel<<<nSplit, 256>>>(ax, hi1, lo1);            // hi1/lo1 free after logits1
    pax_cp<true, 3><<<gPax, 256, SMP3>>>((unsigned*)P, Pl, hi1, lo1, ux, sktnc, gen);

    // ===== layer 2 =====
    transpose_kernel<<<dim3(CDIM / 32, HW / 32, BATCH), tb>>>(gen, gencn, HW, CDIM);
    split_kernel<<<nSplit, 256>>>(gencn, hi0, lo0);
    gemm_rr<false><<<gLin, 256, SM1>>>(gen, Wa4, ba4, ax, CDIM);
    gemm_rr<false><<<gLin, 256, SM1>>>(gen, Wu4, bu4, ux, CDIM);
    logits_cp<true, 3><<<gLog, 256, SMLC>>>(hi0, lo0, hi0, lo0, P);
    softmax_kernel<false><<<dim3(HW, BATCH), 512>>>(P, (unsigned*)P, Pl);
    colsum_kernel<false><<<dim3(HW / 256, 16, BATCH), 256>>>((unsigned*)P, Pl, colpart);
    colinv_kernel<<<(BATCH * HW) / 256, 256>>>(colpart, colinv);
    scale_ax_kernel<<<(BATCH * HW * CDIM) / (4 * 256), 256>>>(ax, colinv);
    split_kernel<<<nSplit, 256>>>(ax, hi1, lo1);
    pax_cp<false, 4><<<gPax, 256, SMP1>>>((unsigned*)P, nullptr, hi1, nullptr, ux, gen, out);
}

// round 10
// speedup vs baseline: 1.0338x; 1.0338x over previous
#include <cuda_runtime.h>
#include <math.h>

#define BATCH 4
#define CDIM  256
#define HW    4096

// ---------------- scratch (no allocations allowed) ----------------
static __device__ float g_P[(size_t)BATCH * HW * HW];          // 268 MB logits/probs (float)
static __device__ float g_ax[(size_t)BATCH * HW * CDIM];
static __device__ float g_ux[(size_t)BATCH * HW * CDIM];
static __device__ float g_gen[(size_t)BATCH * HW * CDIM];
static __device__ float g_gencn[(size_t)BATCH * HW * CDIM];
static __device__ float g_sktnc[(size_t)BATCH * HW * CDIM];
static __device__ float g_refnc[(size_t)BATCH * HW * CDIM];
static __device__ float g_colpart[(size_t)BATCH * 16 * HW];
static __device__ float g_colinv[(size_t)BATCH * HW];
static __device__ unsigned g_hi0[(size_t)BATCH * HW * CDIM];
static __device__ unsigned g_lo0[(size_t)BATCH * HW * CDIM];
static __device__ unsigned g_hi1[(size_t)BATCH * HW * CDIM];
static __device__ unsigned g_lo1[(size_t)BATCH * HW * CDIM];

// ---------------- tf32 helpers ----------------
__device__ __forceinline__ unsigned f2tf(float x) {
    unsigned r;
    asm("cvt.rna.tf32.f32 %0, %1;" : "=r"(r) : "f"(x));
    return r;
}

__device__ __forceinline__ void mma_tf32(float* d, const unsigned* a, const unsigned* b) {
    asm("mma.sync.aligned.m16n8k8.row.col.f32.tf32.tf32.f32 "
        "{%0,%1,%2,%3},{%4,%5,%6,%7},{%8,%9},{%0,%1,%2,%3};"
        : "+f"(d[0]), "+f"(d[1]), "+f"(d[2]), "+f"(d[3])
        : "r"(a[0]), "r"(a[1]), "r"(a[2]), "r"(a[3]), "r"(b[0]), "r"(b[1]));
}

__device__ __forceinline__ void cpa16(unsigned saddr, const void* g) {
    asm volatile("cp.async.cg.shared.global [%0], [%1], 16;\n" :: "r"(saddr), "l"(g));
}

template<int N>
__device__ __forceinline__ void cp_wait() {
    asm volatile("cp.async.wait_group %0;\n" :: "n"(N) : "memory");
}

// ---------------- split: float -> (tf32 hi, tf32 lo) ----------------
__global__ void split_kernel(const float* __restrict__ in, unsigned* __restrict__ hi,
                             unsigned* __restrict__ lo) {
    size_t i = (size_t)blockIdx.x * 256 + threadIdx.x;
    float4 v = ((const float4*)in)[i];
    uint4 h, l;
    h.x = f2tf(v.x); l.x = f2tf(v.x - __uint_as_float(h.x));
    h.y = f2tf(v.y); l.y = f2tf(v.y - __uint_as_float(h.y));
    h.z = f2tf(v.z); l.z = f2tf(v.z - __uint_as_float(h.z));
    h.w = f2tf(v.w); l.w = f2tf(v.w - __uint_as_float(h.w));
    ((uint4*)hi)[i] = h;
    ((uint4*)lo)[i] = l;
}

// ---------------- fused: ax *= colinv[row]; split to hi/lo ----------------
__global__ void scale_split_kernel(const float* __restrict__ ax,
                                   const float* __restrict__ colinv,
                                   unsigned* __restrict__ hi, unsigned* __restrict__ lo) {
    size_t i = (size_t)blockIdx.x * 256 + threadIdx.x;   // float4 index
    int row = (int)(i >> 6);                             // 64 float4 per row
    float sc = colinv[row];
    float4 v = ((const float4*)ax)[i];
    v.x *= sc; v.y *= sc; v.z *= sc; v.w *= sc;
    uint4 h, l;
    h.x = f2tf(v.x); l.x = f2tf(v.x - __uint_as_float(h.x));
    h.y = f2tf(v.y); l.y = f2tf(v.y - __uint_as_float(h.y));
    h.z = f2tf(v.z); l.z = f2tf(v.z - __uint_as_float(h.z));
    h.w = f2tf(v.w); l.w = f2tf(v.w - __uint_as_float(h.w));
    ((uint4*)hi)[i] = h;
    ((uint4*)lo)[i] = l;
}

// ---------------- transpose ----------------
__global__ void transpose_kernel(const float* __restrict__ in, float* __restrict__ out,
                                 int R, int S) {
    __shared__ float tile[32][33];
    int b = blockIdx.z;
    int s0 = blockIdx.x * 32, r0 = blockIdx.y * 32;
    const float* inb = in + (size_t)b * R * S;
    float* outb = out + (size_t)b * R * S;
    int tx = threadIdx.x, ty = threadIdx.y;
#pragma unroll
    for (int i = 0; i < 32; i += 8)
        tile[ty + i][tx] = inb[(size_t)(r0 + ty + i) * S + s0 + tx];
    __syncthreads();
#pragma unroll
    for (int i = 0; i < 32; i += 8)
        outb[(size_t)(s0 + ty + i) * R + r0 + tx] = tile[tx][ty + i];
}

// =====================================================================
// logits_cp: L[n][m] = sum_k A[k][n]*B[k][m], 3xTF32 pre-split, NST-stage
// pipeline with (NST-1)-deep overlap.
// =====================================================================
template<bool SYM, int NST>
__global__ __launch_bounds__(256)
void logits_cp(const unsigned* __restrict__ Ah, const unsigned* __restrict__ Al,
               const unsigned* __restrict__ Bh, const unsigned* __restrict__ Bl,
               float* __restrict__ L) {
    extern __shared__ unsigned sm[];
    constexpr int ARR = 32 * 136;
    constexpr int STG = 4 * ARR;
    constexpr int NIT = CDIM / 32;     // 8

    int bx = blockIdx.x, by = blockIdx.y, b = blockIdx.z;
    if (SYM && bx < by) return;
    int m0 = bx * 128, n0 = by * 128;

    const unsigned* Ahb = Ah + (size_t)b * CDIM * HW;
    const unsigned* Alb = Al + (size_t)b * CDIM * HW;
    const unsigned* Bhb = Bh + (size_t)b * CDIM * HW;
    const unsigned* Blb = Bl + (size_t)b * CDIM * HW;
    float* Lb = L + (size_t)b * HW * HW;

    unsigned sbase;
    asm("{ .reg .u64 t0; cvta.to.shared.u64 t0, %1; cvt.u32.u64 %0, t0; }"
        : "=r"(sbase) : "l"(sm));

    int tid = threadIdx.x;
    int warp = tid >> 5, lane = tid & 31;
    int g = lane >> 2, t = lane & 3;
    int wm = warp >> 2, wn = warp & 3;

    auto prefetch = [&](int it, int s) {
        int k0 = it * 32;
        unsigned sb = sbase + (unsigned)(s * STG) * 4u;
#pragma unroll
        for (int q = 0; q < 4; q++) {
            int f = tid + q * 256;
            int k = f >> 5, c4 = (f & 31) * 4;
            size_t go = (size_t)(k0 + k) * HW;
            unsigned so = sb + (unsigned)(k * 136 + c4) * 4u;
            cpa16(so + 0u * ARR * 4u, Ahb + go + n0 + c4);
            cpa16(so + 1u * ARR * 4u, Alb + go + n0 + c4);
            cpa16(so + 2u * ARR * 4u, Bhb + go + m0 + c4);
            cpa16(so + 3u * ARR * 4u, Blb + go + m0 + c4);
        }
        asm volatile("cp.async.commit_group;\n" ::: "memory");
    };

    float acc[4][4][4] = {};

#pragma unroll
    for (int p = 0; p < NST - 1; p++) prefetch(p, p);

    for (int it = 0; it < NIT; it++) {
        int nx = it + NST - 1;
        if (nx < NIT) { prefetch(nx, nx % NST); cp_wait<NST - 1>(); }
        else cp_wait<0>();
        __syncthreads();

        const unsigned* As  = sm + (it % NST) * STG;
        const unsigned* Asr = As + ARR;
        const unsigned* Bs  = As + 2 * ARR;
        const unsigned* Bsr = As + 3 * ARR;

#pragma unroll
        for (int c = 0; c < 4; c++) {
            int kc = c * 8;
            unsigned bb[4][2], br[4][2];
#pragma unroll
            for (int j = 0; j < 4; j++) {
                int col = wn * 32 + j * 8 + g;
                bb[j][0] = Bs[(kc + t) * 136 + col];
                bb[j][1] = Bs[(kc + t + 4) * 136 + col];
                br[j][0] = Bsr[(kc + t) * 136 + col];
                br[j][1] = Bsr[(kc + t + 4) * 136 + col];
            }
#pragma unroll
            for (int i = 0; i < 4; i++) {
                int row = wm * 64 + i * 16 + g;
                unsigned aa[4], ar[4];
                aa[0] = As[(kc + t) * 136 + row];
                aa[1] = As[(kc + t) * 136 + row + 8];
                aa[2] = As[(kc + t + 4) * 136 + row];
                aa[3] = As[(kc + t + 4) * 136 + row + 8];
                ar[0] = Asr[(kc + t) * 136 + row];
                ar[1] = Asr[(kc + t) * 136 + row + 8];
                ar[2] = Asr[(kc + t + 4) * 136 + row];
                ar[3] = Asr[(kc + t + 4) * 136 + row + 8];
#pragma unroll
                for (int j = 0; j < 4; j++) {
                    mma_tf32(acc[i][j], aa, bb[j]);
                    mma_tf32(acc[i][j], aa, br[j]);
                    mma_tf32(acc[i][j], ar, bb[j]);
                }
            }
        }
        __syncthreads();
    }

#pragma unroll
    for (int i = 0; i < 4; i++) {
        int r = n0 + wm * 64 + i * 16 + g;
#pragma unroll
        for (int j = 0; j < 4; j++) {
            int cc = m0 + wn * 32 + j * 8 + 2 * t;
            *(float2*)&Lb[(size_t)r * HW + cc] =
                make_float2(acc[i][j][0], acc[i][j][1]);
            *(float2*)&Lb[(size_t)(r + 8) * HW + cc] =
                make_float2(acc[i][j][2], acc[i][j][3]);
        }
    }
    if (SYM && bx != by) {
#pragma unroll
        for (int i = 0; i < 4; i++) {
            int rr = n0 + wm * 64 + i * 16 + g;
#pragma unroll
            for (int j = 0; j < 4; j++) {
                int cc = m0 + wn * 32 + j * 8 + 2 * t;
                Lb[(size_t)cc * HW + rr]           = acc[i][j][0];
                Lb[(size_t)(cc + 1) * HW + rr]     = acc[i][j][1];
                Lb[(size_t)cc * HW + rr + 8]       = acc[i][j][2];
                Lb[(size_t)(cc + 1) * HW + rr + 8] = acc[i][j][3];
            }
        }
    }
}

// =====================================================================
// pax_cp: C[n][d] = sum_k P[n][k]*ax[k][d] + U + R.
// P staged as FLOAT via cp.async; hi/lo split at fragment load (3x) or
// single cvt (1x). ax pre-split hi(/lo). 2 CTAs/SM.
// =====================================================================
template<bool THREE, int NST>
__global__ __launch_bounds__(256)
void pax_cp(const float* __restrict__ Pf,
            const unsigned* __restrict__ Bh, const unsigned* __restrict__ Bl,
            const float* __restrict__ U, const float* __restrict__ Rr,
            float* __restrict__ C) {
    extern __shared__ unsigned sm[];
    constexpr int AW = 128 * 36;                 // float P tile words
    constexpr int BW = 32 * 136;
    constexpr int STG = AW + (THREE ? 2 : 1) * BW;
    constexpr int NIT = HW / 32;                 // 128

    int b = blockIdx.z;
    int d0 = blockIdx.x * 128;
    int n0 = blockIdx.y * 128;

    const float* Pb = Pf + (size_t)b * HW * HW;
    const unsigned* Bhb = Bh + (size_t)b * HW * CDIM;
    const unsigned* Blb = THREE ? Bl + (size_t)b * HW * CDIM : nullptr;

    unsigned sbase;
    asm("{ .reg .u64 t0; cvta.to.shared.u64 t0, %1; cvt.u32.u64 %0, t0; }"
        : "=r"(sbase) : "l"(sm));

    int tid = threadIdx.x;
    int warp = tid >> 5, lane = tid & 31;
    int g = lane >> 2, t = lane & 3;
    int wm = warp >> 2, wn = warp & 3;

    auto prefetch = [&](int it, int s) {
        int k0 = it * 32;
        unsigned sb = sbase + (unsigned)(s * STG) * 4u;
#pragma unroll
        for (int q = 0; q < 4; q++) {
            int f = tid + q * 256;
            int n = f >> 3, c4 = (f & 7) * 4;
            cpa16(sb + (unsigned)(n * 36 + c4) * 4u,
                  Pb + (size_t)(n0 + n) * HW + k0 + c4);
        }
#pragma unroll
        for (int q = 0; q < 4; q++) {
            int f = tid + q * 256;
            int k = f >> 5, d4 = (f & 31) * 4;
            size_t go = (size_t)(k0 + k) * CDIM + d0 + d4;
            unsigned so = sb + (unsigned)(AW + k * 136 + d4) * 4u;
            cpa16(so, Bhb + go);
            if (THREE) cpa16(so + BW * 4u, Blb + go);
        }
        asm volatile("cp.async.commit_group;\n" ::: "memory");
    };

    float acc[4][4][4] = {};

#pragma unroll
    for (int p = 0; p < NST - 1; p++) prefetch(p, p);

    for (int it = 0; it < NIT; it++) {
        int nx = it + NST - 1;
        if (nx < NIT) { prefetch(nx, nx % NST); cp_wait<NST - 1>(); }
        else cp_wait<0>();
        __syncthreads();

        const float* As = (const float*)(sm + (it % NST) * STG);
        const unsigned* Bs  = (const unsigned*)(As + AW);
        const unsigned* Bsr = Bs + BW;

#pragma unroll
        for (int c = 0; c < 4; c++) {
            int kc = c * 8;
            unsigned bb[4][2], br[4][2];
#pragma unroll
            for (int j = 0; j < 4; j++) {
                int col = wn * 32 + j * 8 + g;
                bb[j][0] = Bs[(kc + t) * 136 + col];
                bb[j][1] = Bs[(kc + t + 4) * 136 + col];
                if (THREE) {
                    br[j][0] = Bsr[(kc + t) * 136 + col];
                    br[j][1] = Bsr[(kc + t + 4) * 136 + col];
                }
            }
#pragma unroll
            for (int i = 0; i < 4; i++) {
                int row = wm * 64 + i * 16 + g;
                float va[4];
                va[0] = As[row * 36 + kc + t];
                va[1] = As[(row + 8) * 36 + kc + t];
                va[2] = As[row * 36 + kc + t + 4];
                va[3] = As[(row + 8) * 36 + kc + t + 4];
                unsigned aa[4], ar[4];
#pragma unroll
                for (int e = 0; e < 4; e++) {
                    aa[e] = f2tf(va[e]);
                    if (THREE) ar[e] = f2tf(va[e] - __uint_as_float(aa[e]));
                }
#pragma unroll
                for (int j = 0; j < 4; j++) {
                    mma_tf32(acc[i][j], aa, bb[j]);
                    if (THREE) {
                        mma_tf32(acc[i][j], aa, br[j]);
                        mma_tf32(acc[i][j], ar, bb[j]);
                    }
                }
            }
        }
        __syncthreads();
    }

    const float* Ub = U + (size_t)b * HW * CDIM;
    const float* Rb = Rr + (size_t)b * HW * CDIM;
    float* Cb = C + (size_t)b * HW * CDIM;
#pragma unroll
    for (int i = 0; i < 4; i++) {
        int r = n0 + wm * 64 + i * 16 + g;
#pragma unroll
        for (int j = 0; j < 4; j++) {
            int cc = d0 + wn * 32 + j * 8 + 2 * t;
            size_t o0 = (size_t)r * CDIM + cc;
            size_t o1 = (size_t)(r + 8) * CDIM + cc;
            float2 u0 = *(const float2*)&Ub[o0], u1 = *(const float2*)&Ub[o1];
            float2 q0 = *(const float2*)&Rb[o0], q1 = *(const float2*)&Rb[o1];
            *(float2*)&Cb[o0] = make_float2(acc[i][j][0] + u0.x + q0.x,
                                            acc[i][j][1] + u0.y + q0.y);
            *(float2*)&Cb[o1] = make_float2(acc[i][j][2] + u1.x + q1.x,
                                            acc[i][j][3] + u1.y + q1.y);
        }
    }
}

// =====================================================================
// gemm_rr (linears): C[m][n] = relu(A@W + bias)   (proven)
// =====================================================================
template<bool THREE>
__global__ __launch_bounds__(256, 2)
void gemm_rr(const float* __restrict__ A, const float* __restrict__ B,
             const float* __restrict__ bias, float* __restrict__ C, int lda) {
    extern __shared__ unsigned sm[];
    unsigned* As  = sm;
    unsigned* Asr = As + 128 * 36;
    unsigned* Bs  = As + (THREE ? 2 : 1) * 128 * 36;
    unsigned* Bsr = Bs + 32 * 136;

    int n0 = blockIdx.x * 128;
    int m0 = blockIdx.y * 128;
    int tid = threadIdx.x;
    int warp = tid >> 5, lane = tid & 31;
    int g = lane >> 2, t = lane & 3;
    int wm = warp >> 2, wn = warp & 3;
    int la_n = tid >> 3, la_k = (tid & 7) * 4;
    int lb_k = tid >> 5, lb_n = (tid & 31) * 4;

    float acc[4][4][4] = {};

    for (int k0 = 0; k0 < CDIM; k0 += 32) {
#pragma unroll
        for (int u = 0; u < 4; u++) {
            int n = la_n + u * 32;
            float4 v = *(const float4*)&A[(size_t)(m0 + n) * lda + k0 + la_k];
            unsigned h0 = f2tf(v.x), h1 = f2tf(v.y), h2 = f2tf(v.z), h3 = f2tf(v.w);
            unsigned* p = &As[n * 36 + la_k];
            p[0] = h0; p[1] = h1; p[2] = h2; p[3] = h3;
            if (THREE) {
                unsigned* q = &Asr[n * 36 + la_k];
                q[0] = f2tf(v.x - __uint_as_float(h0));
                q[1] = f2tf(v.y - __uint_as_float(h1));
                q[2] = f2tf(v.z - __uint_as_float(h2));
                q[3] = f2tf(v.w - __uint_as_float(h3));
            }
        }
#pragma unroll
        for (int u = 0; u < 4; u++) {
            int k = lb_k + u * 8;
            float4 v = *(const float4*)&B[(size_t)(k0 + k) * CDIM + n0 + lb_n];
            unsigned h0 = f2tf(v.x), h1 = f2tf(v.y), h2 = f2tf(v.z), h3 = f2tf(v.w);
            unsigned* p = &Bs[k * 136 + lb_n];
            p[0] = h0; p[1] = h1; p[2] = h2; p[3] = h3;
            if (THREE) {
                unsigned* q = &Bsr[k * 136 + lb_n];
                q[0] = f2tf(v.x - __uint_as_float(h0));
                q[1] = f2tf(v.y - __uint_as_float(h1));
                q[2] = f2tf(v.z - __uint_as_float(h2));
                q[3] = f2tf(v.w - __uint_as_float(h3));
            }
        }
        __syncthreads();

#pragma unroll
        for (int c = 0; c < 4; c++) {
            int kc = c * 8;
            unsigned bb[4][2], br[4][2];
#pragma unroll
            for (int j = 0; j < 4; j++) {
                int col = wn * 32 + j * 8 + g;
                bb[j][0] = Bs[(kc + t) * 136 + col];
                bb[j][1] = Bs[(kc + t + 4) * 136 + col];
                if (THREE) {
                    br[j][0] = Bsr[(kc + t) * 136 + col];
                    br[j][1] = Bsr[(kc + t + 4) * 136 + col];
                }
            }
#pragma unroll
            for (int i = 0; i < 4; i++) {
                int row = wm * 64 + i * 16 + g;
                unsigned aa[4], ar[4];
                aa[0] = As[row * 36 + kc + t];
                aa[1] = As[(row + 8) * 36 + kc + t];
                aa[2] = As[row * 36 + kc + t + 4];
                aa[3] = As[(row + 8) * 36 + kc + t + 4];
                if (THREE) {
                    ar[0] = Asr[row * 36 + kc + t];
                    ar[1] = Asr[(row + 8) * 36 + kc + t];
                    ar[2] = Asr[row * 36 + kc + t + 4];
                    ar[3] = Asr[(row + 8) * 36 + kc + t + 4];
                }
#pragma unroll
                for (int j = 0; j < 4; j++) {
                    mma_tf32(acc[i][j], aa, bb[j]);
                    if (THREE) {
                        mma_tf32(acc[i][j], aa, br[j]);
                        mma_tf32(acc[i][j], ar, bb[j]);
                    }
                }
            }
        }
        __syncthreads();
    }

#pragma unroll
    for (int i = 0; i < 4; i++) {
        int r = m0 + wm * 64 + i * 16 + g;
#pragma unroll
        for (int j = 0; j < 4; j++) {
            int cc = n0 + wn * 32 + j * 8 + 2 * t;
            size_t o0 = (size_t)r * CDIM + cc;
            size_t o1 = (size_t)(r + 8) * CDIM + cc;
            float2 bv = *(const float2*)&bias[cc];
            *(float2*)&C[o0] = make_float2(fmaxf(acc[i][j][0] + bv.x, 0.f),
                                           fmaxf(acc[i][j][1] + bv.y, 0.f));
            *(float2*)&C[o1] = make_float2(fmaxf(acc[i][j][2] + bv.x, 0.f),
                                           fmaxf(acc[i][j][3] + bv.y, 0.f));
        }
    }
}

// ---------------- row softmax in place (float) ----------------
__global__ void softmax_kernel(float* __restrict__ P) {
    float* row = P + ((size_t)blockIdx.y * HW + blockIdx.x) * HW;
    int t = threadIdx.x;
    __shared__ float red[16];
    float v[8];
    float mx = -1e30f;
#pragma unroll
    for (int i = 0; i < 8; i++) { v[i] = row[t + i * 512]; mx = fmaxf(mx, v[i]); }
    for (int o = 16; o; o >>= 1) mx = fmaxf(mx, __shfl_xor_sync(0xffffffffu, mx, o));
    int warp = t >> 5, lane = t & 31;
    if (lane == 0) red[warp] = mx;
    __syncthreads();
    if (warp == 0) {
        float m2 = red[lane & 15];
        for (int o = 8; o; o >>= 1) m2 = fmaxf(m2, __shfl_xor_sync(0xffffffffu, m2, o));
        if (lane == 0) red[0] = m2;
    }
    __syncthreads();
    mx = red[0];
    __syncthreads();
    float s = 0.f;
#pragma unroll
    for (int i = 0; i < 8; i++) { v[i] = __expf(v[i] - mx); s += v[i]; }
    for (int o = 16; o; o >>= 1) s += __shfl_xor_sync(0xffffffffu, s, o);
    if (lane == 0) red[warp] = s;
    __syncthreads();
    if (warp == 0) {
        float s2 = red[lane & 15];
        for (int o = 8; o; o >>= 1) s2 += __shfl_xor_sync(0xffffffffu, s2, o);
        if (lane == 0) red[0] = s2;
    }
    __syncthreads();
    float inv = 1.f / red[0];
#pragma unroll
    for (int i = 0; i < 8; i++) row[t + i * 512] = v[i] * inv;
}

// ---------------- column partial sums (float P) ----------------
__global__ void colsum_kernel(const float* __restrict__ P, float* __restrict__ part) {
    int b = blockIdx.z;
    int m = blockIdx.x * 256 + threadIdx.x;
    int r0 = blockIdx.y * 256;
    const float* Pb = P + (size_t)b * HW * HW;
    float s = 0.f;
#pragma unroll 8
    for (int r = 0; r < 256; r++) s += Pb[(size_t)(r0 + r) * HW + m];
    part[((size_t)b * 16 + blockIdx.y) * HW + m] = s;
}

__global__ void colinv_kernel(const float* __restrict__ part, float* __restrict__ colinv) {
    int i = blockIdx.x * 256 + threadIdx.x;
    int b = i >> 12, m = i & (HW - 1);
    float s = 0.f;
#pragma unroll
    for (int c2 = 0; c2 < 16; c2++) s += part[((size_t)b * 16 + c2) * HW + m];
    colinv[i] = 1.f / fmaxf(s, 1e-12f);
}

// ---------------- launch ----------------
extern "C" void kernel_launch(void* const* d_in, const int* in_sizes, int n_in,
                              void* d_out, int out_size) {
    (void)in_sizes; (void)n_in; (void)out_size;
    const float* skt = (const float*)d_in[0];
    const float* ref = (const float*)d_in[1];
    const float* Wa3 = (const float*)d_in[2];
    const float* ba3 = (const float*)d_in[3];
    const float* Wu3 = (const float*)d_in[4];
    const float* bu3 = (const float*)d_in[5];
    const float* Wa4 = (const float*)d_in[6];
    const float* ba4 = (const float*)d_in[7];
    const float* Wu4 = (const float*)d_in[8];
    const float* bu4 = (const float*)d_in[9];
    float* out = (float*)d_out;

    float *P, *ax, *ux, *gen, *gencn, *sktnc, *refnc, *colpart, *colinv;
    unsigned *hi0, *lo0, *hi1, *lo1;
    cudaGetSymbolAddress((void**)&P, g_P);
    cudaGetSymbolAddress((void**)&ax, g_ax);
    cudaGetSymbolAddress((void**)&ux, g_ux);
    cudaGetSymbolAddress((void**)&gen, g_gen);
    cudaGetSymbolAddress((void**)&gencn, g_gencn);
    cudaGetSymbolAddress((void**)&sktnc, g_sktnc);
    cudaGetSymbolAddress((void**)&refnc, g_refnc);
    cudaGetSymbolAddress((void**)&colpart, g_colpart);
    cudaGetSymbolAddress((void**)&colinv, g_colinv);
    cudaGetSymbolAddress((void**)&hi0, g_hi0);
    cudaGetSymbolAddress((void**)&lo0, g_lo0);
    cudaGetSymbolAddress((void**)&hi1, g_hi1);
    cudaGetSymbolAddress((void**)&lo1, g_lo1);

    const int SM3   = (2 * 128 * 36 + 2 * 32 * 136) * 4;              // 71680
    const int SM1   = (128 * 36 + 32 * 136) * 4;                      // 35840
    const int SMLC  = 3 * 4 * 32 * 136 * 4;                           // 208896
    const int SMP3  = 2 * (128 * 36 + 2 * 32 * 136) * 4;              // 106496
    const int SMP1  = 3 * (128 * 36 + 32 * 136) * 4;                  // 107520
    cudaFuncSetAttribute(gemm_rr<true>,       cudaFuncAttributeMaxDynamicSharedMemorySize, SM3);
    cudaFuncSetAttribute(gemm_rr<false>,      cudaFuncAttributeMaxDynamicSharedMemorySize, SM1);
    cudaFuncSetAttribute(logits_cp<false, 3>, cudaFuncAttributeMaxDynamicSharedMemorySize, SMLC);
    cudaFuncSetAttribute(logits_cp<true, 3>,  cudaFuncAttributeMaxDynamicSharedMemorySize, SMLC);
    cudaFuncSetAttribute(pax_cp<true, 2>,     cudaFuncAttributeMaxDynamicSharedMemorySize, SMP3);
    cudaFuncSetAttribute(pax_cp<false, 3>,    cudaFuncAttributeMaxDynamicSharedMemorySize, SMP1);

    dim3 tb(32, 8);
    dim3 gLin(CDIM / 128, (BATCH * HW) / 128, 1);
    dim3 gLog(HW / 128, HW / 128, BATCH);
    dim3 gPax(CDIM / 128, HW / 128, BATCH);
    const int nSplit = (BATCH * HW * CDIM) / (4 * 256);

    // ===== layer 1 =====
    transpose_kernel<<<dim3(HW / 32, CDIM / 32, BATCH), tb>>>(skt, sktnc, CDIM, HW);
    transpose_kernel<<<dim3(HW / 32, CDIM / 32, BATCH), tb>>>(ref, refnc, CDIM, HW);
    split_kernel<<<nSplit, 256>>>(skt, hi0, lo0);
    split_kernel<<<nSplit, 256>>>(ref, hi1, lo1);
    gemm_rr<true><<<gLin, 256, SM3>>>(refnc, Wa3, ba3, ax, CDIM);
    gemm_rr<true><<<gLin, 256, SM3>>>(sktnc, Wu3, bu3, ux, CDIM);
    logits_cp<false, 3><<<gLog, 256, SMLC>>>(hi0, lo0, hi1, lo1, P);
    softmax_kernel<<<dim3(HW, BATCH), 512>>>(P);
    colsum_kernel<<<dim3(HW / 256, 16, BATCH), 256>>>(P, colpart);
    colinv_kernel<<<(BATCH * HW) / 256, 256>>>(colpart, colinv);
    scale_split_kernel<<<nSplit, 256>>>(ax, colinv, hi1, lo1);   // hi1/lo1 free after logits1
    pax_cp<true, 2><<<gPax, 256, SMP3>>>(P, hi1, lo1, ux, sktnc, gen);

    // ===== layer 2 =====
    transpose_kernel<<<dim3(CDIM / 32, HW / 32, BATCH), tb>>>(gen, gencn, HW, CDIM);
    split_kernel<<<nSplit, 256>>>(gencn, hi0, lo0);
    gemm_rr<false><<<gLin, 256, SM1>>>(gen, Wa4, ba4, ax, CDIM);
    gemm_rr<false><<<gLin, 256, SM1>>>(gen, Wu4, bu4, ux, CDIM);
    logits_cp<true, 3><<<gLog, 256, SMLC>>>(hi0, lo0, hi0, lo0, P);
    softmax_kernel<<<dim3(HW, BATCH), 512>>>(P);
    colsum_kernel<<<dim3(HW / 256, 16, BATCH), 256>>>(P, colpart);
    colinv_kernel<<<(BATCH * HW) / 256, 256>>>(colpart, colinv);
    scale_split_kernel<<<nSplit, 256>>>(ax, colinv, hi1, lo1);
    pax_cp<false, 3><<<gPax, 256, SMP1>>>(P, hi1, nullptr, ux, gen, out);
}

// round 12
// speedup vs baseline: 1.4469x; 1.3996x over previous
#include <cuda_runtime.h>
#include <cuda_bf16.h>
#include <math.h>

#define BATCH 4
#define CDIM  256
#define HW    4096
#define NPL   ((size_t)BATCH * HW * CDIM)   // elements per bf16 plane (operand)

typedef unsigned short ushortT;

// ---------------- scratch (no allocations allowed) ----------------
static __device__ float g_P[(size_t)BATCH * HW * HW];          // logits / probs (float)
static __device__ ushortT g_Pb0[(size_t)BATCH * HW * HW];      // P bf16 hi plane
static __device__ ushortT g_Pb1[(size_t)BATCH * HW * HW];      // P bf16 lo plane
static __device__ float g_ax[(size_t)BATCH * HW * CDIM];
static __device__ float g_ux[(size_t)BATCH * HW * CDIM];
static __device__ float g_gen[(size_t)BATCH * HW * CDIM];
static __device__ float g_sktnc[(size_t)BATCH * HW * CDIM];
static __device__ float g_refnc[(size_t)BATCH * HW * CDIM];
static __device__ float g_colpart[(size_t)BATCH * 16 * HW];
static __device__ float g_colinv[(size_t)BATCH * HW];
static __device__ unsigned g_hi0[(size_t)BATCH * HW * CDIM];   // 2 bf16 planes (A)
static __device__ unsigned g_lo0[(size_t)BATCH * HW * CDIM];   // 2 bf16 planes (B)
static __device__ unsigned g_hi1[(size_t)BATCH * HW * CDIM];   // 2 bf16 planes (axT)
static __device__ unsigned g_lo1[(size_t)BATCH * HW * CDIM];   // tf32 hi for pax2

// ---------------- helpers ----------------
__device__ __forceinline__ unsigned f2tf(float x) {
    unsigned r;
    asm("cvt.rna.tf32.f32 %0, %1;" : "=r"(r) : "f"(x));
    return r;
}

__device__ __forceinline__ void mma_tf32(float* d, const unsigned* a, const unsigned* b) {
    asm("mma.sync.aligned.m16n8k8.row.col.f32.tf32.tf32.f32 "
        "{%0,%1,%2,%3},{%4,%5,%6,%7},{%8,%9},{%0,%1,%2,%3};"
        : "+f"(d[0]), "+f"(d[1]), "+f"(d[2]), "+f"(d[3])
        : "r"(a[0]), "r"(a[1]), "r"(a[2]), "r"(a[3]), "r"(b[0]), "r"(b[1]));
}

__device__ __forceinline__ void mma_bf16(float* d, const unsigned* a, const unsigned* b) {
    asm("mma.sync.aligned.m16n8k16.row.col.f32.bf16.bf16.f32 "
        "{%0,%1,%2,%3},{%4,%5,%6,%7},{%8,%9},{%0,%1,%2,%3};"
        : "+f"(d[0]), "+f"(d[1]), "+f"(d[2]), "+f"(d[3])
        : "r"(a[0]), "r"(a[1]), "r"(a[2]), "r"(a[3]), "r"(b[0]), "r"(b[1]));
}

__device__ __forceinline__ void cpa16(unsigned saddr, const void* g) {
    asm volatile("cp.async.cg.shared.global [%0], [%1], 16;\n" :: "r"(saddr), "l"(g));
}

template<int N>
__device__ __forceinline__ void cp_wait() {
    asm volatile("cp.async.wait_group %0;\n" :: "n"(N) : "memory");
}

__device__ __forceinline__ unsigned smem_u32(const void* p) {
    unsigned a;
    asm("{ .reg .u64 t; cvta.to.shared.u64 t, %1; cvt.u32.u64 %0, t; }" : "=r"(a) : "l"(p));
    return a;
}

__device__ __forceinline__ void bsplit(float x, ushortT& h, ushortT& l) {
    __nv_bfloat16 b0 = __float2bfloat16(x);
    __nv_bfloat16 b1 = __float2bfloat16(x - __bfloat162float(b0));
    h = __bfloat16_as_ushort(b0);
    l = __bfloat16_as_ushort(b1);
}

// ---------------- bf16 2-plane split: float -> (hi, lo) ----------------
__global__ void bsplit2_kernel(const float* __restrict__ in,
                               ushortT* __restrict__ p0, ushortT* __restrict__ p1) {
    size_t i = (size_t)blockIdx.x * 256 + threadIdx.x;   // float4 index
    float4 v = ((const float4*)in)[i];
    float x[4] = {v.x, v.y, v.z, v.w};
    ushortT h[4], l[4];
#pragma unroll
    for (int e = 0; e < 4; e++) bsplit(x[e], h[e], l[e]);
    ((uint2*)p0)[i] = make_uint2(h[0] | ((unsigned)h[1] << 16), h[2] | ((unsigned)h[3] << 16));
    ((uint2*)p1)[i] = make_uint2(l[0] | ((unsigned)l[1] << 16), l[2] | ((unsigned)l[3] << 16));
}

// ---------------- tf32 scale+split (for pax2) ----------------
__global__ void scale_split_kernel(const float* __restrict__ ax,
                                   const float* __restrict__ colinv,
                                   unsigned* __restrict__ hi) {
    size_t i = (size_t)blockIdx.x * 256 + threadIdx.x;
    int row = (int)(i >> 6);
    float sc = colinv[row];
    float4 v = ((const float4*)ax)[i];
    uint4 h;
    h.x = f2tf(v.x * sc); h.y = f2tf(v.y * sc);
    h.z = f2tf(v.z * sc); h.w = f2tf(v.w * sc);
    ((uint4*)hi)[i] = h;
}

// ---------------- ax scale + transpose + bf16 split -> axT planes [d][k] ----------------
__global__ void axt_split_kernel(const float* __restrict__ ax, const float* __restrict__ colinv,
                                 ushortT* __restrict__ p0, ushortT* __restrict__ p1) {
    __shared__ float tile[32][33];
    int b = blockIdx.z;
    int k0 = blockIdx.x * 32, d0 = blockIdx.y * 32;
    int tx = threadIdx.x, ty = threadIdx.y;
    const float* axb = ax + (size_t)b * HW * CDIM;
#pragma unroll
    for (int i = 0; i < 32; i += 8) {
        float sc = colinv[(b << 12) + k0 + ty + i];
        tile[ty + i][tx] = axb[(size_t)(k0 + ty + i) * CDIM + d0 + tx] * sc;
    }
    __syncthreads();
#pragma unroll
    for (int i = 0; i < 32; i += 8) {
        float v = tile[tx][ty + i];
        ushortT h, l;
        bsplit(v, h, l);
        size_t o = (size_t)b * CDIM * HW + (size_t)(d0 + ty + i) * HW + k0 + tx;
        p0[o] = h;
        p1[o] = l;
    }
}

// ---------------- transpose ----------------
__global__ void transpose_kernel(const float* __restrict__ in, float* __restrict__ out,
                                 int R, int S) {
    __shared__ float tile[32][33];
    int b = blockIdx.z;
    int s0 = blockIdx.x * 32, r0 = blockIdx.y * 32;
    const float* inb = in + (size_t)b * R * S;
    float* outb = out + (size_t)b * R * S;
    int tx = threadIdx.x, ty = threadIdx.y;
#pragma unroll
    for (int i = 0; i < 32; i += 8)
        tile[ty + i][tx] = inb[(size_t)(r0 + ty + i) * S + s0 + tx];
    __syncthreads();
#pragma unroll
    for (int i = 0; i < 32; i += 8)
        outb[(size_t)(s0 + ty + i) * R + r0 + tx] = tile[tx][ty + i];
}

// =====================================================================
// bf16 3-product GEMM core: D[n][m] += A[n][k] * B[m][k]^T
// Both operands m-major [row][k] bf16 planes (hi, lo). BK=32.
// SMEM per operand-plane tile: 128 rows x 16 u32 words, stride 20.
// Fragments: A word = As[row][kc+t]; B word = Bs[col][kc+t] — k-pairs
// pack naturally into u32.
// =====================================================================
#define RST 20
#define PLW (128 * RST)          // words per plane tile
#define STGW (4 * PLW)           // words per stage (A0,A1,B0,B1)

// logits: L[n][m] = sum_k A[n][k]*B[m][k]; lda = ldb = CDIM; NIT = 8
template<bool SYM>
__global__ __launch_bounds__(256)
void logits_bf(const ushortT* __restrict__ A0, const ushortT* __restrict__ A1,
               const ushortT* __restrict__ B0, const ushortT* __restrict__ B1,
               float* __restrict__ L) {
    extern __shared__ unsigned sm[];
    constexpr int NIT = CDIM / 32;

    int bx = blockIdx.x, by = blockIdx.y, b = blockIdx.z;
    if (SYM && bx < by) return;
    int m0 = bx * 128, n0 = by * 128;

    const ushortT* gp[4];
    gp[0] = A0 + ((size_t)b * HW + n0) * CDIM;
    gp[1] = A1 + ((size_t)b * HW + n0) * CDIM;
    gp[2] = B0 + ((size_t)b * HW + m0) * CDIM;
    gp[3] = B1 + ((size_t)b * HW + m0) * CDIM;
    float* Lb = L + (size_t)b * HW * HW;

    unsigned sbase = smem_u32(sm);
    int tid = threadIdx.x;
    int warp = tid >> 5, lane = tid & 31;
    int g = lane >> 2, t = lane & 3;
    int wm = warp >> 2, wn = warp & 3;

    auto prefetch = [&](int it, int s) {
        int k0 = it * 32;
        unsigned sb = sbase + (unsigned)(s * STGW) * 4u;
#pragma unroll
        for (int q = 0; q < 8; q++) {
            int e = tid + q * 256;          // 0..2047
            int pl = e >> 9;                // plane 0..3
            int ep = e & 511;
            int r = ep >> 2, wc = ep & 3;   // row, 4-word chunk
            cpa16(sb + (unsigned)(pl * PLW + r * RST + wc * 4) * 4u,
                  gp[pl] + (size_t)r * CDIM + k0 + wc * 8);
        }
        asm volatile("cp.async.commit_group;\n" ::: "memory");
    };

    float acc[4][4][4] = {};

    prefetch(0, 0);
    for (int it = 0; it < NIT; it++) {
        if (it + 1 < NIT) { prefetch(it + 1, (it + 1) & 1); cp_wait<1>(); }
        else cp_wait<0>();
        __syncthreads();

        const unsigned* As0 = sm + (it & 1) * STGW;
        const unsigned* As1 = As0 + PLW;
        const unsigned* Bs0 = As0 + 2 * PLW;
        const unsigned* Bs1 = As0 + 3 * PLW;

#pragma unroll
        for (int c = 0; c < 2; c++) {       // two k16 slices
            int kc = c * 8;
            unsigned b0[4][2], b1[4][2];
#pragma unroll
            for (int j = 0; j < 4; j++) {
                int col = wn * 32 + j * 8 + g;
                b0[j][0] = Bs0[col * RST + kc + t];
                b0[j][1] = Bs0[col * RST + kc + t + 4];
                b1[j][0] = Bs1[col * RST + kc + t];
                b1[j][1] = Bs1[col * RST + kc + t + 4];
            }
#pragma unroll
            for (int i = 0; i < 4; i++) {
                int row = wm * 64 + i * 16 + g;
                unsigned a0[4], a1[4];
                a0[0] = As0[row * RST + kc + t];
                a0[1] = As0[(row + 8) * RST + kc + t];
                a0[2] = As0[row * RST + kc + t + 4];
                a0[3] = As0[(row + 8) * RST + kc + t + 4];
                a1[0] = As1[row * RST + kc + t];
                a1[1] = As1[(row + 8) * RST + kc + t];
                a1[2] = As1[row * RST + kc + t + 4];
                a1[3] = As1[(row + 8) * RST + kc + t + 4];
#pragma unroll
                for (int j = 0; j < 4; j++) {
                    mma_bf16(acc[i][j], a0, b0[j]);
                    mma_bf16(acc[i][j], a0, b1[j]);
                    mma_bf16(acc[i][j], a1, b0[j]);
                }
            }
        }
        __syncthreads();
    }

#pragma unroll
    for (int i = 0; i < 4; i++) {
        int r = n0 + wm * 64 + i * 16 + g;
#pragma unroll
        for (int j = 0; j < 4; j++) {
            int cc = m0 + wn * 32 + j * 8 + 2 * t;
            *(float2*)&Lb[(size_t)r * HW + cc] =
                make_float2(acc[i][j][0], acc[i][j][1]);
            *(float2*)&Lb[(size_t)(r + 8) * HW + cc] =
                make_float2(acc[i][j][2], acc[i][j][3]);
        }
    }
    if (SYM && bx != by) {
#pragma unroll
        for (int i = 0; i < 4; i++) {
            int rr = n0 + wm * 64 + i * 16 + g;
#pragma unroll
            for (int j = 0; j < 4; j++) {
                int cc = m0 + wn * 32 + j * 8 + 2 * t;
                Lb[(size_t)cc * HW + rr]           = acc[i][j][0];
                Lb[(size_t)(cc + 1) * HW + rr]     = acc[i][j][1];
                Lb[(size_t)cc * HW + rr + 8]       = acc[i][j][2];
                Lb[(size_t)(cc + 1) * HW + rr + 8] = acc[i][j][3];
            }
        }
    }
}

// pax1: C[n][d] = sum_k P[n][k]*axT[d][k] + U + R.  A = P planes (lda=HW),
// B = axT planes (ldb=HW). NIT = 128.
__global__ __launch_bounds__(256)
void pax_bf(const ushortT* __restrict__ P0, const ushortT* __restrict__ P1,
            const ushortT* __restrict__ X0, const ushortT* __restrict__ X1,
            const float* __restrict__ U, const float* __restrict__ Rr,
            float* __restrict__ C) {
    extern __shared__ unsigned sm[];
    constexpr int NIT = HW / 32;

    int b = blockIdx.z;
    int d0 = blockIdx.x * 128;
    int n0 = blockIdx.y * 128;

    const ushortT* gp[4];
    gp[0] = P0 + ((size_t)b * HW + n0) * HW;
    gp[1] = P1 + ((size_t)b * HW + n0) * HW;
    gp[2] = X0 + (size_t)b * CDIM * HW + (size_t)d0 * HW;
    gp[3] = X1 + (size_t)b * CDIM * HW + (size_t)d0 * HW;

    unsigned sbase = smem_u32(sm);
    int tid = threadIdx.x;
    int warp = tid >> 5, lane = tid & 31;
    int g = lane >> 2, t = lane & 3;
    int wm = warp >> 2, wn = warp & 3;

    auto prefetch = [&](int it, int s) {
        int k0 = it * 32;
        unsigned sb = sbase + (unsigned)(s * STGW) * 4u;
#pragma unroll
        for (int q = 0; q < 8; q++) {
            int e = tid + q * 256;
            int pl = e >> 9;
            int ep = e & 511;
            int r = ep >> 2, wc = ep & 3;
            cpa16(sb + (unsigned)(pl * PLW + r * RST + wc * 4) * 4u,
                  gp[pl] + (size_t)r * HW + k0 + wc * 8);
        }
        asm volatile("cp.async.commit_group;\n" ::: "memory");
    };

    float acc[4][4][4] = {};

    prefetch(0, 0);
    for (int it = 0; it < NIT; it++) {
        if (it + 1 < NIT) { prefetch(it + 1, (it + 1) & 1); cp_wait<1>(); }
        else cp_wait<0>();
        __syncthreads();

        const unsigned* As0 = sm + (it & 1) * STGW;
        const unsigned* As1 = As0 + PLW;
        const unsigned* Bs0 = As0 + 2 * PLW;
        const unsigned* Bs1 = As0 + 3 * PLW;

#pragma unroll
        for (int c = 0; c < 2; c++) {
            int kc = c * 8;
            unsigned b0[4][2], b1[4][2];
#pragma unroll
            for (int j = 0; j < 4; j++) {
                int col = wn * 32 + j * 8 + g;
                b0[j][0] = Bs0[col * RST + kc + t];
                b0[j][1] = Bs0[col * RST + kc + t + 4];
                b1[j][0] = Bs1[col * RST + kc + t];
                b1[j][1] = Bs1[col * RST + kc + t + 4];
            }
#pragma unroll
            for (int i = 0; i < 4; i++) {
                int row = wm * 64 + i * 16 + g;
                unsigned a0[4], a1[4];
                a0[0] = As0[row * RST + kc + t];
                a0[1] = As0[(row + 8) * RST + kc + t];
                a0[2] = As0[row * RST + kc + t + 4];
                a0[3] = As0[(row + 8) * RST + kc + t + 4];
                a1[0] = As1[row * RST + kc + t];
                a1[1] = As1[(row + 8) * RST + kc + t];
                a1[2] = As1[row * RST + kc + t + 4];
                a1[3] = As1[(row + 8) * RST + kc + t + 4];
#pragma unroll
                for (int j = 0; j < 4; j++) {
                    mma_bf16(acc[i][j], a0, b0[j]);
                    mma_bf16(acc[i][j], a0, b1[j]);
                    mma_bf16(acc[i][j], a1, b0[j]);
                }
            }
        }
        __syncthreads();
    }

    const float* Ub = U + (size_t)b * HW * CDIM;
    const float* Rb = Rr + (size_t)b * HW * CDIM;
    float* Cb = C + (size_t)b * HW * CDIM;
#pragma unroll
    for (int i = 0; i < 4; i++) {
        int r = n0 + wm * 64 + i * 16 + g;
#pragma unroll
        for (int j = 0; j < 4; j++) {
            int cc = d0 + wn * 32 + j * 8 + 2 * t;
            size_t o0 = (size_t)r * CDIM + cc;
            size_t o1 = (size_t)(r + 8) * CDIM + cc;
            float2 u0 = *(const float2*)&Ub[o0], u1 = *(const float2*)&Ub[o1];
            float2 q0 = *(const float2*)&Rb[o0], q1 = *(const float2*)&Rb[o1];
            *(float2*)&Cb[o0] = make_float2(acc[i][j][0] + u0.x + q0.x,
                                            acc[i][j][1] + u0.y + q0.y);
            *(float2*)&Cb[o1] = make_float2(acc[i][j][2] + u1.x + q1.x,
                                            acc[i][j][3] + u1.y + q1.y);
        }
    }
}

// =====================================================================
// pax_cp (pax2, proven tf32 single-pass): C = P@axh + U + R
// =====================================================================
__global__ __launch_bounds__(256)
void pax_cp(const float* __restrict__ Pf, const unsigned* __restrict__ Bh,
            const float* __restrict__ U, const float* __restrict__ Rr,
            float* __restrict__ C) {
    extern __shared__ unsigned sm[];
    constexpr int AW = 128 * 36;
    constexpr int BW = 32 * 136;
    constexpr int STG = AW + BW;
    constexpr int NST = 3;
    constexpr int NIT = HW / 32;

    int b = blockIdx.z;
    int d0 = blockIdx.x * 128;
    int n0 = blockIdx.y * 128;

    const float* Pb = Pf + (size_t)b * HW * HW;
    const unsigned* Bhb = Bh + (size_t)b * HW * CDIM;

    unsigned sbase = smem_u32(sm);
    int tid = threadIdx.x;
    int warp = tid >> 5, lane = tid & 31;
    int g = lane >> 2, t = lane & 3;
    int wm = warp >> 2, wn = warp & 3;

    auto prefetch = [&](int it, int s) {
        int k0 = it * 32;
        unsigned sb = sbase + (unsigned)(s * STG) * 4u;
#pragma unroll
        for (int q = 0; q < 4; q++) {
            int f = tid + q * 256;
            int n = f >> 3, c4 = (f & 7) * 4;
            cpa16(sb + (unsigned)(n * 36 + c4) * 4u,
                  Pb + (size_t)(n0 + n) * HW + k0 + c4);
        }
#pragma unroll
        for (int q = 0; q < 4; q++) {
            int f = tid + q * 256;
            int k = f >> 5, d4 = (f & 31) * 4;
            cpa16(sb + (unsigned)(AW + k * 136 + d4) * 4u,
                  Bhb + (size_t)(k0 + k) * CDIM + d0 + d4);
        }
        asm volatile("cp.async.commit_group;\n" ::: "memory");
    };

    float acc[4][4][4] = {};

#pragma unroll
    for (int p = 0; p < NST - 1; p++) prefetch(p, p);

    for (int it = 0; it < NIT; it++) {
        int nx = it + NST - 1;
        if (nx < NIT) { prefetch(nx, nx % NST); cp_wait<NST - 1>(); }
        else cp_wait<0>();
        __syncthreads();

        const float* As = (const float*)(sm + (it % NST) * STG);
        const unsigned* Bs = (const unsigned*)(As + AW);

#pragma unroll
        for (int c = 0; c < 4; c++) {
            int kc = c * 8;
            unsigned bb[4][2];
#pragma unroll
            for (int j = 0; j < 4; j++) {
                int col = wn * 32 + j * 8 + g;
                bb[j][0] = Bs[(kc + t) * 136 + col];
                bb[j][1] = Bs[(kc + t + 4) * 136 + col];
            }
#pragma unroll
            for (int i = 0; i < 4; i++) {
                int row = wm * 64 + i * 16 + g;
                unsigned aa[4];
                aa[0] = f2tf(As[row * 36 + kc + t]);
                aa[1] = f2tf(As[(row + 8) * 36 + kc + t]);
                aa[2] = f2tf(As[row * 36 + kc + t + 4]);
                aa[3] = f2tf(As[(row + 8) * 36 + kc + t + 4]);
#pragma unroll
                for (int j = 0; j < 4; j++) mma_tf32(acc[i][j], aa, bb[j]);
            }
        }
        __syncthreads();
    }

    const float* Ub = U + (size_t)b * HW * CDIM;
    const float* Rb = Rr + (size_t)b * HW * CDIM;
    float* Cb = C + (size_t)b * HW * CDIM;
#pragma unroll
    for (int i = 0; i < 4; i++) {
        int r = n0 + wm * 64 + i * 16 + g;
#pragma unroll
        for (int j = 0; j < 4; j++) {
            int cc = d0 + wn * 32 + j * 8 + 2 * t;
            size_t o0 = (size_t)r * CDIM + cc;
            size_t o1 = (size_t)(r + 8) * CDIM + cc;
            float2 u0 = *(const float2*)&Ub[o0], u1 = *(const float2*)&Ub[o1];
            float2 q0 = *(const float2*)&Rb[o0], q1 = *(const float2*)&Rb[o1];
            *(float2*)&Cb[o0] = make_float2(acc[i][j][0] + u0.x + q0.x,
                                            acc[i][j][1] + u0.y + q0.y);
            *(float2*)&Cb[o1] = make_float2(acc[i][j][2] + u1.x + q1.x,
                                            acc[i][j][3] + u1.y + q1.y);
        }
    }
}

// =====================================================================
// gemm_rr (linears): C[m][n] = relu(A@W + bias)   (proven)
// =====================================================================
template<bool THREE>
__global__ __launch_bounds__(256, 2)
void gemm_rr(const float* __restrict__ A, const float* __restrict__ B,
             const float* __restrict__ bias, float* __restrict__ C, int lda) {
    extern __shared__ unsigned sm[];
    unsigned* As  = sm;
    unsigned* Asr = As + 128 * 36;
    unsigned* Bs  = As + (THREE ? 2 : 1) * 128 * 36;
    unsigned* Bsr = Bs + 32 * 136;

    int n0 = blockIdx.x * 128;
    int m0 = blockIdx.y * 128;
    int tid = threadIdx.x;
    int warp = tid >> 5, lane = tid & 31;
    int g = lane >> 2, t = lane & 3;
    int wm = warp >> 2, wn = warp & 3;
    int la_n = tid >> 3, la_k = (tid & 7) * 4;
    int lb_k = tid >> 5, lb_n = (tid & 31) * 4;

    float acc[4][4][4] = {};

    for (int k0 = 0; k0 < CDIM; k0 += 32) {
#pragma unroll
        for (int u = 0; u < 4; u++) {
            int n = la_n + u * 32;
            float4 v = *(const float4*)&A[(size_t)(m0 + n) * lda + k0 + la_k];
            unsigned h0 = f2tf(v.x), h1 = f2tf(v.y), h2 = f2tf(v.z), h3 = f2tf(v.w);
            unsigned* p = &As[n * 36 + la_k];
            p[0] = h0; p[1] = h1; p[2] = h2; p[3] = h3;
            if (THREE) {
                unsigned* q = &Asr[n * 36 + la_k];
                q[0] = f2tf(v.x - __uint_as_float(h0));
                q[1] = f2tf(v.y - __uint_as_float(h1));
                q[2] = f2tf(v.z - __uint_as_float(h2));
                q[3] = f2tf(v.w - __uint_as_float(h3));
            }
        }
#pragma unroll
        for (int u = 0; u < 4; u++) {
            int k = lb_k + u * 8;
            float4 v = *(const float4*)&B[(size_t)(k0 + k) * CDIM + n0 + lb_n];
            unsigned h0 = f2tf(v.x), h1 = f2tf(v.y), h2 = f2tf(v.z), h3 = f2tf(v.w);
            unsigned* p = &Bs[k * 136 + lb_n];
            p[0] = h0; p[1] = h1; p[2] = h2; p[3] = h3;
            if (THREE) {
                unsigned* q = &Bsr[k * 136 + lb_n];
                q[0] = f2tf(v.x - __uint_as_float(h0));
                q[1] = f2tf(v.y - __uint_as_float(h1));
                q[2] = f2tf(v.z - __uint_as_float(h2));
                q[3] = f2tf(v.w - __uint_as_float(h3));
            }
        }
        __syncthreads();

#pragma unroll
        for (int c = 0; c < 4; c++) {
            int kc = c * 8;
            unsigned bb[4][2], br[4][2];
#pragma unroll
            for (int j = 0; j < 4; j++) {
                int col = wn * 32 + j * 8 + g;
                bb[j][0] = Bs[(kc + t) * 136 + col];
                bb[j][1] = Bs[(kc + t + 4) * 136 + col];
                if (THREE) {
                    br[j][0] = Bsr[(kc + t) * 136 + col];
                    br[j][1] = Bsr[(kc + t + 4) * 136 + col];
                }
            }
#pragma unroll
            for (int i = 0; i < 4; i++) {
                int row = wm * 64 + i * 16 + g;
                unsigned aa[4], ar[4];
                aa[0] = As[row * 36 + kc + t];
                aa[1] = As[(row + 8) * 36 + kc + t];
                aa[2] = As[row * 36 + kc + t + 4];
                aa[3] = As[(row + 8) * 36 + kc + t + 4];
                if (THREE) {
                    ar[0] = Asr[row * 36 + kc + t];
                    ar[1] = Asr[(row + 8) * 36 + kc + t];
                    ar[2] = Asr[row * 36 + kc + t + 4];
                    ar[3] = Asr[(row + 8) * 36 + kc + t + 4];
                }
#pragma unroll
                for (int j = 0; j < 4; j++) {
                    mma_tf32(acc[i][j], aa, bb[j]);
                    if (THREE) {
                        mma_tf32(acc[i][j], aa, br[j]);
                        mma_tf32(acc[i][j], ar, bb[j]);
                    }
                }
            }
        }
        __syncthreads();
    }

#pragma unroll
    for (int i = 0; i < 4; i++) {
        int r = m0 + wm * 64 + i * 16 + g;
#pragma unroll
        for (int j = 0; j < 4; j++) {
            int cc = n0 + wn * 32 + j * 8 + 2 * t;
            size_t o0 = (size_t)r * CDIM + cc;
            size_t o1 = (size_t)(r + 8) * CDIM + cc;
            float2 bv = *(const float2*)&bias[cc];
            *(float2*)&C[o0] = make_float2(fmaxf(acc[i][j][0] + bv.x, 0.f),
                                           fmaxf(acc[i][j][1] + bv.y, 0.f));
            *(float2*)&C[o1] = make_float2(fmaxf(acc[i][j][2] + bv.x, 0.f),
                                           fmaxf(acc[i][j][3] + bv.y, 0.f));
        }
    }
}

// ---------------- row softmax: float in; WBF -> bf16 planes, else float ----------------
template<bool WBF>
__global__ void softmax_kernel(float* __restrict__ P, ushortT* __restrict__ Q0,
                               ushortT* __restrict__ Q1) {
    size_t ro = ((size_t)blockIdx.y * HW + blockIdx.x) * HW;
    float* row = P + ro;
    int t = threadIdx.x;
    __shared__ float red[16];
    float v[8];
    float mx = -1e30f;
#pragma unroll
    for (int i = 0; i < 8; i++) { v[i] = row[t + i * 512]; mx = fmaxf(mx, v[i]); }
    for (int o = 16; o; o >>= 1) mx = fmaxf(mx, __shfl_xor_sync(0xffffffffu, mx, o));
    int warp = t >> 5, lane = t & 31;
    if (lane == 0) red[warp] = mx;
    __syncthreads();
    if (warp == 0) {
        float m2 = red[lane & 15];
        for (int o = 8; o; o >>= 1) m2 = fmaxf(m2, __shfl_xor_sync(0xffffffffu, m2, o));
        if (lane == 0) red[0] = m2;
    }
    __syncthreads();
    mx = red[0];
    __syncthreads();
    float s = 0.f;
#pragma unroll
    for (int i = 0; i < 8; i++) { v[i] = __expf(v[i] - mx); s += v[i]; }
    for (int o = 16; o; o >>= 1) s += __shfl_xor_sync(0xffffffffu, s, o);
    if (lane == 0) red[warp] = s;
    __syncthreads();
    if (warp == 0) {
        float s2 = red[lane & 15];
        for (int o = 8; o; o >>= 1) s2 += __shfl_xor_sync(0xffffffffu, s2, o);
        if (lane == 0) red[0] = s2;
    }
    __syncthreads();
    float inv = 1.f / red[0];
#pragma unroll
    for (int i = 0; i < 8; i++) {
        float p = v[i] * inv;
        if (WBF) {
            ushortT h, l;
            bsplit(p, h, l);
            Q0[ro + t + i * 512] = h;
            Q1[ro + t + i * 512] = l;
        } else {
            row[t + i * 512] = p;
        }
    }
}

// ---------------- column partial sums ----------------
template<bool BF>
__global__ void colsum_kernel(const float* __restrict__ P,
                              const ushortT* __restrict__ Q0,
                              const ushortT* __restrict__ Q1,
                              float* __restrict__ part) {
    int b = blockIdx.z;
    int m = blockIdx.x * 256 + threadIdx.x;
    int r0 = blockIdx.y * 256;
    float s = 0.f;
    if (BF) {
        const ushortT* Q0b = Q0 + (size_t)b * HW * HW;
        const ushortT* Q1b = Q1 + (size_t)b * HW * HW;
#pragma unroll 8
        for (int r = 0; r < 256; r++) {
            size_t o = (size_t)(r0 + r) * HW + m;
            s += __bfloat162float(__ushort_as_bfloat16(Q0b[o]))
               + __bfloat162float(__ushort_as_bfloat16(Q1b[o]));
        }
    } else {
        const float* Pb = P + (size_t)b * HW * HW;
#pragma unroll 8
        for (int r = 0; r < 256; r++) s += Pb[(size_t)(r0 + r) * HW + m];
    }
    part[((size_t)b * 16 + blockIdx.y) * HW + m] = s;
}

__global__ void colinv_kernel(const float* __restrict__ part, float* __restrict__ colinv) {
    int i = blockIdx.x * 256 + threadIdx.x;
    int b = i >> 12, m = i & (HW - 1);
    float s = 0.f;
#pragma unroll
    for (int c2 = 0; c2 < 16; c2++) s += part[((size_t)b * 16 + c2) * HW + m];
    colinv[i] = 1.f / fmaxf(s, 1e-12f);
}

// ---------------- launch ----------------
extern "C" void kernel_launch(void* const* d_in, const int* in_sizes, int n_in,
                              void* d_out, int out_size) {
    (void)in_sizes; (void)n_in; (void)out_size;
    const float* skt = (const float*)d_in[0];
    const float* ref = (const float*)d_in[1];
    const float* Wa3 = (const float*)d_in[2];
    const float* ba3 = (const float*)d_in[3];
    const float* Wu3 = (const float*)d_in[4];
    const float* bu3 = (const float*)d_in[5];
    const float* Wa4 = (const float*)d_in[6];
    const float* ba4 = (const float*)d_in[7];
    const float* Wu4 = (const float*)d_in[8];
    const float* bu4 = (const float*)d_in[9];
    float* out = (float*)d_out;

    float *P, *ax, *ux, *gen, *sktnc, *refnc, *colpart, *colinv;
    unsigned *hi0, *lo0, *hi1, *lo1;
    ushortT *Pb0, *Pb1;
    cudaGetSymbolAddress((void**)&P, g_P);
    cudaGetSymbolAddress((void**)&Pb0, g_Pb0);
    cudaGetSymbolAddress((void**)&Pb1, g_Pb1);
    cudaGetSymbolAddress((void**)&ax, g_ax);
    cudaGetSymbolAddress((void**)&ux, g_ux);
    cudaGetSymbolAddress((void**)&gen, g_gen);
    cudaGetSymbolAddress((void**)&sktnc, g_sktnc);
    cudaGetSymbolAddress((void**)&refnc, g_refnc);
    cudaGetSymbolAddress((void**)&colpart, g_colpart);
    cudaGetSymbolAddress((void**)&colinv, g_colinv);
    cudaGetSymbolAddress((void**)&hi0, g_hi0);
    cudaGetSymbolAddress((void**)&lo0, g_lo0);
    cudaGetSymbolAddress((void**)&hi1, g_hi1);
    cudaGetSymbolAddress((void**)&lo1, g_lo1);

    // bf16 plane carving (each unsigned buffer holds 2 ushort planes)
    ushortT* SA0 = (ushortT*)hi0;  ushortT* SA1 = SA0 + NPL;   // sktnc / gen planes
    ushortT* SB0 = (ushortT*)lo0;  ushortT* SB1 = SB0 + NPL;   // refnc planes
    ushortT* XT0 = (ushortT*)hi1;  ushortT* XT1 = XT0 + NPL;   // axT planes
    unsigned* AXH = lo1;                                        // tf32 hi (pax2)

    const int SM3   = (2 * 128 * 36 + 2 * 32 * 136) * 4;   // 71680
    const int SM1   = (128 * 36 + 32 * 136) * 4;           // 35840
    const int SMBF  = 2 * STGW * 4;                        // 81920
    const int SMP1  = 3 * (128 * 36 + 32 * 136) * 4;       // 107520
    cudaFuncSetAttribute(gemm_rr<true>,    cudaFuncAttributeMaxDynamicSharedMemorySize, SM3);
    cudaFuncSetAttribute(gemm_rr<false>,   cudaFuncAttributeMaxDynamicSharedMemorySize, SM1);
    cudaFuncSetAttribute(logits_bf<false>, cudaFuncAttributeMaxDynamicSharedMemorySize, SMBF);
    cudaFuncSetAttribute(logits_bf<true>,  cudaFuncAttributeMaxDynamicSharedMemorySize, SMBF);
    cudaFuncSetAttribute(pax_bf,           cudaFuncAttributeMaxDynamicSharedMemorySize, SMBF);
    cudaFuncSetAttribute(pax_cp,           cudaFuncAttributeMaxDynamicSharedMemorySize, SMP1);

    dim3 tb(32, 8);
    dim3 gLin(CDIM / 128, (BATCH * HW) / 128, 1);
    dim3 gLog(HW / 128, HW / 128, BATCH);
    dim3 gPax(CDIM / 128, HW / 128, BATCH);
    const int nSplit = (BATCH * HW * CDIM) / (4 * 256);

    // ===== layer 1 =====
    transpose_kernel<<<dim3(HW / 32, CDIM / 32, BATCH), tb>>>(skt, sktnc, CDIM, HW);
    transpose_kernel<<<dim3(HW / 32, CDIM / 32, BATCH), tb>>>(ref, refnc, CDIM, HW);
    bsplit2_kernel<<<nSplit, 256>>>(sktnc, SA0, SA1);
    bsplit2_kernel<<<nSplit, 256>>>(refnc, SB0, SB1);
    gemm_rr<true><<<gLin, 256, SM3>>>(refnc, Wa3, ba3, ax, CDIM);
    gemm_rr<true><<<gLin, 256, SM3>>>(sktnc, Wu3, bu3, ux, CDIM);
    logits_bf<false><<<gLog, 256, SMBF>>>(SA0, SA1, SB0, SB1, P);
    softmax_kernel<true><<<dim3(HW, BATCH), 512>>>(P, Pb0, Pb1);
    colsum_kernel<true><<<dim3(HW / 256, 16, BATCH), 256>>>(nullptr, Pb0, Pb1, colpart);
    colinv_kernel<<<(BATCH * HW) / 256, 256>>>(colpart, colinv);
    axt_split_kernel<<<dim3(HW / 32, CDIM / 32, BATCH), tb>>>(ax, colinv, XT0, XT1);
    pax_bf<<<gPax, 256, SMBF>>>(Pb0, Pb1, XT0, XT1, ux, sktnc, gen);

    // ===== layer 2 (logits symmetric: gen.genT) =====
    bsplit2_kernel<<<nSplit, 256>>>(gen, SA0, SA1);
    gemm_rr<false><<<gLin, 256, SM1>>>(gen, Wa4, ba4, ax, CDIM);
    gemm_rr<false><<<gLin, 256, SM1>>>(gen, Wu4, bu4, ux, CDIM);
    logits_bf<true><<<gLog, 256, SMBF>>>(SA0, SA1, SA0, SA1, P);
    softmax_kernel<false><<<dim3(HW, BATCH), 512>>>(P, nullptr, nullptr);
    colsum_kernel<false><<<dim3(HW / 256, 16, BATCH), 256>>>(P, nullptr, nullptr, colpart);
    colinv_kernel<<<(BATCH * HW) / 256, 256>>>(colpart, colinv);
    scale_split_kernel<<<nSplit, 256>>>(ax, colinv, AXH);
    pax_cp<<<gPax, 256, SMP1>>>(P, AXH, ux, gen, out);
}

// round 14
// speedup vs baseline: 1.4969x; 1.0346x over previous
#include <cuda_runtime.h>
#include <cuda_bf16.h>
#include <math.h>

#define BATCH 4
#define CDIM  256
#define HW    4096
#define NPL   ((size_t)BATCH * HW * CDIM)

typedef unsigned short ushortT;

// ---------------- scratch ----------------
static __device__ float g_P[(size_t)BATCH * HW * HW];
static __device__ ushortT g_Pb0[(size_t)BATCH * HW * HW];
static __device__ ushortT g_Pb1[(size_t)BATCH * HW * HW];
static __device__ float g_ax[(size_t)BATCH * HW * CDIM];
static __device__ float g_ux[(size_t)BATCH * HW * CDIM];
static __device__ float g_gen[(size_t)BATCH * HW * CDIM];
static __device__ float g_sktnc[(size_t)BATCH * HW * CDIM];
static __device__ float g_refnc[(size_t)BATCH * HW * CDIM];
static __device__ float g_colpart[(size_t)BATCH * 16 * HW];
static __device__ float g_colinv[(size_t)BATCH * HW];
static __device__ unsigned g_hi0[(size_t)BATCH * HW * CDIM];   // SA planes
static __device__ unsigned g_lo0[(size_t)BATCH * HW * CDIM];   // SB planes
static __device__ unsigned g_hi1[(size_t)BATCH * HW * CDIM];   // XT planes
static __device__ unsigned g_lo1[(size_t)BATCH * HW * CDIM];   // tf32 ax hi (pax2)
static __device__ ushortT g_wt[4][256 * 256];                  // WaT0,WaT1,WuT0,WuT1

// ---------------- helpers ----------------
__device__ __forceinline__ unsigned f2tf(float x) {
    unsigned r;
    asm("cvt.rna.tf32.f32 %0, %1;" : "=r"(r) : "f"(x));
    return r;
}

__device__ __forceinline__ void mma_tf32(float* d, const unsigned* a, const unsigned* b) {
    asm("mma.sync.aligned.m16n8k8.row.col.f32.tf32.tf32.f32 "
        "{%0,%1,%2,%3},{%4,%5,%6,%7},{%8,%9},{%0,%1,%2,%3};"
        : "+f"(d[0]), "+f"(d[1]), "+f"(d[2]), "+f"(d[3])
        : "r"(a[0]), "r"(a[1]), "r"(a[2]), "r"(a[3]), "r"(b[0]), "r"(b[1]));
}

__device__ __forceinline__ void mma_bf16(float* d, const unsigned* a, const unsigned* b) {
    asm("mma.sync.aligned.m16n8k16.row.col.f32.bf16.bf16.f32 "
        "{%0,%1,%2,%3},{%4,%5,%6,%7},{%8,%9},{%0,%1,%2,%3};"
        : "+f"(d[0]), "+f"(d[1]), "+f"(d[2]), "+f"(d[3])
        : "r"(a[0]), "r"(a[1]), "r"(a[2]), "r"(a[3]), "r"(b[0]), "r"(b[1]));
}

__device__ __forceinline__ void cpa16(unsigned saddr, const void* g) {
    asm volatile("cp.async.cg.shared.global [%0], [%1], 16;\n" :: "r"(saddr), "l"(g));
}

template<int N>
__device__ __forceinline__ void cp_wait() {
    asm volatile("cp.async.wait_group %0;\n" :: "n"(N) : "memory");
}

__device__ __forceinline__ unsigned smem_u32(const void* p) {
    unsigned a;
    asm("{ .reg .u64 t; cvta.to.shared.u64 t, %1; cvt.u32.u64 %0, t; }" : "=r"(a) : "l"(p));
    return a;
}

__device__ __forceinline__ void bsplit(float x, ushortT& h, ushortT& l) {
    __nv_bfloat16 b0 = __float2bfloat16(x);
    __nv_bfloat16 b1 = __float2bfloat16(x - __bfloat162float(b0));
    h = __bfloat16_as_ushort(b0);
    l = __bfloat16_as_ushort(b1);
}

// ---------------- bf16 2-plane split ----------------
__global__ void bsplit2_kernel(const float* __restrict__ in,
                               ushortT* __restrict__ p0, ushortT* __restrict__ p1) {
    size_t i = (size_t)blockIdx.x * 256 + threadIdx.x;
    float4 v = ((const float4*)in)[i];
    float x[4] = {v.x, v.y, v.z, v.w};
    ushortT h[4], l[4];
#pragma unroll
    for (int e = 0; e < 4; e++) bsplit(x[e], h[e], l[e]);
    ((uint2*)p0)[i] = make_uint2(h[0] | ((unsigned)h[1] << 16), h[2] | ((unsigned)h[3] << 16));
    ((uint2*)p1)[i] = make_uint2(l[0] | ((unsigned)l[1] << 16), l[2] | ((unsigned)l[3] << 16));
}

// ---------------- tf32 scale+split (pax2) ----------------
__global__ void scale_split_kernel(const float* __restrict__ ax,
                                   const float* __restrict__ colinv,
                                   unsigned* __restrict__ hi) {
    size_t i = (size_t)blockIdx.x * 256 + threadIdx.x;
    int row = (int)(i >> 6);
    float sc = colinv[row];
    float4 v = ((const float4*)ax)[i];
    uint4 h;
    h.x = f2tf(v.x * sc); h.y = f2tf(v.y * sc);
    h.z = f2tf(v.z * sc); h.w = f2tf(v.w * sc);
    ((uint4*)hi)[i] = h;
}

// ---------------- ax scale + transpose + bf16 split -> [d][k] planes ----------------
__global__ void axt_split_kernel(const float* __restrict__ ax, const float* __restrict__ colinv,
                                 ushortT* __restrict__ p0, ushortT* __restrict__ p1) {
    __shared__ float tile[32][33];
    int b = blockIdx.z;
    int k0 = blockIdx.x * 32, d0 = blockIdx.y * 32;
    int tx = threadIdx.x, ty = threadIdx.y;
    const float* axb = ax + (size_t)b * HW * CDIM;
#pragma unroll
    for (int i = 0; i < 32; i += 8) {
        float sc = colinv[(b << 12) + k0 + ty + i];
        tile[ty + i][tx] = axb[(size_t)(k0 + ty + i) * CDIM + d0 + tx] * sc;
    }
    __syncthreads();
#pragma unroll
    for (int i = 0; i < 32; i += 8) {
        float v = tile[tx][ty + i];
        ushortT h, l;
        bsplit(v, h, l);
        size_t o = (size_t)b * CDIM * HW + (size_t)(d0 + ty + i) * HW + k0 + tx;
        p0[o] = h;
        p1[o] = l;
    }
}

// ---------------- W transpose + split: W[k][n] -> WT planes [n][k] ----------------
__global__ void wt_split_kernel(const float* __restrict__ W,
                                ushortT* __restrict__ p0, ushortT* __restrict__ p1) {
    __shared__ float tile[32][33];
    int k0 = blockIdx.x * 32, n0 = blockIdx.y * 32;
    int tx = threadIdx.x, ty = threadIdx.y;
#pragma unroll
    for (int i = 0; i < 32; i += 8)
        tile[ty + i][tx] = W[(size_t)(k0 + ty + i) * CDIM + n0 + tx];
    __syncthreads();
#pragma unroll
    for (int i = 0; i < 32; i += 8) {
        float v = tile[tx][ty + i];
        ushortT h, l;
        bsplit(v, h, l);
        size_t o = (size_t)(n0 + ty + i) * CDIM + k0 + tx;
        p0[o] = h;
        p1[o] = l;
    }
}

// ---------------- transpose ----------------
__global__ void transpose_kernel(const float* __restrict__ in, float* __restrict__ out,
                                 int R, int S) {
    __shared__ float tile[32][33];
    int b = blockIdx.z;
    int s0 = blockIdx.x * 32, r0 = blockIdx.y * 32;
    const float* inb = in + (size_t)b * R * S;
    float* outb = out + (size_t)b * R * S;
    int tx = threadIdx.x, ty = threadIdx.y;
#pragma unroll
    for (int i = 0; i < 32; i += 8)
        tile[ty + i][tx] = inb[(size_t)(r0 + ty + i) * S + s0 + tx];
    __syncthreads();
#pragma unroll
    for (int i = 0; i < 32; i += 8)
        outb[(size_t)(s0 + ty + i) * R + r0 + tx] = tile[tx][ty + i];
}

// =====================================================================
// bf16 3-product core, 4 warps (128 thr), warp tile 64x64, CTA 128x128.
// =====================================================================
#define RST 20
#define PLW (128 * RST)
#define STGW (4 * PLW)           // words per stage

#define BF_MAINLOOP(LD)                                                          \
    float acc[4][8][4] = {};                                                     \
    prefetch(0, 0);                                                              \
    for (int it = 0; it < NIT; it++) {                                           \
        if (it + 1 < NIT) { prefetch(it + 1, (it + 1) & 1); cp_wait<1>(); }      \
        else cp_wait<0>();                                                       \
        __syncthreads();                                                         \
        const unsigned* As0 = sm + (it & 1) * STGW;                              \
        const unsigned* As1 = As0 + PLW;                                         \
        const unsigned* Bs0 = As0 + 2 * PLW;                                     \
        const unsigned* Bs1 = As0 + 3 * PLW;                                     \
        _Pragma("unroll")                                                        \
        for (int c = 0; c < 2; c++) {                                            \
            int kc = c * 8;                                                      \
            unsigned b0[8][2], b1[8][2];                                         \
            _Pragma("unroll")                                                    \
            for (int j = 0; j < 8; j++) {                                        \
                int col = wn * 64 + j * 8 + g;                                   \
                b0[j][0] = Bs0[col * RST + kc + t];                              \
                b0[j][1] = Bs0[col * RST + kc + t + 4];                          \
                b1[j][0] = Bs1[col * RST + kc + t];                              \
                b1[j][1] = Bs1[col * RST + kc + t + 4];                          \
            }                                                                    \
            _Pragma("unroll")                                                    \
            for (int i = 0; i < 4; i++) {                                        \
                int row = wm * 64 + i * 16 + g;                                  \
                unsigned a0[4], a1[4];                                           \
                a0[0] = As0[row * RST + kc + t];                                 \
                a0[1] = As0[(row + 8) * RST + kc + t];                           \
                a0[2] = As0[row * RST + kc + t + 4];                             \
                a0[3] = As0[(row + 8) * RST + kc + t + 4];                       \
                a1[0] = As1[row * RST + kc + t];                                 \
                a1[1] = As1[(row + 8) * RST + kc + t];                           \
                a1[2] = As1[row * RST + kc + t + 4];                             \
                a1[3] = As1[(row + 8) * RST + kc + t + 4];                       \
                _Pragma("unroll")                                                \
                for (int j = 0; j < 8; j++) {                                    \
                    mma_bf16(acc[i][j], a0, b0[j]);                              \
                    mma_bf16(acc[i][j], a0, b1[j]);                              \
                    mma_bf16(acc[i][j], a1, b0[j]);                              \
                }                                                                \
            }                                                                    \
        }                                                                        \
        __syncthreads();                                                         \
    }

#define BF_PREFETCH(LD)                                                          \
    auto prefetch = [&](int it, int s) {                                         \
        int k0 = it * 32;                                                        \
        unsigned sb = sbase + (unsigned)(s * STGW) * 4u;                         \
        _Pragma("unroll")                                                        \
        for (int q = 0; q < 16; q++) {                                           \
            int e = tid + q * 128;                                               \
            int pl = e >> 9;                                                     \
            int ep = e & 511;                                                    \
            int r = ep >> 2, wc = ep & 3;                                        \
            cpa16(sb + (unsigned)(pl * PLW + r * RST + wc * 4) * 4u,             \
                  gp[pl] + (size_t)r * (LD) + k0 + wc * 8);                      \
        }                                                                        \
        asm volatile("cp.async.commit_group;\n" ::: "memory");                   \
    };

// logits: L[n][m] = sum_k A[n][k]*B[m][k]; NIT = 8
template<bool SYM>
__global__ __launch_bounds__(128)
void logits_bf(const ushortT* __restrict__ A0, const ushortT* __restrict__ A1,
               const ushortT* __restrict__ B0, const ushortT* __restrict__ B1,
               float* __restrict__ L) {
    extern __shared__ unsigned sm[];
    constexpr int NIT = CDIM / 32;

    int bx = blockIdx.x, by = blockIdx.y, b = blockIdx.z;
    if (SYM && bx < by) return;
    int m0 = bx * 128, n0 = by * 128;

    const ushortT* gp[4];
    gp[0] = A0 + ((size_t)b * HW + n0) * CDIM;
    gp[1] = A1 + ((size_t)b * HW + n0) * CDIM;
    gp[2] = B0 + ((size_t)b * HW + m0) * CDIM;
    gp[3] = B1 + ((size_t)b * HW + m0) * CDIM;
    float* Lb = L + (size_t)b * HW * HW;

    unsigned sbase = smem_u32(sm);
    int tid = threadIdx.x;
    int w = tid >> 5, lane = tid & 31;
    int g = lane >> 2, t = lane & 3;
    int wm = w >> 1, wn = w & 1;

    BF_PREFETCH(CDIM)
    BF_MAINLOOP(CDIM)

#pragma unroll
    for (int i = 0; i < 4; i++) {
        int r = n0 + wm * 64 + i * 16 + g;
#pragma unroll
        for (int j = 0; j < 8; j++) {
            int cc = m0 + wn * 64 + j * 8 + 2 * t;
            *(float2*)&Lb[(size_t)r * HW + cc] =
                make_float2(acc[i][j][0], acc[i][j][1]);
            *(float2*)&Lb[(size_t)(r + 8) * HW + cc] =
                make_float2(acc[i][j][2], acc[i][j][3]);
        }
    }
    if (SYM && bx != by) {
#pragma unroll
        for (int i = 0; i < 4; i++) {
            int rr = n0 + wm * 64 + i * 16 + g;
#pragma unroll
            for (int j = 0; j < 8; j++) {
                int cc = m0 + wn * 64 + j * 8 + 2 * t;
                Lb[(size_t)cc * HW + rr]           = acc[i][j][0];
                Lb[(size_t)(cc + 1) * HW + rr]     = acc[i][j][1];
                Lb[(size_t)cc * HW + rr + 8]       = acc[i][j][2];
                Lb[(size_t)(cc + 1) * HW + rr + 8] = acc[i][j][3];
            }
        }
    }
}

// pax1: C[n][d] = sum_k P[n][k]*axT[d][k] + U + R; NIT = 128
__global__ __launch_bounds__(128)
void pax_bf(const ushortT* __restrict__ P0, const ushortT* __restrict__ P1,
            const ushortT* __restrict__ X0, const ushortT* __restrict__ X1,
            const float* __restrict__ U, const float* __restrict__ Rr,
            float* __restrict__ C) {
    extern __shared__ unsigned sm[];
    constexpr int NIT = HW / 32;

    int b = blockIdx.z;
    int d0 = blockIdx.x * 128;
    int n0 = blockIdx.y * 128;

    const ushortT* gp[4];
    gp[0] = P0 + ((size_t)b * HW + n0) * HW;
    gp[1] = P1 + ((size_t)b * HW + n0) * HW;
    gp[2] = X0 + (size_t)b * CDIM * HW + (size_t)d0 * HW;
    gp[3] = X1 + (size_t)b * CDIM * HW + (size_t)d0 * HW;

    unsigned sbase = smem_u32(sm);
    int tid = threadIdx.x;
    int w = tid >> 5, lane = tid & 31;
    int g = lane >> 2, t = lane & 3;
    int wm = w >> 1, wn = w & 1;

    BF_PREFETCH(HW)
    BF_MAINLOOP(HW)

    const float* Ub = U + (size_t)b * HW * CDIM;
    const float* Rb = Rr + (size_t)b * HW * CDIM;
    float* Cb = C + (size_t)b * HW * CDIM;
#pragma unroll
    for (int i = 0; i < 4; i++) {
        int r = n0 + wm * 64 + i * 16 + g;
#pragma unroll
        for (int j = 0; j < 8; j++) {
            int cc = d0 + wn * 64 + j * 8 + 2 * t;
            size_t o0 = (size_t)r * CDIM + cc;
            size_t o1 = (size_t)(r + 8) * CDIM + cc;
            float2 u0 = *(const float2*)&Ub[o0], u1 = *(const float2*)&Ub[o1];
            float2 q0 = *(const float2*)&Rb[o0], q1 = *(const float2*)&Rb[o1];
            *(float2*)&Cb[o0] = make_float2(acc[i][j][0] + u0.x + q0.x,
                                            acc[i][j][1] + u0.y + q0.y);
            *(float2*)&Cb[o1] = make_float2(acc[i][j][2] + u1.x + q1.x,
                                            acc[i][j][3] + u1.y + q1.y);
        }
    }
}

// linear (layer 1): C[m][n] = relu(A@W + bias); A planes [m][k], WT planes [n][k]
__global__ __launch_bounds__(128)
void linear_bf(const ushortT* __restrict__ A0, const ushortT* __restrict__ A1,
               const ushortT* __restrict__ W0, const ushortT* __restrict__ W1,
               const float* __restrict__ bias, float* __restrict__ C) {
    extern __shared__ unsigned sm[];
    constexpr int NIT = CDIM / 32;

    int n0 = blockIdx.x * 128;
    int m0 = blockIdx.y * 128;

    const ushortT* gp[4];
    gp[0] = A0 + (size_t)m0 * CDIM;
    gp[1] = A1 + (size_t)m0 * CDIM;
    gp[2] = W0 + (size_t)n0 * CDIM;
    gp[3] = W1 + (size_t)n0 * CDIM;

    unsigned sbase = smem_u32(sm);
    int tid = threadIdx.x;
    int w = tid >> 5, lane = tid & 31;
    int g = lane >> 2, t = lane & 3;
    int wm = w >> 1, wn = w & 1;

    BF_PREFETCH(CDIM)
    BF_MAINLOOP(CDIM)

#pragma unroll
    for (int i = 0; i < 4; i++) {
        int r = m0 + wm * 64 + i * 16 + g;
#pragma unroll
        for (int j = 0; j < 8; j++) {
            int cc = n0 + wn * 64 + j * 8 + 2 * t;
            size_t o0 = (size_t)r * CDIM + cc;
            size_t o1 = (size_t)(r + 8) * CDIM + cc;
            float2 bv = *(const float2*)&bias[cc];
            *(float2*)&C[o0] = make_float2(fmaxf(acc[i][j][0] + bv.x, 0.f),
                                           fmaxf(acc[i][j][1] + bv.y, 0.f));
            *(float2*)&C[o1] = make_float2(fmaxf(acc[i][j][2] + bv.x, 0.f),
                                           fmaxf(acc[i][j][3] + bv.y, 0.f));
        }
    }
}

// =====================================================================
// pax_cp (pax2, proven tf32 single-pass, 256 thr)
// =====================================================================
__global__ __launch_bounds__(256)
void pax_cp(const float* __restrict__ Pf, const unsigned* __restrict__ Bh,
            const float* __restrict__ U, const float* __restrict__ Rr,
            float* __restrict__ C) {
    extern __shared__ unsigned sm[];
    constexpr int AW = 128 * 36;
    constexpr int BW = 32 * 136;
    constexpr int STG = AW + BW;
    constexpr int NST = 3;
    constexpr int NIT = HW / 32;

    int b = blockIdx.z;
    int d0 = blockIdx.x * 128;
    int n0 = blockIdx.y * 128;

    const float* Pb = Pf + (size_t)b * HW * HW;
    const unsigned* Bhb = Bh + (size_t)b * HW * CDIM;

    unsigned sbase = smem_u32(sm);
    int tid = threadIdx.x;
    int warp = tid >> 5, lane = tid & 31;
    int g = lane >> 2, t = lane & 3;
    int wm = warp >> 2, wn = warp & 3;

    auto prefetch = [&](int it, int s) {
        int k0 = it * 32;
        unsigned sb = sbase + (unsigned)(s * STG) * 4u;
#pragma unroll
        for (int q = 0; q < 4; q++) {
            int f = tid + q * 256;
            int n = f >> 3, c4 = (f & 7) * 4;
            cpa16(sb + (unsigned)(n * 36 + c4) * 4u,
                  Pb + (size_t)(n0 + n) * HW + k0 + c4);
        }
#pragma unroll
        for (int q = 0; q < 4; q++) {
            int f = tid + q * 256;
            int k = f >> 5, d4 = (f & 31) * 4;
            cpa16(sb + (unsigned)(AW + k * 136 + d4) * 4u,
                  Bhb + (size_t)(k0 + k) * CDIM + d0 + d4);
        }
        asm volatile("cp.async.commit_group;\n" ::: "memory");
    };

    float acc[4][4][4] = {};

#pragma unroll
    for (int p = 0; p < NST - 1; p++) prefetch(p, p);

    for (int it = 0; it < NIT; it++) {
        int nx = it + NST - 1;
        if (nx < NIT) { prefetch(nx, nx % NST); cp_wait<NST - 1>(); }
        else cp_wait<0>();
        __syncthreads();

        const float* As = (const float*)(sm + (it % NST) * STG);
        const unsigned* Bs = (const unsigned*)(As + AW);

#pragma unroll
        for (int c = 0; c < 4; c++) {
            int kc = c * 8;
            unsigned bb[4][2];
#pragma unroll
            for (int j = 0; j < 4; j++) {
                int col = wn * 32 + j * 8 + g;
                bb[j][0] = Bs[(kc + t) * 136 + col];
                bb[j][1] = Bs[(kc + t + 4) * 136 + col];
            }
#pragma unroll
            for (int i = 0; i < 4; i++) {
                int row = wm * 64 + i * 16 + g;
                unsigned aa[4];
                aa[0] = f2tf(As[row * 36 + kc + t]);
                aa[1] = f2tf(As[(row + 8) * 36 + kc + t]);
                aa[2] = f2tf(As[row * 36 + kc + t + 4]);
                aa[3] = f2tf(As[(row + 8) * 36 + kc + t + 4]);
#pragma unroll
                for (int j = 0; j < 4; j++) mma_tf32(acc[i][j], aa, bb[j]);
            }
        }
        __syncthreads();
    }

    const float* Ub = U + (size_t)b * HW * CDIM;
    const float* Rb = Rr + (size_t)b * HW * CDIM;
    float* Cb = C + (size_t)b * HW * CDIM;
#pragma unroll
    for (int i = 0; i < 4; i++) {
        int r = n0 + wm * 64 + i * 16 + g;
#pragma unroll
        for (int j = 0; j < 4; j++) {
            int cc = d0 + wn * 32 + j * 8 + 2 * t;
            size_t o0 = (size_t)r * CDIM + cc;
            size_t o1 = (size_t)(r + 8) * CDIM + cc;
            float2 u0 = *(const float2*)&Ub[o0], u1 = *(const float2*)&Ub[o1];
            float2 q0 = *(const float2*)&Rb[o0], q1 = *(const float2*)&Rb[o1];
            *(float2*)&Cb[o0] = make_float2(acc[i][j][0] + u0.x + q0.x,
                                            acc[i][j][1] + u0.y + q0.y);
            *(float2*)&Cb[o1] = make_float2(acc[i][j][2] + u1.x + q1.x,
                                            acc[i][j][3] + u1.y + q1.y);
        }
    }
}

// =====================================================================
// gemm_rr (layer-2 linears, tf32 single): C = relu(A@W + bias)
// =====================================================================
__global__ __launch_bounds__(256, 2)
void gemm_rr(const float* __restrict__ A, const float* __restrict__ B,
             const float* __restrict__ bias, float* __restrict__ C, int lda) {
    extern __shared__ unsigned sm[];
    unsigned* As = sm;
    unsigned* Bs = As + 128 * 36;

    int n0 = blockIdx.x * 128;
    int m0 = blockIdx.y * 128;
    int tid = threadIdx.x;
    int warp = tid >> 5, lane = tid & 31;
    int g = lane >> 2, t = lane & 3;
    int wm = warp >> 2, wn = warp & 3;
    int la_n = tid >> 3, la_k = (tid & 7) * 4;
    int lb_k = tid >> 5, lb_n = (tid & 31) * 4;

    float acc[4][4][4] = {};

    for (int k0 = 0; k0 < CDIM; k0 += 32) {
#pragma unroll
        for (int u = 0; u < 4; u++) {
            int n = la_n + u * 32;
            float4 v = *(const float4*)&A[(size_t)(m0 + n) * lda + k0 + la_k];
            unsigned* p = &As[n * 36 + la_k];
            p[0] = f2tf(v.x); p[1] = f2tf(v.y); p[2] = f2tf(v.z); p[3] = f2tf(v.w);
        }
#pragma unroll
        for (int u = 0; u < 4; u++) {
            int k = lb_k + u * 8;
            float4 v = *(const float4*)&B[(size_t)(k0 + k) * CDIM + n0 + lb_n];
            unsigned* p = &Bs[k * 136 + lb_n];
            p[0] = f2tf(v.x); p[1] = f2tf(v.y); p[2] = f2tf(v.z); p[3] = f2tf(v.w);
        }
        __syncthreads();

#pragma unroll
        for (int c = 0; c < 4; c++) {
            int kc = c * 8;
            unsigned bb[4][2];
#pragma unroll
            for (int j = 0; j < 4; j++) {
                int col = wn * 32 + j * 8 + g;
                bb[j][0] = Bs[(kc + t) * 136 + col];
                bb[j][1] = Bs[(kc + t + 4) * 136 + col];
            }
#pragma unroll
            for (int i = 0; i < 4; i++) {
                int row = wm * 64 + i * 16 + g;
                unsigned aa[4];
                aa[0] = As[row * 36 + kc + t];
                aa[1] = As[(row + 8) * 36 + kc + t];
                aa[2] = As[row * 36 + kc + t + 4];
                aa[3] = As[(row + 8) * 36 + kc + t + 4];
#pragma unroll
                for (int j = 0; j < 4; j++) mma_tf32(acc[i][j], aa, bb[j]);
            }
        }
        __syncthreads();
    }

#pragma unroll
    for (int i = 0; i < 4; i++) {
        int r = m0 + wm * 64 + i * 16 + g;
#pragma unroll
        for (int j = 0; j < 4; j++) {
            int cc = n0 + wn * 32 + j * 8 + 2 * t;
            size_t o0 = (size_t)r * CDIM + cc;
            size_t o1 = (size_t)(r + 8) * CDIM + cc;
            float2 bv = *(const float2*)&bias[cc];
            *(float2*)&C[o0] = make_float2(fmaxf(acc[i][j][0] + bv.x, 0.f),
                                           fmaxf(acc[i][j][1] + bv.y, 0.f));
            *(float2*)&C[o1] = make_float2(fmaxf(acc[i][j][2] + bv.x, 0.f),
                                           fmaxf(acc[i][j][3] + bv.y, 0.f));
        }
    }
}

// ---------------- row softmax ----------------
template<bool WBF>
__global__ void softmax_kernel(float* __restrict__ P, ushortT* __restrict__ Q0,
                               ushortT* __restrict__ Q1) {
    size_t ro = ((size_t)blockIdx.y * HW + blockIdx.x) * HW;
    float* row = P + ro;
    int t = threadIdx.x;
    __shared__ float red[16];
    float v[8];
    float mx = -1e30f;
#pragma unroll
    for (int i = 0; i < 8; i++) { v[i] = row[t + i * 512]; mx = fmaxf(mx, v[i]); }
    for (int o = 16; o; o >>= 1) mx = fmaxf(mx, __shfl_xor_sync(0xffffffffu, mx, o));
    int warp = t >> 5, lane = t & 31;
    if (lane == 0) red[warp] = mx;
    __syncthreads();
    if (warp == 0) {
        float m2 = red[lane & 15];
        for (int o = 8; o; o >>= 1) m2 = fmaxf(m2, __shfl_xor_sync(0xffffffffu, m2, o));
        if (lane == 0) red[0] = m2;
    }
    __syncthreads();
    mx = red[0];
    __syncthreads();
    float s = 0.f;
#pragma unroll
    for (int i = 0; i < 8; i++) { v[i] = __expf(v[i] - mx); s += v[i]; }
    for (int o = 16; o; o >>= 1) s += __shfl_xor_sync(0xffffffffu, s, o);
    if (lane == 0) red[warp] = s;
    __syncthreads();
    if (warp == 0) {
        float s2 = red[lane & 15];
        for (int o = 8; o; o >>= 1) s2 += __shfl_xor_sync(0xffffffffu, s2, o);
        if (lane == 0) red[0] = s2;
    }
    __syncthreads();
    float inv = 1.f / red[0];
#pragma unroll
    for (int i = 0; i < 8; i++) {
        float p = v[i] * inv;
        if (WBF) {
            ushortT h, l;
            bsplit(p, h, l);
            Q0[ro + t + i * 512] = h;
            Q1[ro + t + i * 512] = l;
        } else {
            row[t + i * 512] = p;
        }
    }
}

// ---------------- column partial sums ----------------
// BF variant reads BOTH planes: softmax is peaked, so hi-only rounding
// (~2^-9 relative) does NOT cancel over the sum — R13 post-mortem.
template<bool BF>
__global__ void colsum_kernel(const float* __restrict__ P,
                              const ushortT* __restrict__ Q0,
                              const ushortT* __restrict__ Q1,
                              float* __restrict__ part) {
    int b = blockIdx.z;
    int m = blockIdx.x * 256 + threadIdx.x;
    int r0 = blockIdx.y * 256;
    float s = 0.f;
    if (BF) {
        const ushortT* Q0b = Q0 + (size_t)b * HW * HW;
        const ushortT* Q1b = Q1 + (size_t)b * HW * HW;
#pragma unroll 8
        for (int r = 0; r < 256; r++) {
            size_t o = (size_t)(r0 + r) * HW + m;
            s += __bfloat162float(__ushort_as_bfloat16(Q0b[o]))
               + __bfloat162float(__ushort_as_bfloat16(Q1b[o]));
        }
    } else {
        const float* Pb = P + (size_t)b * HW * HW;
#pragma unroll 8
        for (int r = 0; r < 256; r++) s += Pb[(size_t)(r0 + r) * HW + m];
    }
    part[((size_t)b * 16 + blockIdx.y) * HW + m] = s;
}

__global__ void colinv_kernel(const float* __restrict__ part, float* __restrict__ colinv) {
    int i = blockIdx.x * 256 + threadIdx.x;
    int b = i >> 12, m = i & (HW - 1);
    float s = 0.f;
#pragma unroll
    for (int c2 = 0; c2 < 16; c2++) s += part[((size_t)b * 16 + c2) * HW + m];
    colinv[i] = 1.f / fmaxf(s, 1e-12f);
}

// ---------------- launch ----------------
extern "C" void kernel_launch(void* const* d_in, const int* in_sizes, int n_in,
                              void* d_out, int out_size) {
    (void)in_sizes; (void)n_in; (void)out_size;
    const float* skt = (const float*)d_in[0];
    const float* ref = (const float*)d_in[1];
    const float* Wa3 = (const float*)d_in[2];
    const float* ba3 = (const float*)d_in[3];
    const float* Wu3 = (const float*)d_in[4];
    const float* bu3 = (const float*)d_in[5];
    const float* Wa4 = (const float*)d_in[6];
    const float* ba4 = (const float*)d_in[7];
    const float* Wu4 = (const float*)d_in[8];
    const float* bu4 = (const float*)d_in[9];
    float* out = (float*)d_out;

    float *P, *ax, *ux, *gen, *sktnc, *refnc, *colpart, *colinv;
    unsigned *hi0, *lo0, *hi1, *lo1;
    ushortT *Pb0, *Pb1, *wt;
    cudaGetSymbolAddress((void**)&P, g_P);
    cudaGetSymbolAddress((void**)&Pb0, g_Pb0);
    cudaGetSymbolAddress((void**)&Pb1, g_Pb1);
    cudaGetSymbolAddress((void**)&ax, g_ax);
    cudaGetSymbolAddress((void**)&ux, g_ux);
    cudaGetSymbolAddress((void**)&gen, g_gen);
    cudaGetSymbolAddress((void**)&sktnc, g_sktnc);
    cudaGetSymbolAddress((void**)&refnc, g_refnc);
    cudaGetSymbolAddress((void**)&colpart, g_colpart);
    cudaGetSymbolAddress((void**)&colinv, g_colinv);
    cudaGetSymbolAddress((void**)&hi0, g_hi0);
    cudaGetSymbolAddress((void**)&lo0, g_lo0);
    cudaGetSymbolAddress((void**)&hi1, g_hi1);
    cudaGetSymbolAddress((void**)&lo1, g_lo1);
    cudaGetSymbolAddress((void**)&wt, g_wt);

    ushortT* SA0 = (ushortT*)hi0;  ushortT* SA1 = SA0 + NPL;
    ushortT* SB0 = (ushortT*)lo0;  ushortT* SB1 = SB0 + NPL;
    ushortT* XT0 = (ushortT*)hi1;  ushortT* XT1 = XT0 + NPL;
    unsigned* AXH = lo1;
    ushortT* WA0 = wt;              ushortT* WA1 = WA0 + 256 * 256;
    ushortT* WU0 = WA1 + 256 * 256; ushortT* WU1 = WU0 + 256 * 256;

    const int SM1   = (128 * 36 + 32 * 136) * 4;           // 35840
    const int SMBF  = 2 * STGW * 4;                        // 81920
    const int SMP1  = 3 * (128 * 36 + 32 * 136) * 4;       // 107520
    cudaFuncSetAttribute(gemm_rr,          cudaFuncAttributeMaxDynamicSharedMemorySize, SM1);
    cudaFuncSetAttribute(logits_bf<false>, cudaFuncAttributeMaxDynamicSharedMemorySize, SMBF);
    cudaFuncSetAttribute(logits_bf<true>,  cudaFuncAttributeMaxDynamicSharedMemorySize, SMBF);
    cudaFuncSetAttribute(pax_bf,           cudaFuncAttributeMaxDynamicSharedMemorySize, SMBF);
    cudaFuncSetAttribute(linear_bf,        cudaFuncAttributeMaxDynamicSharedMemorySize, SMBF);
    cudaFuncSetAttribute(pax_cp,           cudaFuncAttributeMaxDynamicSharedMemorySize, SMP1);

    dim3 tb(32, 8);
    dim3 gLin(CDIM / 128, (BATCH * HW) / 128, 1);
    dim3 gLog(HW / 128, HW / 128, BATCH);
    dim3 gPax(CDIM / 128, HW / 128, BATCH);
    const int nSplit = (BATCH * HW * CDIM) / (4 * 256);

    // ===== layer 1 =====
    transpose_kernel<<<dim3(HW / 32, CDIM / 32, BATCH), tb>>>(skt, sktnc, CDIM, HW);
    transpose_kernel<<<dim3(HW / 32, CDIM / 32, BATCH), tb>>>(ref, refnc, CDIM, HW);
    bsplit2_kernel<<<nSplit, 256>>>(sktnc, SA0, SA1);
    bsplit2_kernel<<<nSplit, 256>>>(refnc, SB0, SB1);
    wt_split_kernel<<<dim3(8, 8), tb>>>(Wa3, WA0, WA1);
    wt_split_kernel<<<dim3(8, 8), tb>>>(Wu3, WU0, WU1);
    linear_bf<<<gLin, 128, SMBF>>>(SB0, SB1, WA0, WA1, ba3, ax);
    linear_bf<<<gLin, 128, SMBF>>>(SA0, SA1, WU0, WU1, bu3, ux);
    logits_bf<false><<<gLog, 128, SMBF>>>(SA0, SA1, SB0, SB1, P);
    softmax_kernel<true><<<dim3(HW, BATCH), 512>>>(P, Pb0, Pb1);
    colsum_kernel<true><<<dim3(HW / 256, 16, BATCH), 256>>>(nullptr, Pb0, Pb1, colpart);
    colinv_kernel<<<(BATCH * HW) / 256, 256>>>(colpart, colinv);
    axt_split_kernel<<<dim3(HW / 32, CDIM / 32, BATCH), tb>>>(ax, colinv, XT0, XT1);
    pax_bf<<<gPax, 128, SMBF>>>(Pb0, Pb1, XT0, XT1, ux, sktnc, gen);

    // ===== layer 2 =====
    bsplit2_kernel<<<nSplit, 256>>>(gen, SA0, SA1);
    gemm_rr<<<gLin, 256, SM1>>>(gen, Wa4, ba4, ax, CDIM);
    gemm_rr<<<gLin, 256, SM1>>>(gen, Wu4, bu4, ux, CDIM);
    logits_bf<true><<<gLog, 128, SMBF>>>(SA0, SA1, SA0, SA1, P);
    softmax_kernel<false><<<dim3(HW, BATCH), 512>>>(P, nullptr, nullptr);
    colsum_kernel<false><<<dim3(HW / 256, 16, BATCH), 256>>>(P, nullptr, nullptr, colpart);
    colinv_kernel<<<(BATCH * HW) / 256, 256>>>(colpart, colinv);
    scale_split_kernel<<<nSplit, 256>>>(ax, colinv, AXH);
    pax_cp<<<gPax, 256, SMP1>>>(P, AXH, ux, gen, out);
}

// round 15
// speedup vs baseline: 1.5248x; 1.0187x over previous
#include <cuda_runtime.h>
#include <cuda_bf16.h>
#include <math.h>

#define BATCH 4
#define CDIM  256
#define HW    4096
#define NPL   ((size_t)BATCH * HW * CDIM)

typedef unsigned short ushortT;

// ---------------- scratch ----------------
static __device__ float g_P[(size_t)BATCH * HW * HW];
static __device__ ushortT g_Pb0[(size_t)BATCH * HW * HW];
static __device__ ushortT g_Pb1[(size_t)BATCH * HW * HW];
static __device__ float g_ax[(size_t)BATCH * HW * CDIM];
static __device__ float g_ux[(size_t)BATCH * HW * CDIM];
static __device__ float g_gen[(size_t)BATCH * HW * CDIM];
static __device__ float g_sktnc[(size_t)BATCH * HW * CDIM];
static __device__ float g_refnc[(size_t)BATCH * HW * CDIM];
static __device__ float g_colpart[(size_t)BATCH * 16 * HW];
static __device__ float g_colinv[(size_t)BATCH * HW];
static __device__ unsigned g_hi0[(size_t)BATCH * HW * CDIM];   // SA planes
static __device__ unsigned g_lo0[(size_t)BATCH * HW * CDIM];   // SB planes
static __device__ unsigned g_hi1[(size_t)BATCH * HW * CDIM];   // XT planes
static __device__ unsigned g_lo1[(size_t)BATCH * HW * CDIM];   // tf32 ax hi (pax2)
static __device__ ushortT g_wt[4][256 * 256];                  // WaT0,WaT1,WuT0,WuT1

// ---------------- helpers ----------------
__device__ __forceinline__ unsigned f2tf(float x) {
    unsigned r;
    asm("cvt.rna.tf32.f32 %0, %1;" : "=r"(r) : "f"(x));
    return r;
}

__device__ __forceinline__ void mma_tf32(float* d, const unsigned* a, const unsigned* b) {
    asm("mma.sync.aligned.m16n8k8.row.col.f32.tf32.tf32.f32 "
        "{%0,%1,%2,%3},{%4,%5,%6,%7},{%8,%9},{%0,%1,%2,%3};"
        : "+f"(d[0]), "+f"(d[1]), "+f"(d[2]), "+f"(d[3])
        : "r"(a[0]), "r"(a[1]), "r"(a[2]), "r"(a[3]), "r"(b[0]), "r"(b[1]));
}

__device__ __forceinline__ void mma_bf16(float* d, const unsigned* a, const unsigned* b) {
    asm("mma.sync.aligned.m16n8k16.row.col.f32.bf16.bf16.f32 "
        "{%0,%1,%2,%3},{%4,%5,%6,%7},{%8,%9},{%0,%1,%2,%3};"
        : "+f"(d[0]), "+f"(d[1]), "+f"(d[2]), "+f"(d[3])
        : "r"(a[0]), "r"(a[1]), "r"(a[2]), "r"(a[3]), "r"(b[0]), "r"(b[1]));
}

__device__ __forceinline__ void cpa16(unsigned saddr, const void* g) {
    asm volatile("cp.async.cg.shared.global [%0], [%1], 16;\n" :: "r"(saddr), "l"(g));
}

template<int N>
__device__ __forceinline__ void cp_wait() {
    asm volatile("cp.async.wait_group %0;\n" :: "n"(N) : "memory");
}

__device__ __forceinline__ unsigned smem_u32(const void* p) {
    unsigned a;
    asm("{ .reg .u64 t; cvta.to.shared.u64 t, %1; cvt.u32.u64 %0, t; }" : "=r"(a) : "l"(p));
    return a;
}

__device__ __forceinline__ void bsplit(float x, ushortT& h, ushortT& l) {
    __nv_bfloat16 b0 = __float2bfloat16(x);
    __nv_bfloat16 b1 = __float2bfloat16(x - __bfloat162float(b0));
    h = __bfloat16_as_ushort(b0);
    l = __bfloat16_as_ushort(b1);
}

// ---------------- bf16 2-plane split ----------------
__global__ void bsplit2_kernel(const float* __restrict__ in,
                               ushortT* __restrict__ p0, ushortT* __restrict__ p1) {
    size_t i = (size_t)blockIdx.x * 256 + threadIdx.x;
    float4 v = ((const float4*)in)[i];
    float x[4] = {v.x, v.y, v.z, v.w};
    ushortT h[4], l[4];
#pragma unroll
    for (int e = 0; e < 4; e++) bsplit(x[e], h[e], l[e]);
    ((uint2*)p0)[i] = make_uint2(h[0] | ((unsigned)h[1] << 16), h[2] | ((unsigned)h[3] << 16));
    ((uint2*)p1)[i] = make_uint2(l[0] | ((unsigned)l[1] << 16), l[2] | ((unsigned)l[3] << 16));
}

// ---------------- tf32 scale+split (pax2) ----------------
__global__ void scale_split_kernel(const float* __restrict__ ax,
                                   const float* __restrict__ colinv,
                                   unsigned* __restrict__ hi) {
    size_t i = (size_t)blockIdx.x * 256 + threadIdx.x;
    int row = (int)(i >> 6);
    float sc = colinv[row];
    float4 v = ((const float4*)ax)[i];
    uint4 h;
    h.x = f2tf(v.x * sc); h.y = f2tf(v.y * sc);
    h.z = f2tf(v.z * sc); h.w = f2tf(v.w * sc);
    ((uint4*)hi)[i] = h;
}

// ---------------- ax scale + transpose + bf16 split -> [d][k] planes ----------------
__global__ void axt_split_kernel(const float* __restrict__ ax, const float* __restrict__ colinv,
                                 ushortT* __restrict__ p0, ushortT* __restrict__ p1) {
    __shared__ float tile[32][33];
    int b = blockIdx.z;
    int k0 = blockIdx.x * 32, d0 = blockIdx.y * 32;
    int tx = threadIdx.x, ty = threadIdx.y;
    const float* axb = ax + (size_t)b * HW * CDIM;
#pragma unroll
    for (int i = 0; i < 32; i += 8) {
        float sc = colinv[(b << 12) + k0 + ty + i];
        tile[ty + i][tx] = axb[(size_t)(k0 + ty + i) * CDIM + d0 + tx] * sc;
    }
    __syncthreads();
#pragma unroll
    for (int i = 0; i < 32; i += 8) {
        float v = tile[tx][ty + i];
        ushortT h, l;
        bsplit(v, h, l);
        size_t o = (size_t)b * CDIM * HW + (size_t)(d0 + ty + i) * HW + k0 + tx;
        p0[o] = h;
        p1[o] = l;
    }
}

// ---------------- W transpose + split: W[k][n] -> WT planes [n][k] ----------------
__global__ void wt_split_kernel(const float* __restrict__ W,
                                ushortT* __restrict__ p0, ushortT* __restrict__ p1) {
    __shared__ float tile[32][33];
    int k0 = blockIdx.x * 32, n0 = blockIdx.y * 32;
    int tx = threadIdx.x, ty = threadIdx.y;
#pragma unroll
    for (int i = 0; i < 32; i += 8)
        tile[ty + i][tx] = W[(size_t)(k0 + ty + i) * CDIM + n0 + tx];
    __syncthreads();
#pragma unroll
    for (int i = 0; i < 32; i += 8) {
        float v = tile[tx][ty + i];
        ushortT h, l;
        bsplit(v, h, l);
        size_t o = (size_t)(n0 + ty + i) * CDIM + k0 + tx;
        p0[o] = h;
        p1[o] = l;
    }
}

// ---------------- transpose ----------------
__global__ void transpose_kernel(const float* __restrict__ in, float* __restrict__ out,
                                 int R, int S) {
    __shared__ float tile[32][33];
    int b = blockIdx.z;
    int s0 = blockIdx.x * 32, r0 = blockIdx.y * 32;
    const float* inb = in + (size_t)b * R * S;
    float* outb = out + (size_t)b * R * S;
    int tx = threadIdx.x, ty = threadIdx.y;
#pragma unroll
    for (int i = 0; i < 32; i += 8)
        tile[ty + i][tx] = inb[(size_t)(r0 + ty + i) * S + s0 + tx];
    __syncthreads();
#pragma unroll
    for (int i = 0; i < 32; i += 8)
        outb[(size_t)(s0 + ty + i) * R + r0 + tx] = tile[tx][ty + i];
}

// =====================================================================
// bf16 3-product core, 4 warps (128 thr), warp tile 64x64, CTA 128x128
// (logits / linears).
// =====================================================================
#define RST 20
#define PLW (128 * RST)
#define STGW (4 * PLW)           // words per stage

#define BF_MAINLOOP(LD)                                                          \
    float acc[4][8][4] = {};                                                     \
    prefetch(0, 0);                                                              \
    for (int it = 0; it < NIT; it++) {                                           \
        if (it + 1 < NIT) { prefetch(it + 1, (it + 1) & 1); cp_wait<1>(); }      \
        else cp_wait<0>();                                                       \
        __syncthreads();                                                         \
        const unsigned* As0 = sm + (it & 1) * STGW;                              \
        const unsigned* As1 = As0 + PLW;                                         \
        const unsigned* Bs0 = As0 + 2 * PLW;                                     \
        const unsigned* Bs1 = As0 + 3 * PLW;                                     \
        _Pragma("unroll")                                                        \
        for (int c = 0; c < 2; c++) {                                            \
            int kc = c * 8;                                                      \
            unsigned b0[8][2], b1[8][2];                                         \
            _Pragma("unroll")                                                    \
            for (int j = 0; j < 8; j++) {                                        \
                int col = wn * 64 + j * 8 + g;                                   \
                b0[j][0] = Bs0[col * RST + kc + t];                              \
                b0[j][1] = Bs0[col * RST + kc + t + 4];                          \
                b1[j][0] = Bs1[col * RST + kc + t];                              \
                b1[j][1] = Bs1[col * RST + kc + t + 4];                          \
            }                                                                    \
            _Pragma("unroll")                                                    \
            for (int i = 0; i < 4; i++) {                                        \
                int row = wm * 64 + i * 16 + g;                                  \
                unsigned a0[4], a1[4];                                           \
                a0[0] = As0[row * RST + kc + t];                                 \
                a0[1] = As0[(row + 8) * RST + kc + t];                           \
                a0[2] = As0[row * RST + kc + t + 4];                             \
                a0[3] = As0[(row + 8) * RST + kc + t + 4];                       \
                a1[0] = As1[row * RST + kc + t];                                 \
                a1[1] = As1[(row + 8) * RST + kc + t];                           \
                a1[2] = As1[row * RST + kc + t + 4];                             \
                a1[3] = As1[(row + 8) * RST + kc + t + 4];                       \
                _Pragma("unroll")                                                \
                for (int j = 0; j < 8; j++) {                                    \
                    mma_bf16(acc[i][j], a0, b0[j]);                              \
                    mma_bf16(acc[i][j], a0, b1[j]);                              \
                    mma_bf16(acc[i][j], a1, b0[j]);                              \
                }                                                                \
            }                                                                    \
        }                                                                        \
        __syncthreads();                                                         \
    }

#define BF_PREFETCH(LD)                                                          \
    auto prefetch = [&](int it, int s) {                                         \
        int k0 = it * 32;                                                        \
        unsigned sb = sbase + (unsigned)(s * STGW) * 4u;                         \
        _Pragma("unroll")                                                        \
        for (int q = 0; q < 16; q++) {                                           \
            int e = tid + q * 128;                                               \
            int pl = e >> 9;                                                     \
            int ep = e & 511;                                                    \
            int r = ep >> 2, wc = ep & 3;                                        \
            cpa16(sb + (unsigned)(pl * PLW + r * RST + wc * 4) * 4u,             \
                  gp[pl] + (size_t)r * (LD) + k0 + wc * 8);                      \
        }                                                                        \
        asm volatile("cp.async.commit_group;\n" ::: "memory");                   \
    };

// logits: L[n][m] = sum_k A[n][k]*B[m][k]; NIT = 8
template<bool SYM>
__global__ __launch_bounds__(128)
void logits_bf(const ushortT* __restrict__ A0, const ushortT* __restrict__ A1,
               const ushortT* __restrict__ B0, const ushortT* __restrict__ B1,
               float* __restrict__ L) {
    extern __shared__ unsigned sm[];
    constexpr int NIT = CDIM / 32;

    int bx = blockIdx.x, by = blockIdx.y, b = blockIdx.z;
    if (SYM && bx < by) return;
    int m0 = bx * 128, n0 = by * 128;

    const ushortT* gp[4];
    gp[0] = A0 + ((size_t)b * HW + n0) * CDIM;
    gp[1] = A1 + ((size_t)b * HW + n0) * CDIM;
    gp[2] = B0 + ((size_t)b * HW + m0) * CDIM;
    gp[3] = B1 + ((size_t)b * HW + m0) * CDIM;
    float* Lb = L + (size_t)b * HW * HW;

    unsigned sbase = smem_u32(sm);
    int tid = threadIdx.x;
    int w = tid >> 5, lane = tid & 31;
    int g = lane >> 2, t = lane & 3;
    int wm = w >> 1, wn = w & 1;

    BF_PREFETCH(CDIM)
    BF_MAINLOOP(CDIM)

#pragma unroll
    for (int i = 0; i < 4; i++) {
        int r = n0 + wm * 64 + i * 16 + g;
#pragma unroll
        for (int j = 0; j < 8; j++) {
            int cc = m0 + wn * 64 + j * 8 + 2 * t;
            *(float2*)&Lb[(size_t)r * HW + cc] =
                make_float2(acc[i][j][0], acc[i][j][1]);
            *(float2*)&Lb[(size_t)(r + 8) * HW + cc] =
                make_float2(acc[i][j][2], acc[i][j][3]);
        }
    }
    if (SYM && bx != by) {
#pragma unroll
        for (int i = 0; i < 4; i++) {
            int rr = n0 + wm * 64 + i * 16 + g;
#pragma unroll
            for (int j = 0; j < 8; j++) {
                int cc = m0 + wn * 64 + j * 8 + 2 * t;
                Lb[(size_t)cc * HW + rr]           = acc[i][j][0];
                Lb[(size_t)(cc + 1) * HW + rr]     = acc[i][j][1];
                Lb[(size_t)cc * HW + rr + 8]       = acc[i][j][2];
                Lb[(size_t)(cc + 1) * HW + rr + 8] = acc[i][j][3];
            }
        }
    }
}

// =====================================================================
// pax1: C[n][d] = sum_k P[n][k]*axT[d][k] + U + R; CTA tile 128x256,
// 256 thr (8 warps 2x4 of 64x64) — P row-slice read ONCE per CTA.
// =====================================================================
__global__ __launch_bounds__(256)
void pax_bf(const ushortT* __restrict__ P0, const ushortT* __restrict__ P1,
            const ushortT* __restrict__ X0, const ushortT* __restrict__ X1,
            const float* __restrict__ U, const float* __restrict__ Rr,
            float* __restrict__ C) {
    extern __shared__ unsigned sm[];
    constexpr int NIT = HW / 32;
    constexpr int APLW = 128 * RST;          // P plane tile words
    constexpr int XPLW = 256 * RST;          // X plane tile words
    constexpr int PSTG = 2 * APLW + 2 * XPLW;

    int b = blockIdx.y;
    int n0 = blockIdx.x * 128;

    const ushortT* gpP[2];
    gpP[0] = P0 + ((size_t)b * HW + n0) * HW;
    gpP[1] = P1 + ((size_t)b * HW + n0) * HW;
    const ushortT* gpX[2];
    gpX[0] = X0 + (size_t)b * CDIM * HW;
    gpX[1] = X1 + (size_t)b * CDIM * HW;

    unsigned sbase = smem_u32(sm);
    int tid = threadIdx.x;
    int w = tid >> 5, lane = tid & 31;
    int g = lane >> 2, t = lane & 3;
    int wm = w >> 2, wn = w & 3;

    auto prefetch = [&](int it, int s) {
        int k0 = it * 32;
        unsigned sb = sbase + (unsigned)(s * PSTG) * 4u;
#pragma unroll
        for (int q = 0; q < 4; q++) {        // P: 2 planes x 128 rows x 4 chunks
            int e = tid + q * 256;
            int pl = e >> 9, ep = e & 511;
            int r = ep >> 2, wc = ep & 3;
            cpa16(sb + (unsigned)(pl * APLW + r * RST + wc * 4) * 4u,
                  gpP[pl] + (size_t)r * HW + k0 + wc * 8);
        }
#pragma unroll
        for (int q = 0; q < 8; q++) {        // X: 2 planes x 256 rows x 4 chunks
            int e = tid + q * 256;
            int pl = e >> 10, ep = e & 1023;
            int r = ep >> 2, wc = ep & 3;
            cpa16(sb + (unsigned)(2 * APLW + pl * XPLW + r * RST + wc * 4) * 4u,
                  gpX[pl] + (size_t)r * HW + k0 + wc * 8);
        }
        asm volatile("cp.async.commit_group;\n" ::: "memory");
    };

    float acc[4][8][4] = {};
    prefetch(0, 0);
    for (int it = 0; it < NIT; it++) {
        if (it + 1 < NIT) { prefetch(it + 1, (it + 1) & 1); cp_wait<1>(); }
        else cp_wait<0>();
        __syncthreads();

        const unsigned* As0 = sm + (it & 1) * PSTG;
        const unsigned* As1 = As0 + APLW;
        const unsigned* Bs0 = As0 + 2 * APLW;
        const unsigned* Bs1 = Bs0 + XPLW;

#pragma unroll
        for (int c = 0; c < 2; c++) {
            int kc = c * 8;
            unsigned b0[8][2], b1[8][2];
#pragma unroll
            for (int j = 0; j < 8; j++) {
                int col = wn * 64 + j * 8 + g;
                b0[j][0] = Bs0[col * RST + kc + t];
                b0[j][1] = Bs0[col * RST + kc + t + 4];
                b1[j][0] = Bs1[col * RST + kc + t];
                b1[j][1] = Bs1[col * RST + kc + t + 4];
            }
#pragma unroll
            for (int i = 0; i < 4; i++) {
                int row = wm * 64 + i * 16 + g;
                unsigned a0[4], a1[4];
                a0[0] = As0[row * RST + kc + t];
                a0[1] = As0[(row + 8) * RST + kc + t];
                a0[2] = As0[row * RST + kc + t + 4];
                a0[3] = As0[(row + 8) * RST + kc + t + 4];
                a1[0] = As1[row * RST + kc + t];
                a1[1] = As1[(row + 8) * RST + kc + t];
                a1[2] = As1[row * RST + kc + t + 4];
                a1[3] = As1[(row + 8) * RST + kc + t + 4];
#pragma unroll
                for (int j = 0; j < 8; j++) {
                    mma_bf16(acc[i][j], a0, b0[j]);
                    mma_bf16(acc[i][j], a0, b1[j]);
                    mma_bf16(acc[i][j], a1, b0[j]);
                }
            }
        }
        __syncthreads();
    }

    const float* Ub = U + (size_t)b * HW * CDIM;
    const float* Rb = Rr + (size_t)b * HW * CDIM;
    float* Cb = C + (size_t)b * HW * CDIM;
#pragma unroll
    for (int i = 0; i < 4; i++) {
        int r = n0 + wm * 64 + i * 16 + g;
#pragma unroll
        for (int j = 0; j < 8; j++) {
            int cc = wn * 64 + j * 8 + 2 * t;
            size_t o0 = (size_t)r * CDIM + cc;
            size_t o1 = (size_t)(r + 8) * CDIM + cc;
            float2 u0 = *(const float2*)&Ub[o0], u1 = *(const float2*)&Ub[o1];
            float2 q0 = *(const float2*)&Rb[o0], q1 = *(const float2*)&Rb[o1];
            *(float2*)&Cb[o0] = make_float2(acc[i][j][0] + u0.x + q0.x,
                                            acc[i][j][1] + u0.y + q0.y);
            *(float2*)&Cb[o1] = make_float2(acc[i][j][2] + u1.x + q1.x,
                                            acc[i][j][3] + u1.y + q1.y);
        }
    }
}

// linear (layer 1): C[m][n] = relu(A@W + bias); A planes [m][k], WT planes [n][k]
__global__ __launch_bounds__(128)
void linear_bf(const ushortT* __restrict__ A0, const ushortT* __restrict__ A1,
               const ushortT* __restrict__ W0, const ushortT* __restrict__ W1,
               const float* __restrict__ bias, float* __restrict__ C) {
    extern __shared__ unsigned sm[];
    constexpr int NIT = CDIM / 32;

    int n0 = blockIdx.x * 128;
    int m0 = blockIdx.y * 128;

    const ushortT* gp[4];
    gp[0] = A0 + (size_t)m0 * CDIM;
    gp[1] = A1 + (size_t)m0 * CDIM;
    gp[2] = W0 + (size_t)n0 * CDIM;
    gp[3] = W1 + (size_t)n0 * CDIM;

    unsigned sbase = smem_u32(sm);
    int tid = threadIdx.x;
    int w = tid >> 5, lane = tid & 31;
    int g = lane >> 2, t = lane & 3;
    int wm = w >> 1, wn = w & 1;

    BF_PREFETCH(CDIM)
    BF_MAINLOOP(CDIM)

#pragma unroll
    for (int i = 0; i < 4; i++) {
        int r = m0 + wm * 64 + i * 16 + g;
#pragma unroll
        for (int j = 0; j < 8; j++) {
            int cc = n0 + wn * 64 + j * 8 + 2 * t;
            size_t o0 = (size_t)r * CDIM + cc;
            size_t o1 = (size_t)(r + 8) * CDIM + cc;
            float2 bv = *(const float2*)&bias[cc];
            *(float2*)&C[o0] = make_float2(fmaxf(acc[i][j][0] + bv.x, 0.f),
                                           fmaxf(acc[i][j][1] + bv.y, 0.f));
            *(float2*)&C[o1] = make_float2(fmaxf(acc[i][j][2] + bv.x, 0.f),
                                           fmaxf(acc[i][j][3] + bv.y, 0.f));
        }
    }
}

// =====================================================================
// pax2 (tf32 single-pass): C = P@axh + U + R; CTA tile 128x256,
// 256 thr (8 warps 2x4 of 64x64) — P row-slice read ONCE per CTA.
// =====================================================================
__global__ __launch_bounds__(256)
void pax_cp(const float* __restrict__ Pf, const unsigned* __restrict__ Bh,
            const float* __restrict__ U, const float* __restrict__ Rr,
            float* __restrict__ C) {
    extern __shared__ unsigned sm[];
    constexpr int AW = 128 * 36;       // P float tile words
    constexpr int BW = 32 * 264;       // ax tile words (32 k x 256 d, pad 8)
    constexpr int STG = AW + BW;
    constexpr int NIT = HW / 32;

    int b = blockIdx.y;
    int n0 = blockIdx.x * 128;

    const float* Pb = Pf + (size_t)b * HW * HW;
    const unsigned* Bhb = Bh + (size_t)b * HW * CDIM;

    unsigned sbase = smem_u32(sm);
    int tid = threadIdx.x;
    int warp = tid >> 5, lane = tid & 31;
    int g = lane >> 2, t = lane & 3;
    int wm = warp >> 2, wn = warp & 3;

    auto prefetch = [&](int it, int s) {
        int k0 = it * 32;
        unsigned sb = sbase + (unsigned)(s * STG) * 4u;
#pragma unroll
        for (int q = 0; q < 4; q++) {      // P: 128 rows x 8 float4
            int f = tid + q * 256;
            int n = f >> 3, c4 = (f & 7) * 4;
            cpa16(sb + (unsigned)(n * 36 + c4) * 4u,
                  Pb + (size_t)(n0 + n) * HW + k0 + c4);
        }
#pragma unroll
        for (int q = 0; q < 8; q++) {      // ax: 32 k x 64 float4
            int f = tid + q * 256;
            int k = f >> 6, d4 = (f & 63) * 4;
            cpa16(sb + (unsigned)(AW + k * 264 + d4) * 4u,
                  Bhb + (size_t)(k0 + k) * CDIM + d4);
        }
        asm volatile("cp.async.commit_group;\n" ::: "memory");
    };

    float acc[4][8][4] = {};

    prefetch(0, 0);
    for (int it = 0; it < NIT; it++) {
        if (it + 1 < NIT) { prefetch(it + 1, (it + 1) & 1); cp_wait<1>(); }
        else cp_wait<0>();
        __syncthreads();

        const float* As = (const float*)(sm + (it & 1) * STG);
        const unsigned* Bs = (const unsigned*)(As + AW);

#pragma unroll
        for (int c = 0; c < 4; c++) {
            int kc = c * 8;
            unsigned bb[8][2];
#pragma unroll
            for (int j = 0; j < 8; j++) {
                int col = wn * 64 + j * 8 + g;
                bb[j][0] = Bs[(kc + t) * 264 + col];
                bb[j][1] = Bs[(kc + t + 4) * 264 + col];
            }
#pragma unroll
            for (int i = 0; i < 4; i++) {
                int row = wm * 64 + i * 16 + g;
                unsigned aa[4];
                aa[0] = f2tf(As[row * 36 + kc + t]);
                aa[1] = f2tf(As[(row + 8) * 36 + kc + t]);
                aa[2] = f2tf(As[row * 36 + kc + t + 4]);
                aa[3] = f2tf(As[(row + 8) * 36 + kc + t + 4]);
#pragma unroll
                for (int j = 0; j < 8; j++) mma_tf32(acc[i][j], aa, bb[j]);
            }
        }
        __syncthreads();
    }

    const float* Ub = U + (size_t)b * HW * CDIM;
    const float* Rb = Rr + (size_t)b * HW * CDIM;
    float* Cb = C + (size_t)b * HW * CDIM;
#pragma unroll
    for (int i = 0; i < 4; i++) {
        int r = n0 + wm * 64 + i * 16 + g;
#pragma unroll
        for (int j = 0; j < 8; j++) {
            int cc = wn * 64 + j * 8 + 2 * t;
            size_t o0 = (size_t)r * CDIM + cc;
            size_t o1 = (size_t)(r + 8) * CDIM + cc;
            float2 u0 = *(const float2*)&Ub[o0], u1 = *(const float2*)&Ub[o1];
            float2 q0 = *(const float2*)&Rb[o0], q1 = *(const float2*)&Rb[o1];
            *(float2*)&Cb[o0] = make_float2(acc[i][j][0] + u0.x + q0.x,
                                            acc[i][j][1] + u0.y + q0.y);
            *(float2*)&Cb[o1] = make_float2(acc[i][j][2] + u1.x + q1.x,
                                            acc[i][j][3] + u1.y + q1.y);
        }
    }
}

// =====================================================================
// gemm_rr (layer-2 linears, tf32 single): C = relu(A@W + bias)
// =====================================================================
__global__ __launch_bounds__(256, 2)
void gemm_rr(const float* __restrict__ A, const float* __restrict__ B,
             const float* __restrict__ bias, float* __restrict__ C, int lda) {
    extern __shared__ unsigned sm[];
    unsigned* As = sm;
    unsigned* Bs = As + 128 * 36;

    int n0 = blockIdx.x * 128;
    int m0 = blockIdx.y * 128;
    int tid = threadIdx.x;
    int warp = tid >> 5, lane = tid & 31;
    int g = lane >> 2, t = lane & 3;
    int wm = warp >> 2, wn = warp & 3;
    int la_n = tid >> 3, la_k = (tid & 7) * 4;
    int lb_k = tid >> 5, lb_n = (tid & 31) * 4;

    float acc[4][4][4] = {};

    for (int k0 = 0; k0 < CDIM; k0 += 32) {
#pragma unroll
        for (int u = 0; u < 4; u++) {
            int n = la_n + u * 32;
            float4 v = *(const float4*)&A[(size_t)(m0 + n) * lda + k0 + la_k];
            unsigned* p = &As[n * 36 + la_k];
            p[0] = f2tf(v.x); p[1] = f2tf(v.y); p[2] = f2tf(v.z); p[3] = f2tf(v.w);
        }
#pragma unroll
        for (int u = 0; u < 4; u++) {
            int k = lb_k + u * 8;
            float4 v = *(const float4*)&B[(size_t)(k0 + k) * CDIM + n0 + lb_n];
            unsigned* p = &Bs[k * 136 + lb_n];
            p[0] = f2tf(v.x); p[1] = f2tf(v.y); p[2] = f2tf(v.z); p[3] = f2tf(v.w);
        }
        __syncthreads();

#pragma unroll
        for (int c = 0; c < 4; c++) {
            int kc = c * 8;
            unsigned bb[4][2];
#pragma unroll
            for (int j = 0; j < 4; j++) {
                int col = wn * 32 + j * 8 + g;
                bb[j][0] = Bs[(kc + t) * 136 + col];
                bb[j][1] = Bs[(kc + t + 4) * 136 + col];
            }
#pragma unroll
            for (int i = 0; i < 4; i++) {
                int row = wm * 64 + i * 16 + g;
                unsigned aa[4];
                aa[0] = As[row * 36 + kc + t];
                aa[1] = As[(row + 8) * 36 + kc + t];
                aa[2] = As[row * 36 + kc + t + 4];
                aa[3] = As[(row + 8) * 36 + kc + t + 4];
#pragma unroll
                for (int j = 0; j < 4; j++) mma_tf32(acc[i][j], aa, bb[j]);
            }
        }
        __syncthreads();
    }

#pragma unroll
    for (int i = 0; i < 4; i++) {
        int r = m0 + wm * 64 + i * 16 + g;
#pragma unroll
        for (int j = 0; j < 4; j++) {
            int cc = n0 + wn * 32 + j * 8 + 2 * t;
            size_t o0 = (size_t)r * CDIM + cc;
            size_t o1 = (size_t)(r + 8) * CDIM + cc;
            float2 bv = *(const float2*)&bias[cc];
            *(float2*)&C[o0] = make_float2(fmaxf(acc[i][j][0] + bv.x, 0.f),
                                           fmaxf(acc[i][j][1] + bv.y, 0.f));
            *(float2*)&C[o1] = make_float2(fmaxf(acc[i][j][2] + bv.x, 0.f),
                                           fmaxf(acc[i][j][3] + bv.y, 0.f));
        }
    }
}

// ---------------- row softmax ----------------
template<bool WBF>
__global__ void softmax_kernel(float* __restrict__ P, ushortT* __restrict__ Q0,
                               ushortT* __restrict__ Q1) {
    size_t ro = ((size_t)blockIdx.y * HW + blockIdx.x) * HW;
    float* row = P + ro;
    int t = threadIdx.x;
    __shared__ float red[16];
    float v[8];
    float mx = -1e30f;
#pragma unroll
    for (int i = 0; i < 8; i++) { v[i] = row[t + i * 512]; mx = fmaxf(mx, v[i]); }
    for (int o = 16; o; o >>= 1) mx = fmaxf(mx, __shfl_xor_sync(0xffffffffu, mx, o));
    int warp = t >> 5, lane = t & 31;
    if (lane == 0) red[warp] = mx;
    __syncthreads();
    if (warp == 0) {
        float m2 = red[lane & 15];
        for (int o = 8; o; o >>= 1) m2 = fmaxf(m2, __shfl_xor_sync(0xffffffffu, m2, o));
        if (lane == 0) red[0] = m2;
    }
    __syncthreads();
    mx = red[0];
    __syncthreads();
    float s = 0.f;
#pragma unroll
    for (int i = 0; i < 8; i++) { v[i] = __expf(v[i] - mx); s += v[i]; }
    for (int o = 16; o; o >>= 1) s += __shfl_xor_sync(0xffffffffu, s, o);
    if (lane == 0) red[warp] = s;
    __syncthreads();
    if (warp == 0) {
        float s2 = red[lane & 15];
        for (int o = 8; o; o >>= 1) s2 += __shfl_xor_sync(0xffffffffu, s2, o);
        if (lane == 0) red[0] = s2;
    }
    __syncthreads();
    float inv = 1.f / red[0];
#pragma unroll
    for (int i = 0; i < 8; i++) {
        float p = v[i] * inv;
        if (WBF) {
            ushortT h, l;
            bsplit(p, h, l);
            Q0[ro + t + i * 512] = h;
            Q1[ro + t + i * 512] = l;
        } else {
            row[t + i * 512] = p;
        }
    }
}

// ---------------- column partial sums ----------------
// BF variant reads BOTH planes (peaked softmax: hi-only rounding does
// not cancel — R13 post-mortem).
template<bool BF>
__global__ void colsum_kernel(const float* __restrict__ P,
                              const ushortT* __restrict__ Q0,
                              const ushortT* __restrict__ Q1,
                              float* __restrict__ part) {
    int b = blockIdx.z;
    int m = blockIdx.x * 256 + threadIdx.x;
    int r0 = blockIdx.y * 256;
    float s = 0.f;
    if (BF) {
        const ushortT* Q0b = Q0 + (size_t)b * HW * HW;
        const ushortT* Q1b = Q1 + (size_t)b * HW * HW;
#pragma unroll 8
        for (int r = 0; r < 256; r++) {
            size_t o = (size_t)(r0 + r) * HW + m;
            s += __bfloat162float(__ushort_as_bfloat16(Q0b[o]))
               + __bfloat162float(__ushort_as_bfloat16(Q1b[o]));
        }
    } else {
        const float* Pb = P + (size_t)b * HW * HW;
#pragma unroll 8
        for (int r = 0; r < 256; r++) s += Pb[(size_t)(r0 + r) * HW + m];
    }
    part[((size_t)b * 16 + blockIdx.y) * HW + m] = s;
}

__global__ void colinv_kernel(const float* __restrict__ part, float* __restrict__ colinv) {
    int i = blockIdx.x * 256 + threadIdx.x;
    int b = i >> 12, m = i & (HW - 1);
    float s = 0.f;
#pragma unroll
    for (int c2 = 0; c2 < 16; c2++) s += part[((size_t)b * 16 + c2) * HW + m];
    colinv[i] = 1.f / fmaxf(s, 1e-12f);
}

// ---------------- launch ----------------
extern "C" void kernel_launch(void* const* d_in, const int* in_sizes, int n_in,
                              void* d_out, int out_size) {
    (void)in_sizes; (void)n_in; (void)out_size;
    const float* skt = (const float*)d_in[0];
    const float* ref = (const float*)d_in[1];
    const float* Wa3 = (const float*)d_in[2];
    const float* ba3 = (const float*)d_in[3];
    const float* Wu3 = (const float*)d_in[4];
    const float* bu3 = (const float*)d_in[5];
    const float* Wa4 = (const float*)d_in[6];
    const float* ba4 = (const float*)d_in[7];
    const float* Wu4 = (const float*)d_in[8];
    const float* bu4 = (const float*)d_in[9];
    float* out = (float*)d_out;

    float *P, *ax, *ux, *gen, *sktnc, *refnc, *colpart, *colinv;
    unsigned *hi0, *lo0, *hi1, *lo1;
    ushortT *Pb0, *Pb1, *wt;
    cudaGetSymbolAddress((void**)&P, g_P);
    cudaGetSymbolAddress((void**)&Pb0, g_Pb0);
    cudaGetSymbolAddress((void**)&Pb1, g_Pb1);
    cudaGetSymbolAddress((void**)&ax, g_ax);
    cudaGetSymbolAddress((void**)&ux, g_ux);
    cudaGetSymbolAddress((void**)&gen, g_gen);
    cudaGetSymbolAddress((void**)&sktnc, g_sktnc);
    cudaGetSymbolAddress((void**)&refnc, g_refnc);
    cudaGetSymbolAddress((void**)&colpart, g_colpart);
    cudaGetSymbolAddress((void**)&colinv, g_colinv);
    cudaGetSymbolAddress((void**)&hi0, g_hi0);
    cudaGetSymbolAddress((void**)&lo0, g_lo0);
    cudaGetSymbolAddress((void**)&hi1, g_hi1);
    cudaGetSymbolAddress((void**)&lo1, g_lo1);
    cudaGetSymbolAddress((void**)&wt, g_wt);

    ushortT* SA0 = (ushortT*)hi0;  ushortT* SA1 = SA0 + NPL;
    ushortT* SB0 = (ushortT*)lo0;  ushortT* SB1 = SB0 + NPL;
    ushortT* XT0 = (ushortT*)hi1;  ushortT* XT1 = XT0 + NPL;
    unsigned* AXH = lo1;
    ushortT* WA0 = wt;              ushortT* WA1 = WA0 + 256 * 256;
    ushortT* WU0 = WA1 + 256 * 256; ushortT* WU1 = WU0 + 256 * 256;

    const int SM1   = (128 * 36 + 32 * 136) * 4;                       // 35840
    const int SMBF  = 2 * STGW * 4;                                    // 81920
    const int SMPB  = 2 * (2 * 128 * RST + 2 * 256 * RST) * 4;         // 122880
    const int SMP1  = 2 * (128 * 36 + 32 * 264) * 4;                   // 104448
    cudaFuncSetAttribute(gemm_rr,          cudaFuncAttributeMaxDynamicSharedMemorySize, SM1);
    cudaFuncSetAttribute(logits_bf<false>, cudaFuncAttributeMaxDynamicSharedMemorySize, SMBF);
    cudaFuncSetAttribute(logits_bf<true>,  cudaFuncAttributeMaxDynamicSharedMemorySize, SMBF);
    cudaFuncSetAttribute(pax_bf,           cudaFuncAttributeMaxDynamicSharedMemorySize, SMPB);
    cudaFuncSetAttribute(linear_bf,        cudaFuncAttributeMaxDynamicSharedMemorySize, SMBF);
    cudaFuncSetAttribute(pax_cp,           cudaFuncAttributeMaxDynamicSharedMemorySize, SMP1);

    dim3 tb(32, 8);
    dim3 gLin(CDIM / 128, (BATCH * HW) / 128, 1);
    dim3 gLog(HW / 128, HW / 128, BATCH);
    dim3 gPax(HW / 128, BATCH);
    const int nSplit = (BATCH * HW * CDIM) / (4 * 256);

    // ===== layer 1 =====
    transpose_kernel<<<dim3(HW / 32, CDIM / 32, BATCH), tb>>>(skt, sktnc, CDIM, HW);
    transpose_kernel<<<dim3(HW / 32, CDIM / 32, BATCH), tb>>>(ref, refnc, CDIM, HW);
    bsplit2_kernel<<<nSplit, 256>>>(sktnc, SA0, SA1);
    bsplit2_kernel<<<nSplit, 256>>>(refnc, SB0, SB1);
    wt_split_kernel<<<dim3(8, 8), tb>>>(Wa3, WA0, WA1);
    wt_split_kernel<<<dim3(8, 8), tb>>>(Wu3, WU0, WU1);
    linear_bf<<<gLin, 128, SMBF>>>(SB0, SB1, WA0, WA1, ba3, ax);
    linear_bf<<<gLin, 128, SMBF>>>(SA0, SA1, WU0, WU1, bu3, ux);
    logits_bf<false><<<gLog, 128, SMBF>>>(SA0, SA1, SB0, SB1, P);
    softmax_kernel<true><<<dim3(HW, BATCH), 512>>>(P, Pb0, Pb1);
    colsum_kernel<true><<<dim3(HW / 256, 16, BATCH), 256>>>(nullptr, Pb0, Pb1, colpart);
    colinv_kernel<<<(BATCH * HW) / 256, 256>>>(colpart, colinv);
    axt_split_kernel<<<dim3(HW / 32, CDIM / 32, BATCH), tb>>>(ax, colinv, XT0, XT1);
    pax_bf<<<gPax, 256, SMPB>>>(Pb0, Pb1, XT0, XT1, ux, sktnc, gen);

    // ===== layer 2 =====
    bsplit2_kernel<<<nSplit, 256>>>(gen, SA0, SA1);
    gemm_rr<<<gLin, 256, SM1>>>(gen, Wa4, ba4, ax, CDIM);
    gemm_rr<<<gLin, 256, SM1>>>(gen, Wu4, bu4, ux, CDIM);
    logits_bf<true><<<gLog, 128, SMBF>>>(SA0, SA1, SA0, SA1, P);
    softmax_kernel<false><<<dim3(HW, BATCH), 512>>>(P, nullptr, nullptr);
    colsum_kernel<false><<<dim3(HW / 256, 16, BATCH), 256>>>(P, nullptr, nullptr, colpart);
    colinv_kernel<<<(BATCH * HW) / 256, 256>>>(colpart, colinv);
    scale_split_kernel<<<nSplit, 256>>>(ax, colinv, AXH);
    pax_cp<<<gPax, 256, SMP1>>>(P, AXH, ux, gen, out);
}

// round 16
// speedup vs baseline: 1.6590x; 1.0880x over previous
#include <cuda_runtime.h>
#include <cuda_bf16.h>
#include <math.h>

#define BATCH 4
#define CDIM  256
#define HW    4096
#define NPL   ((size_t)BATCH * HW * CDIM)

typedef unsigned short ushortT;

// ---------------- scratch ----------------
static __device__ float g_P[(size_t)BATCH * HW * HW];
static __device__ ushortT g_Pb0[(size_t)BATCH * HW * HW];
static __device__ ushortT g_Pb1[(size_t)BATCH * HW * HW];
static __device__ float g_ax[(size_t)BATCH * HW * CDIM];
static __device__ float g_ux[(size_t)BATCH * HW * CDIM];
static __device__ float g_gen[(size_t)BATCH * HW * CDIM];
static __device__ float g_sktnc[(size_t)BATCH * HW * CDIM];
static __device__ float g_refnc[(size_t)BATCH * HW * CDIM];
static __device__ float g_colpart[(size_t)BATCH * 16 * HW];
static __device__ float g_colinv[(size_t)BATCH * HW];
static __device__ unsigned g_hi0[(size_t)BATCH * HW * CDIM];   // SA planes
static __device__ unsigned g_lo0[(size_t)BATCH * HW * CDIM];   // SB planes
static __device__ unsigned g_hi1[(size_t)BATCH * HW * CDIM];   // XT planes
static __device__ unsigned g_lo1[(size_t)BATCH * HW * CDIM];   // tf32 ax hi (pax2)
static __device__ ushortT g_wt[4][256 * 256];                  // WaT0,WaT1,WuT0,WuT1

// ---------------- helpers ----------------
__device__ __forceinline__ unsigned f2tf(float x) {
    unsigned r;
    asm("cvt.rna.tf32.f32 %0, %1;" : "=r"(r) : "f"(x));
    return r;
}

__device__ __forceinline__ void mma_tf32(float* d, const unsigned* a, const unsigned* b) {
    asm("mma.sync.aligned.m16n8k8.row.col.f32.tf32.tf32.f32 "
        "{%0,%1,%2,%3},{%4,%5,%6,%7},{%8,%9},{%0,%1,%2,%3};"
        : "+f"(d[0]), "+f"(d[1]), "+f"(d[2]), "+f"(d[3])
        : "r"(a[0]), "r"(a[1]), "r"(a[2]), "r"(a[3]), "r"(b[0]), "r"(b[1]));
}

__device__ __forceinline__ void mma_bf16(float* d, const unsigned* a, const unsigned* b) {
    asm("mma.sync.aligned.m16n8k16.row.col.f32.bf16.bf16.f32 "
        "{%0,%1,%2,%3},{%4,%5,%6,%7},{%8,%9},{%0,%1,%2,%3};"
        : "+f"(d[0]), "+f"(d[1]), "+f"(d[2]), "+f"(d[3])
        : "r"(a[0]), "r"(a[1]), "r"(a[2]), "r"(a[3]), "r"(b[0]), "r"(b[1]));
}

__device__ __forceinline__ void cpa16(unsigned saddr, const void* g) {
    asm volatile("cp.async.cg.shared.global [%0], [%1], 16;\n" :: "r"(saddr), "l"(g));
}

template<int N>
__device__ __forceinline__ void cp_wait() {
    asm volatile("cp.async.wait_group %0;\n" :: "n"(N) : "memory");
}

__device__ __forceinline__ unsigned smem_u32(const void* p) {
    unsigned a;
    asm("{ .reg .u64 t; cvta.to.shared.u64 t, %1; cvt.u32.u64 %0, t; }" : "=r"(a) : "l"(p));
    return a;
}

__device__ __forceinline__ void bsplit(float x, ushortT& h, ushortT& l) {
    __nv_bfloat16 b0 = __float2bfloat16(x);
    __nv_bfloat16 b1 = __float2bfloat16(x - __bfloat162float(b0));
    h = __bfloat16_as_ushort(b0);
    l = __bfloat16_as_ushort(b1);
}

// XOR chunk swizzle: row of 16 words = 4 chunks of 4 words; chunk index
// XORed with row bits [1:3) -> B-fragment loads (col stride 8) become
// bank-conflict-free (bank = 16(g&1) + 4((c^(g>>1))&3) + t, all distinct).
__device__ __forceinline__ int swz(int row, int kw) {
    return row * 16 + ((((kw >> 2) ^ (row >> 1)) & 3) << 2) + (kw & 3);
}

// ---------------- bf16 2-plane split ----------------
__global__ void bsplit2_kernel(const float* __restrict__ in,
                               ushortT* __restrict__ p0, ushortT* __restrict__ p1) {
    size_t i = (size_t)blockIdx.x * 256 + threadIdx.x;
    float4 v = ((const float4*)in)[i];
    float x[4] = {v.x, v.y, v.z, v.w};
    ushortT h[4], l[4];
#pragma unroll
    for (int e = 0; e < 4; e++) bsplit(x[e], h[e], l[e]);
    ((uint2*)p0)[i] = make_uint2(h[0] | ((unsigned)h[1] << 16), h[2] | ((unsigned)h[3] << 16));
    ((uint2*)p1)[i] = make_uint2(l[0] | ((unsigned)l[1] << 16), l[2] | ((unsigned)l[3] << 16));
}

// ---------------- tf32 scale+split (pax2) ----------------
__global__ void scale_split_kernel(const float* __restrict__ ax,
                                   const float* __restrict__ colinv,
                                   unsigned* __restrict__ hi) {
    size_t i = (size_t)blockIdx.x * 256 + threadIdx.x;
    int row = (int)(i >> 6);
    float sc = colinv[row];
    float4 v = ((const float4*)ax)[i];
    uint4 h;
    h.x = f2tf(v.x * sc); h.y = f2tf(v.y * sc);
    h.z = f2tf(v.z * sc); h.w = f2tf(v.w * sc);
    ((uint4*)hi)[i] = h;
}

// ---------------- ax scale + transpose + bf16 split -> [d][k] planes ----------------
__global__ void axt_split_kernel(const float* __restrict__ ax, const float* __restrict__ colinv,
                                 ushortT* __restrict__ p0, ushortT* __restrict__ p1) {
    __shared__ float tile[32][33];
    int b = blockIdx.z;
    int k0 = blockIdx.x * 32, d0 = blockIdx.y * 32;
    int tx = threadIdx.x, ty = threadIdx.y;
    const float* axb = ax + (size_t)b * HW * CDIM;
#pragma unroll
    for (int i = 0; i < 32; i += 8) {
        float sc = colinv[(b << 12) + k0 + ty + i];
        tile[ty + i][tx] = axb[(size_t)(k0 + ty + i) * CDIM + d0 + tx] * sc;
    }
    __syncthreads();
#pragma unroll
    for (int i = 0; i < 32; i += 8) {
        float v = tile[tx][ty + i];
        ushortT h, l;
        bsplit(v, h, l);
        size_t o = (size_t)b * CDIM * HW + (size_t)(d0 + ty + i) * HW + k0 + tx;
        p0[o] = h;
        p1[o] = l;
    }
}

// ---------------- W transpose + split: W[k][n] -> WT planes [n][k] ----------------
__global__ void wt_split_kernel(const float* __restrict__ W,
                                ushortT* __restrict__ p0, ushortT* __restrict__ p1) {
    __shared__ float tile[32][33];
    int k0 = blockIdx.x * 32, n0 = blockIdx.y * 32;
    int tx = threadIdx.x, ty = threadIdx.y;
#pragma unroll
    for (int i = 0; i < 32; i += 8)
        tile[ty + i][tx] = W[(size_t)(k0 + ty + i) * CDIM + n0 + tx];
    __syncthreads();
#pragma unroll
    for (int i = 0; i < 32; i += 8) {
        float v = tile[tx][ty + i];
        ushortT h, l;
        bsplit(v, h, l);
        size_t o = (size_t)(n0 + ty + i) * CDIM + k0 + tx;
        p0[o] = h;
        p1[o] = l;
    }
}

// ---------------- transpose ----------------
__global__ void transpose_kernel(const float* __restrict__ in, float* __restrict__ out,
                                 int R, int S) {
    __shared__ float tile[32][33];
    int b = blockIdx.z;
    int s0 = blockIdx.x * 32, r0 = blockIdx.y * 32;
    const float* inb = in + (size_t)b * R * S;
    float* outb = out + (size_t)b * R * S;
    int tx = threadIdx.x, ty = threadIdx.y;
#pragma unroll
    for (int i = 0; i < 32; i += 8)
        tile[ty + i][tx] = inb[(size_t)(r0 + ty + i) * S + s0 + tx];
    __syncthreads();
#pragma unroll
    for (int i = 0; i < 32; i += 8)
        outb[(size_t)(s0 + ty + i) * R + r0 + tx] = tile[tx][ty + i];
}

// =====================================================================
// bf16 3-product core, 4 warps, warp tile 64x64, CTA 128x128.
// RST=16 (no pad) + XOR chunk swizzle: conflict-free A and B loads.
// =====================================================================
#define RST 16
#define PLW (128 * RST)
#define STGW (4 * PLW)           // words per stage

#define BF_MAINLOOP(LD)                                                          \
    float acc[4][8][4] = {};                                                     \
    prefetch(0, 0);                                                              \
    for (int it = 0; it < NIT; it++) {                                           \
        if (it + 1 < NIT) { prefetch(it + 1, (it + 1) & 1); cp_wait<1>(); }      \
        else cp_wait<0>();                                                       \
        __syncthreads();                                                         \
        const unsigned* As0 = sm + (it & 1) * STGW;                              \
        const unsigned* As1 = As0 + PLW;                                         \
        const unsigned* Bs0 = As0 + 2 * PLW;                                     \
        const unsigned* Bs1 = As0 + 3 * PLW;                                     \
        _Pragma("unroll")                                                        \
        for (int c = 0; c < 2; c++) {                                            \
            int kc = c * 8;                                                      \
            unsigned b0[8][2], b1[8][2];                                         \
            _Pragma("unroll")                                                    \
            for (int j = 0; j < 8; j++) {                                        \
                int col = wn * 64 + j * 8 + g;                                   \
                b0[j][0] = Bs0[swz(col, kc + t)];                                \
                b0[j][1] = Bs0[swz(col, kc + t + 4)];                            \
                b1[j][0] = Bs1[swz(col, kc + t)];                                \
                b1[j][1] = Bs1[swz(col, kc + t + 4)];                            \
            }                                                                    \
            _Pragma("unroll")                                                    \
            for (int i = 0; i < 4; i++) {                                        \
                int row = wm * 64 + i * 16 + g;                                  \
                unsigned a0[4], a1[4];                                           \
                a0[0] = As0[swz(row, kc + t)];                                   \
                a0[1] = As0[swz(row + 8, kc + t)];                               \
                a0[2] = As0[swz(row, kc + t + 4)];                               \
                a0[3] = As0[swz(row + 8, kc + t + 4)];                           \
                a1[0] = As1[swz(row, kc + t)];                                   \
                a1[1] = As1[swz(row + 8, kc + t)];                               \
                a1[2] = As1[swz(row, kc + t + 4)];                               \
                a1[3] = As1[swz(row + 8, kc + t + 4)];                           \
                _Pragma("unroll")                                                \
                for (int j = 0; j < 8; j++) {                                    \
                    mma_bf16(acc[i][j], a0, b0[j]);                              \
                    mma_bf16(acc[i][j], a0, b1[j]);                              \
                    mma_bf16(acc[i][j], a1, b0[j]);                              \
                }                                                                \
            }                                                                    \
        }                                                                        \
        __syncthreads();                                                         \
    }

#define BF_PREFETCH(LD)                                                          \
    auto prefetch = [&](int it, int s) {                                         \
        int k0 = it * 32;                                                        \
        unsigned sb = sbase + (unsigned)(s * STGW) * 4u;                         \
        _Pragma("unroll")                                                        \
        for (int q = 0; q < 16; q++) {                                           \
            int e = tid + q * 128;                                               \
            int pl = e >> 9;                                                     \
            int ep = e & 511;                                                    \
            int r = ep >> 2, wc = ep & 3;                                        \
            int pc = (wc ^ (r >> 1)) & 3;                                        \
            cpa16(sb + (unsigned)(pl * PLW + r * RST + pc * 4) * 4u,             \
                  gp[pl] + (size_t)r * (LD) + k0 + wc * 8);                      \
        }                                                                        \
        asm volatile("cp.async.commit_group;\n" ::: "memory");                   \
    };

// logits: L[n][m] = sum_k A[n][k]*B[m][k]; NIT = 8
template<bool SYM>
__global__ __launch_bounds__(128)
void logits_bf(const ushortT* __restrict__ A0, const ushortT* __restrict__ A1,
               const ushortT* __restrict__ B0, const ushortT* __restrict__ B1,
               float* __restrict__ L) {
    extern __shared__ unsigned sm[];
    constexpr int NIT = CDIM / 32;

    int bx = blockIdx.x, by = blockIdx.y, b = blockIdx.z;
    if (SYM && bx < by) return;
    int m0 = bx * 128, n0 = by * 128;

    const ushortT* gp[4];
    gp[0] = A0 + ((size_t)b * HW + n0) * CDIM;
    gp[1] = A1 + ((size_t)b * HW + n0) * CDIM;
    gp[2] = B0 + ((size_t)b * HW + m0) * CDIM;
    gp[3] = B1 + ((size_t)b * HW + m0) * CDIM;
    float* Lb = L + (size_t)b * HW * HW;

    unsigned sbase = smem_u32(sm);
    int tid = threadIdx.x;
    int w = tid >> 5, lane = tid & 31;
    int g = lane >> 2, t = lane & 3;
    int wm = w >> 1, wn = w & 1;

    BF_PREFETCH(CDIM)
    BF_MAINLOOP(CDIM)

#pragma unroll
    for (int i = 0; i < 4; i++) {
        int r = n0 + wm * 64 + i * 16 + g;
#pragma unroll
        for (int j = 0; j < 8; j++) {
            int cc = m0 + wn * 64 + j * 8 + 2 * t;
            *(float2*)&Lb[(size_t)r * HW + cc] =
                make_float2(acc[i][j][0], acc[i][j][1]);
            *(float2*)&Lb[(size_t)(r + 8) * HW + cc] =
                make_float2(acc[i][j][2], acc[i][j][3]);
        }
    }
    if (SYM && bx != by) {
#pragma unroll
        for (int i = 0; i < 4; i++) {
            int rr = n0 + wm * 64 + i * 16 + g;
#pragma unroll
            for (int j = 0; j < 8; j++) {
                int cc = m0 + wn * 64 + j * 8 + 2 * t;
                Lb[(size_t)cc * HW + rr]           = acc[i][j][0];
                Lb[(size_t)(cc + 1) * HW + rr]     = acc[i][j][1];
                Lb[(size_t)cc * HW + rr + 8]       = acc[i][j][2];
                Lb[(size_t)(cc + 1) * HW + rr + 8] = acc[i][j][3];
            }
        }
    }
}

// =====================================================================
// pax1: C[n][d] = sum_k P[n][k]*axT[d][k] + U + R; CTA tile 128x256,
// 256 thr (8 warps 2x4 of 64x64).
// =====================================================================
__global__ __launch_bounds__(256)
void pax_bf(const ushortT* __restrict__ P0, const ushortT* __restrict__ P1,
            const ushortT* __restrict__ X0, const ushortT* __restrict__ X1,
            const float* __restrict__ U, const float* __restrict__ Rr,
            float* __restrict__ C) {
    extern __shared__ unsigned sm[];
    constexpr int NIT = HW / 32;
    constexpr int APLW = 128 * RST;
    constexpr int XPLW = 256 * RST;
    constexpr int PSTG = 2 * APLW + 2 * XPLW;

    int b = blockIdx.y;
    int n0 = blockIdx.x * 128;

    const ushortT* gpP[2];
    gpP[0] = P0 + ((size_t)b * HW + n0) * HW;
    gpP[1] = P1 + ((size_t)b * HW + n0) * HW;
    const ushortT* gpX[2];
    gpX[0] = X0 + (size_t)b * CDIM * HW;
    gpX[1] = X1 + (size_t)b * CDIM * HW;

    unsigned sbase = smem_u32(sm);
    int tid = threadIdx.x;
    int w = tid >> 5, lane = tid & 31;
    int g = lane >> 2, t = lane & 3;
    int wm = w >> 2, wn = w & 3;

    auto prefetch = [&](int it, int s) {
        int k0 = it * 32;
        unsigned sb = sbase + (unsigned)(s * PSTG) * 4u;
#pragma unroll
        for (int q = 0; q < 4; q++) {        // P: 2 planes x 128 rows x 4 chunks
            int e = tid + q * 256;
            int pl = e >> 9, ep = e & 511;
            int r = ep >> 2, wc = ep & 3;
            int pc = (wc ^ (r >> 1)) & 3;
            cpa16(sb + (unsigned)(pl * APLW + r * RST + pc * 4) * 4u,
                  gpP[pl] + (size_t)r * HW + k0 + wc * 8);
        }
#pragma unroll
        for (int q = 0; q < 8; q++) {        // X: 2 planes x 256 rows x 4 chunks
            int e = tid + q * 256;
            int pl = e >> 10, ep = e & 1023;
            int r = ep >> 2, wc = ep & 3;
            int pc = (wc ^ (r >> 1)) & 3;
            cpa16(sb + (unsigned)(2 * APLW + pl * XPLW + r * RST + pc * 4) * 4u,
                  gpX[pl] + (size_t)r * HW + k0 + wc * 8);
        }
        asm volatile("cp.async.commit_group;\n" ::: "memory");
    };

    float acc[4][8][4] = {};
    prefetch(0, 0);
    for (int it = 0; it < NIT; it++) {
        if (it + 1 < NIT) { prefetch(it + 1, (it + 1) & 1); cp_wait<1>(); }
        else cp_wait<0>();
        __syncthreads();

        const unsigned* As0 = sm + (it & 1) * PSTG;
        const unsigned* As1 = As0 + APLW;
        const unsigned* Bs0 = As0 + 2 * APLW;
        const unsigned* Bs1 = Bs0 + XPLW;

#pragma unroll
        for (int c = 0; c < 2; c++) {
            int kc = c * 8;
            unsigned b0[8][2], b1[8][2];
#pragma unroll
            for (int j = 0; j < 8; j++) {
                int col = wn * 64 + j * 8 + g;
                b0[j][0] = Bs0[swz(col, kc + t)];
                b0[j][1] = Bs0[swz(col, kc + t + 4)];
                b1[j][0] = Bs1[swz(col, kc + t)];
                b1[j][1] = Bs1[swz(col, kc + t + 4)];
            }
#pragma unroll
            for (int i = 0; i < 4; i++) {
                int row = wm * 64 + i * 16 + g;
                unsigned a0[4], a1[4];
                a0[0] = As0[swz(row, kc + t)];
                a0[1] = As0[swz(row + 8, kc + t)];
                a0[2] = As0[swz(row, kc + t + 4)];
                a0[3] = As0[swz(row + 8, kc + t + 4)];
                a1[0] = As1[swz(row, kc + t)];
                a1[1] = As1[swz(row + 8, kc + t)];
                a1[2] = As1[swz(row, kc + t + 4)];
                a1[3] = As1[swz(row + 8, kc + t + 4)];
#pragma unroll
                for (int j = 0; j < 8; j++) {
                    mma_bf16(acc[i][j], a0, b0[j]);
                    mma_bf16(acc[i][j], a0, b1[j]);
                    mma_bf16(acc[i][j], a1, b0[j]);
                }
            }
        }
        __syncthreads();
    }

    const float* Ub = U + (size_t)b * HW * CDIM;
    const float* Rb = Rr + (size_t)b * HW * CDIM;
    float* Cb = C + (size_t)b * HW * CDIM;
#pragma unroll
    for (int i = 0; i < 4; i++) {
        int r = n0 + wm * 64 + i * 16 + g;
#pragma unroll
        for (int j = 0; j < 8; j++) {
            int cc = wn * 64 + j * 8 + 2 * t;
            size_t o0 = (size_t)r * CDIM + cc;
            size_t o1 = (size_t)(r + 8) * CDIM + cc;
            float2 u0 = *(const float2*)&Ub[o0], u1 = *(const float2*)&Ub[o1];
            float2 q0 = *(const float2*)&Rb[o0], q1 = *(const float2*)&Rb[o1];
            *(float2*)&Cb[o0] = make_float2(acc[i][j][0] + u0.x + q0.x,
                                            acc[i][j][1] + u0.y + q0.y);
            *(float2*)&Cb[o1] = make_float2(acc[i][j][2] + u1.x + q1.x,
                                            acc[i][j][3] + u1.y + q1.y);
        }
    }
}

// linear (layer 1): C[m][n] = relu(A@W + bias)
__global__ __launch_bounds__(128)
void linear_bf(const ushortT* __restrict__ A0, const ushortT* __restrict__ A1,
               const ushortT* __restrict__ W0, const ushortT* __restrict__ W1,
               const float* __restrict__ bias, float* __restrict__ C) {
    extern __shared__ unsigned sm[];
    constexpr int NIT = CDIM / 32;

    int n0 = blockIdx.x * 128;
    int m0 = blockIdx.y * 128;

    const ushortT* gp[4];
    gp[0] = A0 + (size_t)m0 * CDIM;
    gp[1] = A1 + (size_t)m0 * CDIM;
    gp[2] = W0 + (size_t)n0 * CDIM;
    gp[3] = W1 + (size_t)n0 * CDIM;

    unsigned sbase = smem_u32(sm);
    int tid = threadIdx.x;
    int w = tid >> 5, lane = tid & 31;
    int g = lane >> 2, t = lane & 3;
    int wm = w >> 1, wn = w & 1;

    BF_PREFETCH(CDIM)
    BF_MAINLOOP(CDIM)

#pragma unroll
    for (int i = 0; i < 4; i++) {
        int r = m0 + wm * 64 + i * 16 + g;
#pragma unroll
        for (int j = 0; j < 8; j++) {
            int cc = n0 + wn * 64 + j * 8 + 2 * t;
            size_t o0 = (size_t)r * CDIM + cc;
            size_t o1 = (size_t)(r + 8) * CDIM + cc;
            float2 bv = *(const float2*)&bias[cc];
            *(float2*)&C[o0] = make_float2(fmaxf(acc[i][j][0] + bv.x, 0.f),
                                           fmaxf(acc[i][j][1] + bv.y, 0.f));
            *(float2*)&C[o1] = make_float2(fmaxf(acc[i][j][2] + bv.x, 0.f),
                                           fmaxf(acc[i][j][3] + bv.y, 0.f));
        }
    }
}

// =====================================================================
// pax2 (tf32 single-pass): CTA tile 128x256 (proven R15)
// =====================================================================
__global__ __launch_bounds__(256)
void pax_cp(const float* __restrict__ Pf, const unsigned* __restrict__ Bh,
            const float* __restrict__ U, const float* __restrict__ Rr,
            float* __restrict__ C) {
    extern __shared__ unsigned sm[];
    constexpr int AW = 128 * 36;
    constexpr int BW = 32 * 264;
    constexpr int STG = AW + BW;
    constexpr int NIT = HW / 32;

    int b = blockIdx.y;
    int n0 = blockIdx.x * 128;

    const float* Pb = Pf + (size_t)b * HW * HW;
    const unsigned* Bhb = Bh + (size_t)b * HW * CDIM;

    unsigned sbase = smem_u32(sm);
    int tid = threadIdx.x;
    int warp = tid >> 5, lane = tid & 31;
    int g = lane >> 2, t = lane & 3;
    int wm = warp >> 2, wn = warp & 3;

    auto prefetch = [&](int it, int s) {
        int k0 = it * 32;
        unsigned sb = sbase + (unsigned)(s * STG) * 4u;
#pragma unroll
        for (int q = 0; q < 4; q++) {
            int f = tid + q * 256;
            int n = f >> 3, c4 = (f & 7) * 4;
            cpa16(sb + (unsigned)(n * 36 + c4) * 4u,
                  Pb + (size_t)(n0 + n) * HW + k0 + c4);
        }
#pragma unroll
        for (int q = 0; q < 8; q++) {
            int f = tid + q * 256;
            int k = f >> 6, d4 = (f & 63) * 4;
            cpa16(sb + (unsigned)(AW + k * 264 + d4) * 4u,
                  Bhb + (size_t)(k0 + k) * CDIM + d4);
        }
        asm volatile("cp.async.commit_group;\n" ::: "memory");
    };

    float acc[4][8][4] = {};

    prefetch(0, 0);
    for (int it = 0; it < NIT; it++) {
        if (it + 1 < NIT) { prefetch(it + 1, (it + 1) & 1); cp_wait<1>(); }
        else cp_wait<0>();
        __syncthreads();

        const float* As = (const float*)(sm + (it & 1) * STG);
        const unsigned* Bs = (const unsigned*)(As + AW);

#pragma unroll
        for (int c = 0; c < 4; c++) {
            int kc = c * 8;
            unsigned bb[8][2];
#pragma unroll
            for (int j = 0; j < 8; j++) {
                int col = wn * 64 + j * 8 + g;
                bb[j][0] = Bs[(kc + t) * 264 + col];
                bb[j][1] = Bs[(kc + t + 4) * 264 + col];
            }
#pragma unroll
            for (int i = 0; i < 4; i++) {
                int row = wm * 64 + i * 16 + g;
                unsigned aa[4];
                aa[0] = f2tf(As[row * 36 + kc + t]);
                aa[1] = f2tf(As[(row + 8) * 36 + kc + t]);
                aa[2] = f2tf(As[row * 36 + kc + t + 4]);
                aa[3] = f2tf(As[(row + 8) * 36 + kc + t + 4]);
#pragma unroll
                for (int j = 0; j < 8; j++) mma_tf32(acc[i][j], aa, bb[j]);
            }
        }
        __syncthreads();
    }

    const float* Ub = U + (size_t)b * HW * CDIM;
    const float* Rb = Rr + (size_t)b * HW * CDIM;
    float* Cb = C + (size_t)b * HW * CDIM;
#pragma unroll
    for (int i = 0; i < 4; i++) {
        int r = n0 + wm * 64 + i * 16 + g;
#pragma unroll
        for (int j = 0; j < 8; j++) {
            int cc = wn * 64 + j * 8 + 2 * t;
            size_t o0 = (size_t)r * CDIM + cc;
            size_t o1 = (size_t)(r + 8) * CDIM + cc;
            float2 u0 = *(const float2*)&Ub[o0], u1 = *(const float2*)&Ub[o1];
            float2 q0 = *(const float2*)&Rb[o0], q1 = *(const float2*)&Rb[o1];
            *(float2*)&Cb[o0] = make_float2(acc[i][j][0] + u0.x + q0.x,
                                            acc[i][j][1] + u0.y + q0.y);
            *(float2*)&Cb[o1] = make_float2(acc[i][j][2] + u1.x + q1.x,
                                            acc[i][j][3] + u1.y + q1.y);
        }
    }
}

// =====================================================================
// gemm_rr (layer-2 linears, tf32 single): C = relu(A@W + bias)
// =====================================================================
__global__ __launch_bounds__(256, 2)
void gemm_rr(const float* __restrict__ A, const float* __restrict__ B,
             const float* __restrict__ bias, float* __restrict__ C, int lda) {
    extern __shared__ unsigned sm[];
    unsigned* As = sm;
    unsigned* Bs = As + 128 * 36;

    int n0 = blockIdx.x * 128;
    int m0 = blockIdx.y * 128;
    int tid = threadIdx.x;
    int warp = tid >> 5, lane = tid & 31;
    int g = lane >> 2, t = lane & 3;
    int wm = warp >> 2, wn = warp & 3;
    int la_n = tid >> 3, la_k = (tid & 7) * 4;
    int lb_k = tid >> 5, lb_n = (tid & 31) * 4;

    float acc[4][4][4] = {};

    for (int k0 = 0; k0 < CDIM; k0 += 32) {
#pragma unroll
        for (int u = 0; u < 4; u++) {
            int n = la_n + u * 32;
            float4 v = *(const float4*)&A[(size_t)(m0 + n) * lda + k0 + la_k];
            unsigned* p = &As[n * 36 + la_k];
            p[0] = f2tf(v.x); p[1] = f2tf(v.y); p[2] = f2tf(v.z); p[3] = f2tf(v.w);
        }
#pragma unroll
        for (int u = 0; u < 4; u++) {
            int k = lb_k + u * 8;
            float4 v = *(const float4*)&B[(size_t)(k0 + k) * CDIM + n0 + lb_n];
            unsigned* p = &Bs[k * 136 + lb_n];
            p[0] = f2tf(v.x); p[1] = f2tf(v.y); p[2] = f2tf(v.z); p[3] = f2tf(v.w);
        }
        __syncthreads();

#pragma unroll
        for (int c = 0; c < 4; c++) {
            int kc = c * 8;
            unsigned bb[4][2];
#pragma unroll
            for (int j = 0; j < 4; j++) {
                int col = wn * 32 + j * 8 + g;
                bb[j][0] = Bs[(kc + t) * 136 + col];
                bb[j][1] = Bs[(kc + t + 4) * 136 + col];
            }
#pragma unroll
            for (int i = 0; i < 4; i++) {
                int row = wm * 64 + i * 16 + g;
                unsigned aa[4];
                aa[0] = As[row * 36 + kc + t];
                aa[1] = As[(row + 8) * 36 + kc + t];
                aa[2] = As[row * 36 + kc + t + 4];
                aa[3] = As[(row + 8) * 36 + kc + t + 4];
#pragma unroll
                for (int j = 0; j < 4; j++) mma_tf32(acc[i][j], aa, bb[j]);
            }
        }
        __syncthreads();
    }

#pragma unroll
    for (int i = 0; i < 4; i++) {
        int r = m0 + wm * 64 + i * 16 + g;
#pragma unroll
        for (int j = 0; j < 4; j++) {
            int cc = n0 + wn * 32 + j * 8 + 2 * t;
            size_t o0 = (size_t)r * CDIM + cc;
            size_t o1 = (size_t)(r + 8) * CDIM + cc;
            float2 bv = *(const float2*)&bias[cc];
            *(float2*)&C[o0] = make_float2(fmaxf(acc[i][j][0] + bv.x, 0.f),
                                           fmaxf(acc[i][j][1] + bv.y, 0.f));
            *(float2*)&C[o1] = make_float2(fmaxf(acc[i][j][2] + bv.x, 0.f),
                                           fmaxf(acc[i][j][3] + bv.y, 0.f));
        }
    }
}

// ---------------- row softmax ----------------
template<bool WBF>
__global__ void softmax_kernel(float* __restrict__ P, ushortT* __restrict__ Q0,
                               ushortT* __restrict__ Q1) {
    size_t ro = ((size_t)blockIdx.y * HW + blockIdx.x) * HW;
    float* row = P + ro;
    int t = threadIdx.x;
    __shared__ float red[16];
    float v[8];
    float mx = -1e30f;
#pragma unroll
    for (int i = 0; i < 8; i++) { v[i] = row[t + i * 512]; mx = fmaxf(mx, v[i]); }
    for (int o = 16; o; o >>= 1) mx = fmaxf(mx, __shfl_xor_sync(0xffffffffu, mx, o));
    int warp = t >> 5, lane = t & 31;
    if (lane == 0) red[warp] = mx;
    __syncthreads();
    if (warp == 0) {
        float m2 = red[lane & 15];
        for (int o = 8; o; o >>= 1) m2 = fmaxf(m2, __shfl_xor_sync(0xffffffffu, m2, o));
        if (lane == 0) red[0] = m2;
    }
    __syncthreads();
    mx = red[0];
    __syncthreads();
    float s = 0.f;
#pragma unroll
    for (int i = 0; i < 8; i++) { v[i] = __expf(v[i] - mx); s += v[i]; }
    for (int o = 16; o; o >>= 1) s += __shfl_xor_sync(0xffffffffu, s, o);
    if (lane == 0) red[warp] = s;
    __syncthreads();
    if (warp == 0) {
        float s2 = red[lane & 15];
        for (int o = 8; o; o >>= 1) s2 += __shfl_xor_sync(0xffffffffu, s2, o);
        if (lane == 0) red[0] = s2;
    }
    __syncthreads();
    float inv = 1.f / red[0];
#pragma unroll
    for (int i = 0; i < 8; i++) {
        float p = v[i] * inv;
        if (WBF) {
            ushortT h, l;
            bsplit(p, h, l);
            Q0[ro + t + i * 512] = h;
            Q1[ro + t + i * 512] = l;
        } else {
            row[t + i * 512] = p;
        }
    }
}

// ---------------- column partial sums (BF reads BOTH planes) ----------------
template<bool BF>
__global__ void colsum_kernel(const float* __restrict__ P,
                              const ushortT* __restrict__ Q0,
                              const ushortT* __restrict__ Q1,
                              float* __restrict__ part) {
    int b = blockIdx.z;
    int m = blockIdx.x * 256 + threadIdx.x;
    int r0 = blockIdx.y * 256;
    float s = 0.f;
    if (BF) {
        const ushortT* Q0b = Q0 + (size_t)b * HW * HW;
        const ushortT* Q1b = Q1 + (size_t)b * HW * HW;
#pragma unroll 8
        for (int r = 0; r < 256; r++) {
            size_t o = (size_t)(r0 + r) * HW + m;
            s += __bfloat162float(__ushort_as_bfloat16(Q0b[o]))
               + __bfloat162float(__ushort_as_bfloat16(Q1b[o]));
        }
    } else {
        const float* Pb = P + (size_t)b * HW * HW;
#pragma unroll 8
        for (int r = 0; r < 256; r++) s += Pb[(size_t)(r0 + r) * HW + m];
    }
    part[((size_t)b * 16 + blockIdx.y) * HW + m] = s;
}

__global__ void colinv_kernel(const float* __restrict__ part, float* __restrict__ colinv) {
    int i = blockIdx.x * 256 + threadIdx.x;
    int b = i >> 12, m = i & (HW - 1);
    float s = 0.f;
#pragma unroll
    for (int c2 = 0; c2 < 16; c2++) s += part[((size_t)b * 16 + c2) * HW + m];
    colinv[i] = 1.f / fmaxf(s, 1e-12f);
}

// ---------------- launch ----------------
extern "C" void kernel_launch(void* const* d_in, const int* in_sizes, int n_in,
                              void* d_out, int out_size) {
    (void)in_sizes; (void)n_in; (void)out_size;
    const float* skt = (const float*)d_in[0];
    const float* ref = (const float*)d_in[1];
    const float* Wa3 = (const float*)d_in[2];
    const float* ba3 = (const float*)d_in[3];
    const float* Wu3 = (const float*)d_in[4];
    const float* bu3 = (const float*)d_in[5];
    const float* Wa4 = (const float*)d_in[6];
    const float* ba4 = (const float*)d_in[7];
    const float* Wu4 = (const float*)d_in[8];
    const float* bu4 = (const float*)d_in[9];
    float* out = (float*)d_out;

    float *P, *ax, *ux, *gen, *sktnc, *refnc, *colpart, *colinv;
    unsigned *hi0, *lo0, *hi1, *lo1;
    ushortT *Pb0, *Pb1, *wt;
    cudaGetSymbolAddress((void**)&P, g_P);
    cudaGetSymbolAddress((void**)&Pb0, g_Pb0);
    cudaGetSymbolAddress((void**)&Pb1, g_Pb1);
    cudaGetSymbolAddress((void**)&ax, g_ax);
    cudaGetSymbolAddress((void**)&ux, g_ux);
    cudaGetSymbolAddress((void**)&gen, g_gen);
    cudaGetSymbolAddress((void**)&sktnc, g_sktnc);
    cudaGetSymbolAddress((void**)&refnc, g_refnc);
    cudaGetSymbolAddress((void**)&colpart, g_colpart);
    cudaGetSymbolAddress((void**)&colinv, g_colinv);
    cudaGetSymbolAddress((void**)&hi0, g_hi0);
    cudaGetSymbolAddress((void**)&lo0, g_lo0);
    cudaGetSymbolAddress((void**)&hi1, g_hi1);
    cudaGetSymbolAddress((void**)&lo1, g_lo1);
    cudaGetSymbolAddress((void**)&wt, g_wt);

    ushortT* SA0 = (ushortT*)hi0;  ushortT* SA1 = SA0 + NPL;
    ushortT* SB0 = (ushortT*)lo0;  ushortT* SB1 = SB0 + NPL;
    ushortT* XT0 = (ushortT*)hi1;  ushortT* XT1 = XT0 + NPL;
    unsigned* AXH = lo1;
    ushortT* WA0 = wt;              ushortT* WA1 = WA0 + 256 * 256;
    ushortT* WU0 = WA1 + 256 * 256; ushortT* WU1 = WU0 + 256 * 256;

    const int SM1   = (128 * 36 + 32 * 136) * 4;                       // 35840
    const int SMBF  = 2 * STGW * 4;                                    // 65536
    const int SMPB  = 2 * (2 * 128 * RST + 2 * 256 * RST) * 4;         // 98304
    const int SMP1  = 2 * (128 * 36 + 32 * 264) * 4;                   // 104448
    cudaFuncSetAttribute(gemm_rr,          cudaFuncAttributeMaxDynamicSharedMemorySize, SM1);
    cudaFuncSetAttribute(logits_bf<false>, cudaFuncAttributeMaxDynamicSharedMemorySize, SMBF);
    cudaFuncSetAttribute(logits_bf<true>,  cudaFuncAttributeMaxDynamicSharedMemorySize, SMBF);
    cudaFuncSetAttribute(pax_bf,           cudaFuncAttributeMaxDynamicSharedMemorySize, SMPB);
    cudaFuncSetAttribute(linear_bf,        cudaFuncAttributeMaxDynamicSharedMemorySize, SMBF);
    cudaFuncSetAttribute(pax_cp,           cudaFuncAttributeMaxDynamicSharedMemorySize, SMP1);

    dim3 tb(32, 8);
    dim3 gLin(CDIM / 128, (BATCH * HW) / 128, 1);
    dim3 gLog(HW / 128, HW / 128, BATCH);
    dim3 gPax(HW / 128, BATCH);
    const int nSplit = (BATCH * HW * CDIM) / (4 * 256);

    // ===== layer 1 =====
    transpose_kernel<<<dim3(HW / 32, CDIM / 32, BATCH), tb>>>(skt, sktnc, CDIM, HW);
    transpose_kernel<<<dim3(HW / 32, CDIM / 32, BATCH), tb>>>(ref, refnc, CDIM, HW);
    bsplit2_kernel<<<nSplit, 256>>>(sktnc, SA0, SA1);
    bsplit2_kernel<<<nSplit, 256>>>(refnc, SB0, SB1);
    wt_split_kernel<<<dim3(8, 8), tb>>>(Wa3, WA0, WA1);
    wt_split_kernel<<<dim3(8, 8), tb>>>(Wu3, WU0, WU1);
    linear_bf<<<gLin, 128, SMBF>>>(SB0, SB1, WA0, WA1, ba3, ax);
    linear_bf<<<gLin, 128, SMBF>>>(SA0, SA1, WU0, WU1, bu3, ux);
    logits_bf<false><<<gLog, 128, SMBF>>>(SA0, SA1, SB0, SB1, P);
    softmax_kernel<true><<<dim3(HW, BATCH), 512>>>(P, Pb0, Pb1);
    colsum_kernel<true><<<dim3(HW / 256, 16, BATCH), 256>>>(nullptr, Pb0, Pb1, colpart);
    colinv_kernel<<<(BATCH * HW) / 256, 256>>>(colpart, colinv);
    axt_split_kernel<<<dim3(HW / 32, CDIM / 32, BATCH), tb>>>(ax, colinv, XT0, XT1);
    pax_bf<<<gPax, 256, SMPB>>>(Pb0, Pb1, XT0, XT1, ux, sktnc, gen);

    // ===== layer 2 =====
    bsplit2_kernel<<<nSplit, 256>>>(gen, SA0, SA1);
    gemm_rr<<<gLin, 256, SM1>>>(gen, Wa4, ba4, ax, CDIM);
    gemm_rr<<<gLin, 256, SM1>>>(gen, Wu4, bu4, ux, CDIM);
    logits_bf<true><<<gLog, 128, SMBF>>>(SA0, SA1, SA0, SA1, P);
    softmax_kernel<false><<<dim3(HW, BATCH), 512>>>(P, nullptr, nullptr);
    colsum_kernel<false><<<dim3(HW / 256, 16, BATCH), 256>>>(P, nullptr, nullptr, colpart);
    colinv_kernel<<<(BATCH * HW) / 256, 256>>>(colpart, colinv);
    scale_split_kernel<<<nSplit, 256>>>(ax, colinv, AXH);
    pax_cp<<<gPax, 256, SMP1>>>(P, AXH, ux, gen, out);
}